// round 7
// baseline (speedup 1.0000x reference)
#include <cuda_runtime.h>
#include <cstdint>

#define HDIM 128
#define NMAX 500000
#define PNUM 50000
#define LN_EPS 1e-5f

// ---------------- scratch (static __device__; no allocation) ----------------
__device__ float g_h0[(size_t)NMAX * HDIM];
__device__ float g_h1[(size_t)NMAX * HDIM];
__device__ float g_agg[(size_t)PNUM * HDIM];
__device__ float g_aggw[(size_t)PNUM * HDIM];
__device__ int   g_counts[PNUM];
__device__ int   g_offsets[PNUM + 1];
__device__ int   g_cursor[PNUM];
__device__ int   g_order[NMAX];   // sorted position -> original row
__device__ int   g_ids[NMAX];     // original row -> id
__device__ int   g_sid[NMAX];     // sorted position -> id (non-decreasing)
__device__ int   g_ids64;

// ---------------- id dtype detection ----------------
__global__ void detect_ids_kernel(const void* idsraw) {
    const long long* a = (const long long*)idsraw;
    int ok = 1;
    for (int i = 0; i < 16; i++) {
        long long v = a[i];
        if (v < 0 || v >= PNUM) ok = 0;
    }
    g_ids64 = ok;
}

__global__ void prep_kernel(const void* idsraw, int N) {
    int i = blockIdx.x * blockDim.x + threadIdx.x;
    if (i >= N) return;
    int v = g_ids64 ? (int)((const long long*)idsraw)[i]
                    : ((const int*)idsraw)[i];
    g_ids[i] = v;
    atomicAdd(&g_counts[v], 1);
}

__global__ void scan_kernel() {
    __shared__ int sums[1024];
    int t = threadIdx.x;
    const int per = (PNUM + 1023) / 1024;
    int start = t * per;
    int end = start + per; if (end > PNUM) end = PNUM;
    int s = 0;
    for (int i = start; i < end; i++) s += g_counts[i];
    sums[t] = s;
    __syncthreads();
    for (int off = 1; off < 1024; off <<= 1) {
        int v = (t >= off) ? sums[t - off] : 0;
        __syncthreads();
        sums[t] += v;
        __syncthreads();
    }
    int run = (t == 0) ? 0 : sums[t - 1];
    for (int i = start; i < end; i++) {
        g_offsets[i] = run;
        g_cursor[i] = run;
        run += g_counts[i];
    }
    if (t == 1023) g_offsets[PNUM] = run;
}

__global__ void scatter_kernel(int N) {
    int i = blockIdx.x * blockDim.x + threadIdx.x;
    if (i >= N) return;
    int id = g_ids[i];
    int pos = atomicAdd(&g_cursor[id], 1);
    g_order[pos] = i;
    g_sid[pos] = id;
}

// ---------------- encoder 0 (sorted output space) ----------------
__global__ __launch_bounds__(256) void enc0_kernel(
    const float* __restrict__ x, const float* __restrict__ W0,
    const float* __restrict__ b0, const float* __restrict__ g0,
    const float* __restrict__ be0, float* __restrict__ out, int N)
{
    int spos = (blockIdx.x * blockDim.x + threadIdx.x) >> 5;
    int lane = threadIdx.x & 31;
    if (spos >= N) return;
    int srow = g_order[spos];

    float xv = (lane < 9) ? x[(size_t)srow * 9 + lane] : 0.f;
    float z[4];
#pragma unroll
    for (int c = 0; c < 4; c++) z[c] = b0[lane + 32 * c];
#pragma unroll
    for (int k = 0; k < 9; k++) {
        float xk = __shfl_sync(0xffffffffu, xv, k);
#pragma unroll
        for (int c = 0; c < 4; c++)
            z[c] = fmaf(xk, W0[k * HDIM + lane + 32 * c], z[c]);
    }
    float s  = z[0] + z[1] + z[2] + z[3];
    float s2 = z[0]*z[0] + z[1]*z[1] + z[2]*z[2] + z[3]*z[3];
#pragma unroll
    for (int o = 16; o > 0; o >>= 1) {
        s  += __shfl_xor_sync(0xffffffffu, s, o);
        s2 += __shfl_xor_sync(0xffffffffu, s2, o);
    }
    float mu  = s * (1.f / HDIM);
    float var = fmaf(s2, 1.f / HDIM, -mu * mu);
    float rs  = rsqrtf(var + LN_EPS);
#pragma unroll
    for (int c = 0; c < 4; c++) {
        int j = lane + 32 * c;
        float v = fmaf((z[c] - mu) * rs, g0[j], be0[j]);
        out[(size_t)spos * HDIM + j] = fmaxf(v, 0.f);
    }
}

// ---------------- segmented max (used once, for h0) ----------------
__global__ __launch_bounds__(256) void segmax_kernel(
    const float* __restrict__ h, float* __restrict__ out, int P)
{
    int p    = (blockIdx.x * blockDim.x + threadIdx.x) >> 5;
    int lane = threadIdx.x & 31;
    if (p >= P) return;
    int beg = g_offsets[p], end = g_offsets[p + 1];
    float4 m1 = make_float4(0.f, 0.f, 0.f, 0.f);
    float4 m2 = make_float4(0.f, 0.f, 0.f, 0.f);
    int i = beg;
    for (; i + 1 < end; i += 2) {
        float4 v1 = *(const float4*)(h + (size_t)i * HDIM + lane * 4);
        float4 v2 = *(const float4*)(h + (size_t)(i + 1) * HDIM + lane * 4);
        m1.x = fmaxf(m1.x, v1.x); m1.y = fmaxf(m1.y, v1.y);
        m1.z = fmaxf(m1.z, v1.z); m1.w = fmaxf(m1.w, v1.w);
        m2.x = fmaxf(m2.x, v2.x); m2.y = fmaxf(m2.y, v2.y);
        m2.z = fmaxf(m2.z, v2.z); m2.w = fmaxf(m2.w, v2.w);
    }
    if (i < end) {
        float4 v = *(const float4*)(h + (size_t)i * HDIM + lane * 4);
        m1.x = fmaxf(m1.x, v.x); m1.y = fmaxf(m1.y, v.y);
        m1.z = fmaxf(m1.z, v.z); m1.w = fmaxf(m1.w, v.w);
    }
    m1.x = fmaxf(m1.x, m2.x); m1.y = fmaxf(m1.y, m2.y);
    m1.z = fmaxf(m1.z, m2.z); m1.w = fmaxf(m1.w, m2.w);
    *(float4*)(out + (size_t)p * HDIM + lane * 4) = m1;
}

// ---------------- tf32 mma.sync helpers ----------------
__device__ __forceinline__ void cp_async16(float* s, const float* g) {
    unsigned sa = (unsigned)__cvta_generic_to_shared(s);
    asm volatile("cp.async.cg.shared.global [%0], [%1], 16;\n" :: "r"(sa), "l"(g));
}
__device__ __forceinline__ void cp_commit() {
    asm volatile("cp.async.commit_group;\n" ::: "memory");
}
template<int n> __device__ __forceinline__ void cp_wait() {
    asm volatile("cp.async.wait_group %0;\n" :: "n"(n) : "memory");
}
__device__ __forceinline__ void mma_tf32(float acc[4], const unsigned a[4], const unsigned b[2]) {
    asm volatile(
        "mma.sync.aligned.m16n8k8.row.col.f32.tf32.tf32.f32 "
        "{%0,%1,%2,%3},{%4,%5,%6,%7},{%8,%9},{%0,%1,%2,%3};\n"
        : "+f"(acc[0]), "+f"(acc[1]), "+f"(acc[2]), "+f"(acc[3])
        : "r"(a[0]), "r"(a[1]), "r"(a[2]), "r"(a[3]), "r"(b[0]), "r"(b[1]));
}

#define AS_STRIDE 36
#define WS_STRIDE 136
#define AS_BUF (128 * AS_STRIDE)
#define WS_BUF (32 * WS_STRIDE)
#define STAGE_STRIDE 132
#define ENC_SMEM_FLOATS (2*AS_BUF + 2*WS_BUF + 512 + 128 + 8)
#define ENC_SMEM_BYTES (ENC_SMEM_FLOATS * 4)

// ---------------- aggw kernel: aggW = bias + agg @ W_bot  (P x 128, K=128) ---
__global__ __launch_bounds__(256, 2) void aggw_kernel(
    const float* __restrict__ agg, const float* __restrict__ Wb,
    const float* __restrict__ b, float* __restrict__ aggw, int P)
{
    extern __shared__ float sm[];
    float* As  = sm;
    float* Wsm = sm + 2 * AS_BUF;

    const int tid = threadIdx.x;
    const int lane = tid & 31;
    const int quad_r = lane >> 2, quad_c = lane & 3;
    const int warp = tid >> 5;
    const int warp_m = warp >> 1, warp_n = warp & 1;
    const int row0 = blockIdx.x * 128;

    float acc[2][8][4];
#pragma unroll
    for (int nt = 0; nt < 8; nt++) {
        float2 bv = *(const float2*)&b[warp_n * 64 + nt * 8 + quad_c * 2];
#pragma unroll
        for (int mf = 0; mf < 2; mf++) {
            acc[mf][nt][0] = bv.x; acc[mf][nt][1] = bv.y;
            acc[mf][nt][2] = bv.x; acc[mf][nt][3] = bv.y;
        }
    }

    auto issue_chunk = [&](int kc, int buf) {
        float* Ab = As + buf * AS_BUF;
        float* Wc = Wsm + buf * WS_BUF;
#pragma unroll
        for (int i = 0; i < 4; i++) {
            int idx = tid + i * 256;
            int r = idx >> 3, f = idx & 7;
            int gr = row0 + r; if (gr >= P) gr = P - 1;
            cp_async16(Ab + r * AS_STRIDE + f * 4,
                       agg + (size_t)gr * HDIM + kc * 32 + f * 4);
        }
#pragma unroll
        for (int i = 0; i < 4; i++) {
            int idx = tid + i * 256;
            int k = idx >> 5, f = idx & 31;
            cp_async16(Wc + k * WS_STRIDE + f * 4,
                       Wb + (size_t)(kc * 32 + k) * HDIM + f * 4);
        }
        cp_commit();
    };

    issue_chunk(0, 0);

#pragma unroll 1
    for (int kc = 0; kc < 4; kc++) {
        if (kc < 3) { issue_chunk(kc + 1, (kc + 1) & 1); cp_wait<1>(); }
        else        { cp_wait<0>(); }
        __syncthreads();
        const float* Ab = As + (kc & 1) * AS_BUF;
        const float* Wc = Wsm + (kc & 1) * WS_BUF;
#pragma unroll
        for (int ks = 0; ks < 4; ks++) {
            const int kk = ks * 8;
            unsigned afr[2][4];
#pragma unroll
            for (int mf = 0; mf < 2; mf++) {
                const float* p = Ab + (warp_m * 32 + mf * 16 + quad_r) * AS_STRIDE
                                    + kk + quad_c;
                afr[mf][0] = __float_as_uint(p[0]);
                afr[mf][1] = __float_as_uint(p[8 * AS_STRIDE]);
                afr[mf][2] = __float_as_uint(p[4]);
                afr[mf][3] = __float_as_uint(p[8 * AS_STRIDE + 4]);
            }
            unsigned bfr[8][2];
#pragma unroll
            for (int nt = 0; nt < 8; nt++) {
                const float* p = Wc + (kk + quad_c) * WS_STRIDE
                                    + warp_n * 64 + nt * 8 + quad_r;
                bfr[nt][0] = __float_as_uint(p[0]);
                bfr[nt][1] = __float_as_uint(p[4 * WS_STRIDE]);
            }
#pragma unroll
            for (int mf = 0; mf < 2; mf++)
#pragma unroll
                for (int nt = 0; nt < 8; nt++)
                    mma_tf32(acc[mf][nt], afr[mf], bfr[nt]);
        }
        __syncthreads();
    }

#pragma unroll
    for (int nt = 0; nt < 8; nt++) {
        int col = warp_n * 64 + nt * 8 + quad_c * 2;
#pragma unroll
        for (int mf = 0; mf < 2; mf++)
#pragma unroll
            for (int h = 0; h < 2; h++) {
                int grow = row0 + warp_m * 32 + mf * 16 + h * 8 + quad_r;
                if (grow < P)
                    *(float2*)(aggw + (size_t)grow * HDIM + col) =
                        make_float2(acc[mf][nt][2 * h], acc[mf][nt][2 * h + 1]);
            }
    }
}

// ---------------- encoder 1/2 with fused segmented max -----------------------
// z = h @ W_top + aggW[sid]; LN; ReLU -> (optional) hout; per-CTA segment max
// -> maxout (direct store for interior segments, atomicMax for the <=2
// boundary segments). maxout must be zero-initialized.
__global__ __launch_bounds__(256, 2) void enc_kernel(
    const float* __restrict__ hprev, const float* __restrict__ aggw,
    const float* __restrict__ Wt, const float* __restrict__ gw,
    const float* __restrict__ be, float* __restrict__ hout,
    float* __restrict__ maxout, int N)
{
    extern __shared__ float sm[];
    float* As   = sm;
    float* Wsm  = sm + 2 * AS_BUF;
    float* stage = sm;                                   // reused post-mainloop
    float2* red2 = (float2*)(sm + 2*AS_BUF + 2*WS_BUF);  // 512 floats
    int*   sidp = (int*)(sm + 2*AS_BUF + 2*WS_BUF + 512); // 128 ints
    int*   spill = sidp + 128;                            // 2 ints

    const int tid = threadIdx.x;
    const int lane = tid & 31;
    const int quad_r = lane >> 2, quad_c = lane & 3;
    const int warp = tid >> 5;
    const int warp_m = warp >> 1, warp_n = warp & 1;
    const int row0 = blockIdx.x * 128;

    if (tid < 128) {
        int r = row0 + tid;
        sidp[tid] = g_sid[(r < N) ? r : (N - 1)];
    }
    __syncthreads();
    if (tid == 0) {
        int pf = sidp[0], pl = sidp[127];
        spill[0] = (g_offsets[pf] < row0)        ? pf : -1;
        spill[1] = (g_offsets[pl + 1] > row0 + 128) ? pl : -1;
    }

    auto issue_chunk = [&](int kc, int buf) {
        float* Ab = As + buf * AS_BUF;
        float* Wc = Wsm + buf * WS_BUF;
#pragma unroll
        for (int i = 0; i < 4; i++) {
            int idx = tid + i * 256;
            int r = idx >> 3, f = idx & 7;
            int gr = row0 + r; if (gr >= N) gr = N - 1;
            cp_async16(Ab + r * AS_STRIDE + f * 4,
                       hprev + (size_t)gr * HDIM + kc * 32 + f * 4);
        }
#pragma unroll
        for (int i = 0; i < 4; i++) {
            int idx = tid + i * 256;
            int k = idx >> 5, f = idx & 31;
            cp_async16(Wc + k * WS_STRIDE + f * 4,
                       Wt + (size_t)(kc * 32 + k) * HDIM + f * 4);
        }
        cp_commit();
    };

    issue_chunk(0, 0);

    // accumulator init = aggW[sid] gather (L2-resident table)
    float acc[2][8][4];
#pragma unroll
    for (int mf = 0; mf < 2; mf++)
#pragma unroll
        for (int h = 0; h < 2; h++) {
            int rl = warp_m * 32 + mf * 16 + h * 8 + quad_r;
            const float* base = aggw + (size_t)sidp[rl] * HDIM;
#pragma unroll
            for (int nt = 0; nt < 8; nt++) {
                float2 v = *(const float2*)(base + warp_n * 64 + nt * 8 + quad_c * 2);
                acc[mf][nt][2 * h]     = v.x;
                acc[mf][nt][2 * h + 1] = v.y;
            }
        }

#pragma unroll 1
    for (int kc = 0; kc < 4; kc++) {
        if (kc < 3) { issue_chunk(kc + 1, (kc + 1) & 1); cp_wait<1>(); }
        else        { cp_wait<0>(); }
        __syncthreads();

        const float* Ab = As + (kc & 1) * AS_BUF;
        const float* Wc = Wsm + (kc & 1) * WS_BUF;
#pragma unroll
        for (int ks = 0; ks < 4; ks++) {
            const int kk = ks * 8;
            unsigned afr[2][4];
#pragma unroll
            for (int mf = 0; mf < 2; mf++) {
                const float* p = Ab + (warp_m * 32 + mf * 16 + quad_r) * AS_STRIDE
                                    + kk + quad_c;
                afr[mf][0] = __float_as_uint(p[0]);
                afr[mf][1] = __float_as_uint(p[8 * AS_STRIDE]);
                afr[mf][2] = __float_as_uint(p[4]);
                afr[mf][3] = __float_as_uint(p[8 * AS_STRIDE + 4]);
            }
            unsigned bfr[8][2];
#pragma unroll
            for (int nt = 0; nt < 8; nt++) {
                const float* p = Wc + (kk + quad_c) * WS_STRIDE
                                    + warp_n * 64 + nt * 8 + quad_r;
                bfr[nt][0] = __float_as_uint(p[0]);
                bfr[nt][1] = __float_as_uint(p[4 * WS_STRIDE]);
            }
#pragma unroll
            for (int mf = 0; mf < 2; mf++)
#pragma unroll
                for (int nt = 0; nt < 8; nt++)
                    mma_tf32(acc[mf][nt], afr[mf], bfr[nt]);
        }
        __syncthreads();
    }

    // ---- LayerNorm statistics ----
    float s[2][2], q[2][2];
#pragma unroll
    for (int mf = 0; mf < 2; mf++)
#pragma unroll
        for (int h = 0; h < 2; h++) {
            float ss = 0.f, qq = 0.f;
#pragma unroll
            for (int nt = 0; nt < 8; nt++) {
                float z0 = acc[mf][nt][2 * h], z1 = acc[mf][nt][2 * h + 1];
                ss += z0 + z1;
                qq += z0 * z0 + z1 * z1;
            }
            s[mf][h] = ss; q[mf][h] = qq;
        }
#pragma unroll
    for (int mk = 1; mk <= 2; mk <<= 1)
#pragma unroll
        for (int mf = 0; mf < 2; mf++)
#pragma unroll
            for (int h = 0; h < 2; h++) {
                s[mf][h] += __shfl_xor_sync(0xffffffffu, s[mf][h], mk);
                q[mf][h] += __shfl_xor_sync(0xffffffffu, q[mf][h], mk);
            }
    if (quad_c == 0) {
#pragma unroll
        for (int mf = 0; mf < 2; mf++)
#pragma unroll
            for (int h = 0; h < 2; h++) {
                int rl = warp_m * 32 + mf * 16 + h * 8 + quad_r;
                red2[rl * 2 + warp_n] = make_float2(s[mf][h], q[mf][h]);
            }
    }
    __syncthreads();
    float mu[2][2], rs[2][2];
#pragma unroll
    for (int mf = 0; mf < 2; mf++)
#pragma unroll
        for (int h = 0; h < 2; h++) {
            int rl = warp_m * 32 + mf * 16 + h * 8 + quad_r;
            float2 r0 = red2[rl * 2 + 0], r1 = red2[rl * 2 + 1];
            float ss = r0.x + r1.x, qq = r0.y + r1.y;
            float m = ss * (1.f / HDIM);
            float var = fmaf(qq, 1.f / HDIM, -m * m);
            mu[mf][h] = m;
            rs[mf][h] = rsqrtf(var + LN_EPS);
        }
    __syncthreads();   // all warps done reading As/Wsm & red2 before staging

    // ---- normalize + ReLU: store to hout (optional) and stage for segmax ----
#pragma unroll
    for (int nt = 0; nt < 8; nt++) {
        int col = warp_n * 64 + nt * 8 + quad_c * 2;
        float2 gv = *(const float2*)&gw[col];
        float2 ev = *(const float2*)&be[col];
#pragma unroll
        for (int mf = 0; mf < 2; mf++)
#pragma unroll
            for (int h = 0; h < 2; h++) {
                int rl = warp_m * 32 + mf * 16 + h * 8 + quad_r;
                float z0 = acc[mf][nt][2 * h], z1 = acc[mf][nt][2 * h + 1];
                float2 o;
                o.x = fmaxf(fmaf((z0 - mu[mf][h]) * rs[mf][h], gv.x, ev.x), 0.f);
                o.y = fmaxf(fmaf((z1 - mu[mf][h]) * rs[mf][h], gv.y, ev.y), 0.f);
                *(float2*)&stage[rl * STAGE_STRIDE + col] = o;
                int grow = row0 + rl;
                if (hout && grow < N)
                    *(float2*)(hout + (size_t)grow * HDIM + col) = o;
            }
    }
    __syncthreads();

    // ---- fused segmented max: one thread per column scans 128 rows ----
    if (tid < 128) {
        const int col = tid;
        const int sf = spill[0], sl = spill[1];
        int cur = sidp[0];
        float cm = stage[col];
#pragma unroll 4
        for (int r = 1; r < 128; r++) {
            int sv = sidp[r];
            float v = stage[r * STAGE_STRIDE + col];
            if (sv != cur) {
                if (cur == sf || cur == sl)
                    atomicMax((int*)&maxout[(size_t)cur * HDIM + col],
                              __float_as_int(cm));
                else
                    maxout[(size_t)cur * HDIM + col] = cm;
                cur = sv; cm = v;
            } else {
                cm = fmaxf(cm, v);
            }
        }
        if (cur == sf || cur == sl)
            atomicMax((int*)&maxout[(size_t)cur * HDIM + col], __float_as_int(cm));
        else
            maxout[(size_t)cur * HDIM + col] = cm;
    }
}

// ---------------- output tail ----------------
__global__ void tail_kernel(float* out, int tail) {
    int i = blockIdx.x * blockDim.x + threadIdx.x;
    float* base = out + (size_t)PNUM * HDIM;
    if (tail == PNUM) {
        if (i < PNUM) base[i] = (float)i;
    } else if (tail == 2 * PNUM) {
        if (i < PNUM) ((long long*)base)[i] = (long long)i;
    } else {
        if (i < tail) base[i] = (float)i;
    }
}

// ---------------- launch ----------------
extern "C" void kernel_launch(void* const* d_in, const int* in_sizes, int n_in,
                              void* d_out, int out_size) {
    const float* x   = (const float*)d_in[0];
    const void*  ids = d_in[1];
    const float* W0  = (const float*)d_in[2];
    const float* b0  = (const float*)d_in[3];
    const float* g0  = (const float*)d_in[4];
    const float* be0 = (const float*)d_in[5];
    const float* W1  = (const float*)d_in[6];
    const float* b1  = (const float*)d_in[7];
    const float* g1  = (const float*)d_in[8];
    const float* be1 = (const float*)d_in[9];
    const float* W2  = (const float*)d_in[10];
    const float* b2  = (const float*)d_in[11];
    const float* g2  = (const float*)d_in[12];
    const float* be2 = (const float*)d_in[13];

    const int N = in_sizes[0] / 9;
    const int P = PNUM;
    float* out = (float*)d_out;

    float *h0, *h1, *agg, *aggw;
    int* counts;
    cudaGetSymbolAddress((void**)&h0,   g_h0);
    cudaGetSymbolAddress((void**)&h1,   g_h1);
    cudaGetSymbolAddress((void**)&agg,  g_agg);
    cudaGetSymbolAddress((void**)&aggw, g_aggw);
    cudaGetSymbolAddress((void**)&counts, g_counts);

    cudaFuncSetAttribute(enc_kernel,
        cudaFuncAttributeMaxDynamicSharedMemorySize, ENC_SMEM_BYTES);
    cudaFuncSetAttribute(aggw_kernel,
        cudaFuncAttributeMaxDynamicSharedMemorySize, ENC_SMEM_BYTES);

    // 1) id normalization + CSR build (sorted order)
    detect_ids_kernel<<<1, 1>>>(ids);
    cudaMemsetAsync(counts, 0, (size_t)P * sizeof(int));
    prep_kernel<<<(N + 255) / 256, 256>>>(ids, N);
    scan_kernel<<<1, 1024>>>();
    scatter_kernel<<<(N + 255) / 256, 256>>>(N);

    // 2) enc0 -> h0 (sorted space)
    enc0_kernel<<<(N + 7) / 8, 256>>>(x, W0, b0, g0, be0, h0, N);

    // 3) layer 1: seg_max(h0) -> agg; aggW; enc1 -> h1 + fused seg_max -> agg
    segmax_kernel<<<(P + 7) / 8, 256>>>(h0, agg, P);
    aggw_kernel<<<(P + 127) / 128, 256, ENC_SMEM_BYTES>>>(
        agg, W1 + (size_t)HDIM * HDIM, b1, aggw, P);
    cudaMemsetAsync(agg, 0, (size_t)P * HDIM * sizeof(float));
    enc_kernel<<<(N + 127) / 128, 256, ENC_SMEM_BYTES>>>(
        h0, aggw, W1, g1, be1, h1, agg, N);

    // 4) layer 2: aggW; enc2 (no h store) + fused seg_max -> out
    aggw_kernel<<<(P + 127) / 128, 256, ENC_SMEM_BYTES>>>(
        agg, W2 + (size_t)HDIM * HDIM, b2, aggw, P);
    cudaMemsetAsync(out, 0, (size_t)P * HDIM * sizeof(float));
    enc_kernel<<<(N + 127) / 128, 256, ENC_SMEM_BYTES>>>(
        h1, aggw, W2, g2, be2, nullptr, out, N);

    // 5) arange tail
    int tail = out_size - P * HDIM;
    if (tail > 0) {
        int elems = (tail == 2 * PNUM) ? PNUM : tail;
        tail_kernel<<<(elems + 255) / 256, 256>>>(out, tail);
    }
}

// round 8
// speedup vs baseline: 1.1276x; 1.1276x over previous
#include <cuda_runtime.h>
#include <cstdint>

#define HDIM 128
#define NMAX 500000
#define PNUM 50000
#define LN_EPS 1e-5f

// ---------------- scratch (static __device__; no allocation) ----------------
__device__ float g_h0[(size_t)NMAX * HDIM];
__device__ float g_h1[(size_t)NMAX * HDIM];
__device__ float g_agg[(size_t)PNUM * HDIM];
__device__ float g_agg2[(size_t)PNUM * HDIM];
__device__ float g_aggw[(size_t)PNUM * HDIM];
__device__ int   g_counts[PNUM];
__device__ int   g_offsets[PNUM + 1];
__device__ int   g_cursor[PNUM];
__device__ int   g_order[NMAX];   // sorted position -> original row
__device__ int   g_ids[NMAX];     // original row -> id
__device__ int   g_sid[NMAX];     // sorted position -> id (non-decreasing)
__device__ int   g_ids64;

// ---------------- id dtype detection ----------------
__global__ void detect_ids_kernel(const void* idsraw) {
    const long long* a = (const long long*)idsraw;
    int ok = 1;
    for (int i = 0; i < 16; i++) {
        long long v = a[i];
        if (v < 0 || v >= PNUM) ok = 0;
    }
    g_ids64 = ok;
}

__global__ void prep_kernel(const void* idsraw, int N) {
    int i = blockIdx.x * blockDim.x + threadIdx.x;
    if (i >= N) return;
    int v = g_ids64 ? (int)((const long long*)idsraw)[i]
                    : ((const int*)idsraw)[i];
    g_ids[i] = v;
    atomicAdd(&g_counts[v], 1);
}

__global__ void scan_kernel() {
    __shared__ int sums[1024];
    int t = threadIdx.x;
    const int per = (PNUM + 1023) / 1024;
    int start = t * per;
    int end = start + per; if (end > PNUM) end = PNUM;
    int s = 0;
    for (int i = start; i < end; i++) s += g_counts[i];
    sums[t] = s;
    __syncthreads();
    for (int off = 1; off < 1024; off <<= 1) {
        int v = (t >= off) ? sums[t - off] : 0;
        __syncthreads();
        sums[t] += v;
        __syncthreads();
    }
    int run = (t == 0) ? 0 : sums[t - 1];
    for (int i = start; i < end; i++) {
        g_offsets[i] = run;
        g_cursor[i] = run;
        run += g_counts[i];
    }
    if (t == 1023) g_offsets[PNUM] = run;
}

__global__ void scatter_kernel(int N) {
    int i = blockIdx.x * blockDim.x + threadIdx.x;
    if (i >= N) return;
    int id = g_ids[i];
    int pos = atomicAdd(&g_cursor[id], 1);
    g_order[pos] = i;
    g_sid[pos] = id;
}

// ---------------- encoder 0 (sorted output space) ----------------
__global__ __launch_bounds__(256) void enc0_kernel(
    const float* __restrict__ x, const float* __restrict__ W0,
    const float* __restrict__ b0, const float* __restrict__ g0,
    const float* __restrict__ be0, float* __restrict__ out, int N)
{
    int spos = (blockIdx.x * blockDim.x + threadIdx.x) >> 5;
    int lane = threadIdx.x & 31;
    if (spos >= N) return;
    int srow = g_order[spos];

    float xv = (lane < 9) ? x[(size_t)srow * 9 + lane] : 0.f;
    float z[4];
#pragma unroll
    for (int c = 0; c < 4; c++) z[c] = b0[lane + 32 * c];
#pragma unroll
    for (int k = 0; k < 9; k++) {
        float xk = __shfl_sync(0xffffffffu, xv, k);
#pragma unroll
        for (int c = 0; c < 4; c++)
            z[c] = fmaf(xk, W0[k * HDIM + lane + 32 * c], z[c]);
    }
    float s  = z[0] + z[1] + z[2] + z[3];
    float s2 = z[0]*z[0] + z[1]*z[1] + z[2]*z[2] + z[3]*z[3];
#pragma unroll
    for (int o = 16; o > 0; o >>= 1) {
        s  += __shfl_xor_sync(0xffffffffu, s, o);
        s2 += __shfl_xor_sync(0xffffffffu, s2, o);
    }
    float mu  = s * (1.f / HDIM);
    float var = fmaf(s2, 1.f / HDIM, -mu * mu);
    float rs  = rsqrtf(var + LN_EPS);
#pragma unroll
    for (int c = 0; c < 4; c++) {
        int j = lane + 32 * c;
        float v = fmaf((z[c] - mu) * rs, g0[j], be0[j]);
        out[(size_t)spos * HDIM + j] = fmaxf(v, 0.f);
    }
}

// ---------------- segmented max (used once, for h0) ----------------
__global__ __launch_bounds__(256) void segmax_kernel(
    const float* __restrict__ h, float* __restrict__ out, int P)
{
    int p    = (blockIdx.x * blockDim.x + threadIdx.x) >> 5;
    int lane = threadIdx.x & 31;
    if (p >= P) return;
    int beg = g_offsets[p], end = g_offsets[p + 1];
    float4 m1 = make_float4(0.f, 0.f, 0.f, 0.f);
    float4 m2 = make_float4(0.f, 0.f, 0.f, 0.f);
    int i = beg;
    for (; i + 1 < end; i += 2) {
        float4 v1 = *(const float4*)(h + (size_t)i * HDIM + lane * 4);
        float4 v2 = *(const float4*)(h + (size_t)(i + 1) * HDIM + lane * 4);
        m1.x = fmaxf(m1.x, v1.x); m1.y = fmaxf(m1.y, v1.y);
        m1.z = fmaxf(m1.z, v1.z); m1.w = fmaxf(m1.w, v1.w);
        m2.x = fmaxf(m2.x, v2.x); m2.y = fmaxf(m2.y, v2.y);
        m2.z = fmaxf(m2.z, v2.z); m2.w = fmaxf(m2.w, v2.w);
    }
    if (i < end) {
        float4 v = *(const float4*)(h + (size_t)i * HDIM + lane * 4);
        m1.x = fmaxf(m1.x, v.x); m1.y = fmaxf(m1.y, v.y);
        m1.z = fmaxf(m1.z, v.z); m1.w = fmaxf(m1.w, v.w);
    }
    m1.x = fmaxf(m1.x, m2.x); m1.y = fmaxf(m1.y, m2.y);
    m1.z = fmaxf(m1.z, m2.z); m1.w = fmaxf(m1.w, m2.w);
    *(float4*)(out + (size_t)p * HDIM + lane * 4) = m1;
}

// ---------------- tf32 mma.sync helpers ----------------
__device__ __forceinline__ void cp_async16(float* s, const float* g) {
    unsigned sa = (unsigned)__cvta_generic_to_shared(s);
    asm volatile("cp.async.cg.shared.global [%0], [%1], 16;\n" :: "r"(sa), "l"(g));
}
__device__ __forceinline__ void cp_commit() {
    asm volatile("cp.async.commit_group;\n" ::: "memory");
}
template<int n> __device__ __forceinline__ void cp_wait() {
    asm volatile("cp.async.wait_group %0;\n" :: "n"(n) : "memory");
}
__device__ __forceinline__ void mma_tf32(float acc[4], const unsigned a[4], const unsigned b[2]) {
    asm volatile(
        "mma.sync.aligned.m16n8k8.row.col.f32.tf32.tf32.f32 "
        "{%0,%1,%2,%3},{%4,%5,%6,%7},{%8,%9},{%0,%1,%2,%3};\n"
        : "+f"(acc[0]), "+f"(acc[1]), "+f"(acc[2]), "+f"(acc[3])
        : "r"(a[0]), "r"(a[1]), "r"(a[2]), "r"(a[3]), "r"(b[0]), "r"(b[1]));
}

#define AS_STRIDE 36
#define WS_STRIDE 136
#define AS_BUF (128 * AS_STRIDE)
#define WS_BUF (32 * WS_STRIDE)
#define STAGE_STRIDE 132
#define ENC_SMEM_FLOATS (2*AS_BUF + 2*WS_BUF + 512 + 128)
#define ENC_SMEM_BYTES (ENC_SMEM_FLOATS * 4)

// ---------------- aggw kernel: aggW = bias + agg @ W_bot  (P x 128, K=128) ---
__global__ __launch_bounds__(256, 2) void aggw_kernel(
    const float* __restrict__ agg, const float* __restrict__ Wb,
    const float* __restrict__ b, float* __restrict__ aggw, int P)
{
    extern __shared__ float sm[];
    float* As  = sm;
    float* Wsm = sm + 2 * AS_BUF;

    const int tid = threadIdx.x;
    const int lane = tid & 31;
    const int quad_r = lane >> 2, quad_c = lane & 3;
    const int warp = tid >> 5;
    const int warp_m = warp >> 1, warp_n = warp & 1;
    const int row0 = blockIdx.x * 128;

    float acc[2][8][4];
#pragma unroll
    for (int nt = 0; nt < 8; nt++) {
        float2 bv = *(const float2*)&b[warp_n * 64 + nt * 8 + quad_c * 2];
#pragma unroll
        for (int mf = 0; mf < 2; mf++) {
            acc[mf][nt][0] = bv.x; acc[mf][nt][1] = bv.y;
            acc[mf][nt][2] = bv.x; acc[mf][nt][3] = bv.y;
        }
    }

    auto issue_chunk = [&](int kc, int buf) {
        float* Ab = As + buf * AS_BUF;
        float* Wc = Wsm + buf * WS_BUF;
#pragma unroll
        for (int i = 0; i < 4; i++) {
            int idx = tid + i * 256;
            int r = idx >> 3, f = idx & 7;
            int gr = row0 + r; if (gr >= P) gr = P - 1;
            cp_async16(Ab + r * AS_STRIDE + f * 4,
                       agg + (size_t)gr * HDIM + kc * 32 + f * 4);
        }
#pragma unroll
        for (int i = 0; i < 4; i++) {
            int idx = tid + i * 256;
            int k = idx >> 5, f = idx & 31;
            cp_async16(Wc + k * WS_STRIDE + f * 4,
                       Wb + (size_t)(kc * 32 + k) * HDIM + f * 4);
        }
        cp_commit();
    };

    issue_chunk(0, 0);

#pragma unroll 1
    for (int kc = 0; kc < 4; kc++) {
        if (kc < 3) { issue_chunk(kc + 1, (kc + 1) & 1); cp_wait<1>(); }
        else        { cp_wait<0>(); }
        __syncthreads();
        const float* Ab = As + (kc & 1) * AS_BUF;
        const float* Wc = Wsm + (kc & 1) * WS_BUF;
#pragma unroll
        for (int ks = 0; ks < 4; ks++) {
            const int kk = ks * 8;
            unsigned afr[2][4];
#pragma unroll
            for (int mf = 0; mf < 2; mf++) {
                const float* p = Ab + (warp_m * 32 + mf * 16 + quad_r) * AS_STRIDE
                                    + kk + quad_c;
                afr[mf][0] = __float_as_uint(p[0]);
                afr[mf][1] = __float_as_uint(p[8 * AS_STRIDE]);
                afr[mf][2] = __float_as_uint(p[4]);
                afr[mf][3] = __float_as_uint(p[8 * AS_STRIDE + 4]);
            }
            unsigned bfr[8][2];
#pragma unroll
            for (int nt = 0; nt < 8; nt++) {
                const float* p = Wc + (kk + quad_c) * WS_STRIDE
                                    + warp_n * 64 + nt * 8 + quad_r;
                bfr[nt][0] = __float_as_uint(p[0]);
                bfr[nt][1] = __float_as_uint(p[4 * WS_STRIDE]);
            }
#pragma unroll
            for (int mf = 0; mf < 2; mf++)
#pragma unroll
                for (int nt = 0; nt < 8; nt++)
                    mma_tf32(acc[mf][nt], afr[mf], bfr[nt]);
        }
        __syncthreads();
    }

#pragma unroll
    for (int nt = 0; nt < 8; nt++) {
        int col = warp_n * 64 + nt * 8 + quad_c * 2;
#pragma unroll
        for (int mf = 0; mf < 2; mf++)
#pragma unroll
            for (int h = 0; h < 2; h++) {
                int grow = row0 + warp_m * 32 + mf * 16 + h * 8 + quad_r;
                if (grow < P)
                    *(float2*)(aggw + (size_t)grow * HDIM + col) =
                        make_float2(acc[mf][nt][2 * h], acc[mf][nt][2 * h + 1]);
            }
    }
}

// ---------------- encoder 1/2 with fused segmented max -----------------------
// z = h @ W_top + aggW[sid]; LN; ReLU -> (optional) hout; warp-per-segment
// max over the staged tile -> maxout (direct store interior, atomicMax for
// the <=2 boundary segments). maxout must be zero-initialized.
__global__ __launch_bounds__(256, 2) void enc_kernel(
    const float* __restrict__ hprev, const float* __restrict__ aggw,
    const float* __restrict__ Wt, const float* __restrict__ gw,
    const float* __restrict__ be, float* __restrict__ hout,
    float* __restrict__ maxout, int N)
{
    extern __shared__ float sm[];
    float* As   = sm;
    float* Wsm  = sm + 2 * AS_BUF;
    float* stage = sm;                                   // reused post-mainloop
    float2* red2 = (float2*)(sm + 2*AS_BUF + 2*WS_BUF);  // 512 floats
    int*   sidp = (int*)(sm + 2*AS_BUF + 2*WS_BUF + 512); // 128 ints

    const int tid = threadIdx.x;
    const int lane = tid & 31;
    const int quad_r = lane >> 2, quad_c = lane & 3;
    const int warp = tid >> 5;
    const int warp_m = warp >> 1, warp_n = warp & 1;
    const int row0 = blockIdx.x * 128;

    if (tid < 128) {
        int r = row0 + tid;
        sidp[tid] = g_sid[(r < N) ? r : (N - 1)];
    }
    __syncthreads();

    auto issue_chunk = [&](int kc, int buf) {
        float* Ab = As + buf * AS_BUF;
        float* Wc = Wsm + buf * WS_BUF;
#pragma unroll
        for (int i = 0; i < 4; i++) {
            int idx = tid + i * 256;
            int r = idx >> 3, f = idx & 7;
            int gr = row0 + r; if (gr >= N) gr = N - 1;
            cp_async16(Ab + r * AS_STRIDE + f * 4,
                       hprev + (size_t)gr * HDIM + kc * 32 + f * 4);
        }
#pragma unroll
        for (int i = 0; i < 4; i++) {
            int idx = tid + i * 256;
            int k = idx >> 5, f = idx & 31;
            cp_async16(Wc + k * WS_STRIDE + f * 4,
                       Wt + (size_t)(kc * 32 + k) * HDIM + f * 4);
        }
        cp_commit();
    };

    issue_chunk(0, 0);

    // accumulator init = aggW[sid] gather (L2-resident table)
    float acc[2][8][4];
#pragma unroll
    for (int mf = 0; mf < 2; mf++)
#pragma unroll
        for (int h = 0; h < 2; h++) {
            int rl = warp_m * 32 + mf * 16 + h * 8 + quad_r;
            const float* base = aggw + (size_t)sidp[rl] * HDIM;
#pragma unroll
            for (int nt = 0; nt < 8; nt++) {
                float2 v = *(const float2*)(base + warp_n * 64 + nt * 8 + quad_c * 2);
                acc[mf][nt][2 * h]     = v.x;
                acc[mf][nt][2 * h + 1] = v.y;
            }
        }

#pragma unroll 1
    for (int kc = 0; kc < 4; kc++) {
        if (kc < 3) { issue_chunk(kc + 1, (kc + 1) & 1); cp_wait<1>(); }
        else        { cp_wait<0>(); }
        __syncthreads();

        const float* Ab = As + (kc & 1) * AS_BUF;
        const float* Wc = Wsm + (kc & 1) * WS_BUF;
#pragma unroll
        for (int ks = 0; ks < 4; ks++) {
            const int kk = ks * 8;
            unsigned afr[2][4];
#pragma unroll
            for (int mf = 0; mf < 2; mf++) {
                const float* p = Ab + (warp_m * 32 + mf * 16 + quad_r) * AS_STRIDE
                                    + kk + quad_c;
                afr[mf][0] = __float_as_uint(p[0]);
                afr[mf][1] = __float_as_uint(p[8 * AS_STRIDE]);
                afr[mf][2] = __float_as_uint(p[4]);
                afr[mf][3] = __float_as_uint(p[8 * AS_STRIDE + 4]);
            }
            unsigned bfr[8][2];
#pragma unroll
            for (int nt = 0; nt < 8; nt++) {
                const float* p = Wc + (kk + quad_c) * WS_STRIDE
                                    + warp_n * 64 + nt * 8 + quad_r;
                bfr[nt][0] = __float_as_uint(p[0]);
                bfr[nt][1] = __float_as_uint(p[4 * WS_STRIDE]);
            }
#pragma unroll
            for (int mf = 0; mf < 2; mf++)
#pragma unroll
                for (int nt = 0; nt < 8; nt++)
                    mma_tf32(acc[mf][nt], afr[mf], bfr[nt]);
        }
        __syncthreads();
    }

    // ---- LayerNorm statistics ----
    float s[2][2], q[2][2];
#pragma unroll
    for (int mf = 0; mf < 2; mf++)
#pragma unroll
        for (int h = 0; h < 2; h++) {
            float ss = 0.f, qq = 0.f;
#pragma unroll
            for (int nt = 0; nt < 8; nt++) {
                float z0 = acc[mf][nt][2 * h], z1 = acc[mf][nt][2 * h + 1];
                ss += z0 + z1;
                qq += z0 * z0 + z1 * z1;
            }
            s[mf][h] = ss; q[mf][h] = qq;
        }
#pragma unroll
    for (int mk = 1; mk <= 2; mk <<= 1)
#pragma unroll
        for (int mf = 0; mf < 2; mf++)
#pragma unroll
            for (int h = 0; h < 2; h++) {
                s[mf][h] += __shfl_xor_sync(0xffffffffu, s[mf][h], mk);
                q[mf][h] += __shfl_xor_sync(0xffffffffu, q[mf][h], mk);
            }
    if (quad_c == 0) {
#pragma unroll
        for (int mf = 0; mf < 2; mf++)
#pragma unroll
            for (int h = 0; h < 2; h++) {
                int rl = warp_m * 32 + mf * 16 + h * 8 + quad_r;
                red2[rl * 2 + warp_n] = make_float2(s[mf][h], q[mf][h]);
            }
    }
    __syncthreads();
    float mu[2][2], rs[2][2];
#pragma unroll
    for (int mf = 0; mf < 2; mf++)
#pragma unroll
        for (int h = 0; h < 2; h++) {
            int rl = warp_m * 32 + mf * 16 + h * 8 + quad_r;
            float2 r0 = red2[rl * 2 + 0], r1 = red2[rl * 2 + 1];
            float ss = r0.x + r1.x, qq = r0.y + r1.y;
            float m = ss * (1.f / HDIM);
            float var = fmaf(qq, 1.f / HDIM, -m * m);
            mu[mf][h] = m;
            rs[mf][h] = rsqrtf(var + LN_EPS);
        }
    __syncthreads();   // all warps done with As/Wsm/red2 before staging

    // ---- normalize + ReLU: store to hout (optional) and stage for segmax ----
#pragma unroll
    for (int nt = 0; nt < 8; nt++) {
        int col = warp_n * 64 + nt * 8 + quad_c * 2;
        float2 gv = *(const float2*)&gw[col];
        float2 ev = *(const float2*)&be[col];
#pragma unroll
        for (int mf = 0; mf < 2; mf++)
#pragma unroll
            for (int h = 0; h < 2; h++) {
                int rl = warp_m * 32 + mf * 16 + h * 8 + quad_r;
                float z0 = acc[mf][nt][2 * h], z1 = acc[mf][nt][2 * h + 1];
                float2 o;
                o.x = fmaxf(fmaf((z0 - mu[mf][h]) * rs[mf][h], gv.x, ev.x), 0.f);
                o.y = fmaxf(fmaf((z1 - mu[mf][h]) * rs[mf][h], gv.y, ev.y), 0.f);
                *(float2*)&stage[rl * STAGE_STRIDE + col] = o;
                int grow = row0 + rl;
                if (hout && grow < N)
                    *(float2*)(hout + (size_t)grow * HDIM + col) = o;
            }
    }
    __syncthreads();

    // ---- fused segmented max: warp-per-segment over the staged tile ----
    {
        const int p_first = sidp[0];
        const int p_last  = sidp[127];
        for (int seg = p_first + warp; seg <= p_last; seg += 8) {
            int b = g_offsets[seg], e = g_offsets[seg + 1];
            int r0 = b - row0; if (r0 < 0) r0 = 0;
            int r1 = e - row0; if (r1 > 128) r1 = 128;
            if (r1 <= r0) continue;                     // empty segment
            float4 m = make_float4(0.f, 0.f, 0.f, 0.f);
            for (int r = r0; r < r1; r++) {
                float4 v = *(const float4*)&stage[r * STAGE_STRIDE + lane * 4];
                m.x = fmaxf(m.x, v.x); m.y = fmaxf(m.y, v.y);
                m.z = fmaxf(m.z, v.z); m.w = fmaxf(m.w, v.w);
            }
            float* dst = maxout + (size_t)seg * HDIM + lane * 4;
            bool bnd = (b < row0) || (e > row0 + 128);
            if (bnd) {
                atomicMax((int*)dst + 0, __float_as_int(m.x));
                atomicMax((int*)dst + 1, __float_as_int(m.y));
                atomicMax((int*)dst + 2, __float_as_int(m.z));
                atomicMax((int*)dst + 3, __float_as_int(m.w));
            } else {
                *(float4*)dst = m;
            }
        }
    }
}

// ---------------- output tail ----------------
__global__ void tail_kernel(float* out, int tail) {
    int i = blockIdx.x * blockDim.x + threadIdx.x;
    float* base = out + (size_t)PNUM * HDIM;
    if (tail == PNUM) {
        if (i < PNUM) base[i] = (float)i;
    } else if (tail == 2 * PNUM) {
        if (i < PNUM) ((long long*)base)[i] = (long long)i;
    } else {
        if (i < tail) base[i] = (float)i;
    }
}

// ---------------- launch ----------------
extern "C" void kernel_launch(void* const* d_in, const int* in_sizes, int n_in,
                              void* d_out, int out_size) {
    const float* x   = (const float*)d_in[0];
    const void*  ids = d_in[1];
    const float* W0  = (const float*)d_in[2];
    const float* b0  = (const float*)d_in[3];
    const float* g0  = (const float*)d_in[4];
    const float* be0 = (const float*)d_in[5];
    const float* W1  = (const float*)d_in[6];
    const float* b1  = (const float*)d_in[7];
    const float* g1  = (const float*)d_in[8];
    const float* be1 = (const float*)d_in[9];
    const float* W2  = (const float*)d_in[10];
    const float* b2  = (const float*)d_in[11];
    const float* g2  = (const float*)d_in[12];
    const float* be2 = (const float*)d_in[13];

    const int N = in_sizes[0] / 9;
    const int P = PNUM;
    float* out = (float*)d_out;

    float *h0, *h1, *agg, *agg2, *aggw;
    int* counts;
    cudaGetSymbolAddress((void**)&h0,   g_h0);
    cudaGetSymbolAddress((void**)&h1,   g_h1);
    cudaGetSymbolAddress((void**)&agg,  g_agg);
    cudaGetSymbolAddress((void**)&agg2, g_agg2);
    cudaGetSymbolAddress((void**)&aggw, g_aggw);
    cudaGetSymbolAddress((void**)&counts, g_counts);

    cudaFuncSetAttribute(enc_kernel,
        cudaFuncAttributeMaxDynamicSharedMemorySize, ENC_SMEM_BYTES);
    cudaFuncSetAttribute(aggw_kernel,
        cudaFuncAttributeMaxDynamicSharedMemorySize, ENC_SMEM_BYTES);

    // 0) independent zero-inits + tail, issued first (no upstream deps)
    cudaMemsetAsync(agg2, 0, (size_t)P * HDIM * sizeof(float));
    cudaMemsetAsync(out,  0, (size_t)P * HDIM * sizeof(float));
    cudaMemsetAsync(counts, 0, (size_t)P * sizeof(int));
    int tail = out_size - P * HDIM;
    if (tail > 0) {
        int elems = (tail == 2 * PNUM) ? PNUM : tail;
        tail_kernel<<<(elems + 255) / 256, 256>>>(out, tail);
    }

    // 1) id normalization + CSR build (sorted order)
    detect_ids_kernel<<<1, 1>>>(ids);
    prep_kernel<<<(N + 255) / 256, 256>>>(ids, N);
    scan_kernel<<<1, 1024>>>();
    scatter_kernel<<<(N + 255) / 256, 256>>>(N);

    // 2) enc0 -> h0 (sorted space)
    enc0_kernel<<<(N + 7) / 8, 256>>>(x, W0, b0, g0, be0, h0, N);

    // 3) layer 1: seg_max(h0) -> agg; aggW; enc1 -> h1 + fused seg_max -> agg2
    segmax_kernel<<<(P + 7) / 8, 256>>>(h0, agg, P);
    aggw_kernel<<<(P + 127) / 128, 256, ENC_SMEM_BYTES>>>(
        agg, W1 + (size_t)HDIM * HDIM, b1, aggw, P);
    enc_kernel<<<(N + 127) / 128, 256, ENC_SMEM_BYTES>>>(
        h0, aggw, W1, g1, be1, h1, agg2, N);

    // 4) layer 2: aggW(agg2); enc2 (no h store) + fused seg_max -> out
    aggw_kernel<<<(P + 127) / 128, 256, ENC_SMEM_BYTES>>>(
        agg2, W2 + (size_t)HDIM * HDIM, b2, aggw, P);
    enc_kernel<<<(N + 127) / 128, 256, ENC_SMEM_BYTES>>>(
        h1, aggw, W2, g2, be2, nullptr, out, N);
}

// round 9
// speedup vs baseline: 1.2690x; 1.1254x over previous
#include <cuda_runtime.h>
#include <cstdint>

#define HDIM 128
#define NMAX 500000
#define PNUM 50000
#define LN_EPS 1e-5f
#define SCAN_NB ((PNUM + 255) / 256)   // 196

// ---------------- scratch (static __device__; no allocation) ----------------
__device__ float g_h0[(size_t)NMAX * HDIM];
__device__ float g_h1[(size_t)NMAX * HDIM];
__device__ float g_agg[(size_t)PNUM * HDIM];
__device__ float g_agg2[(size_t)PNUM * HDIM];
__device__ float g_aggw[(size_t)PNUM * HDIM];
__device__ int   g_counts[PNUM];
__device__ int   g_scantmp[PNUM];
__device__ int   g_blocksums[SCAN_NB];
__device__ int   g_offsets[PNUM + 1];
__device__ int   g_cursor[PNUM];
__device__ int   g_order[NMAX];   // sorted position -> original row
__device__ int   g_ids[NMAX];     // original row -> id
__device__ int   g_sid[NMAX];     // sorted position -> id (non-decreasing)
__device__ int   g_ids64;

// ---------------- id dtype detection ----------------
__global__ void detect_ids_kernel(const void* idsraw) {
    const long long* a = (const long long*)idsraw;
    int ok = 1;
    for (int i = 0; i < 16; i++) {
        long long v = a[i];
        if (v < 0 || v >= PNUM) ok = 0;
    }
    g_ids64 = ok;
}

__global__ void prep_kernel(const void* idsraw, int N) {
    int i = blockIdx.x * blockDim.x + threadIdx.x;
    if (i >= N) return;
    int v = g_ids64 ? (int)((const long long*)idsraw)[i]
                    : ((const int*)idsraw)[i];
    g_ids[i] = v;
    atomicAdd(&g_counts[v], 1);
}

// ---------------- three-phase scan over g_counts ----------------
__device__ __forceinline__ int block_inclusive_scan_256(int v, int* wsum) {
    int lane = threadIdx.x & 31, w = threadIdx.x >> 5;
    int x = v;
#pragma unroll
    for (int o = 1; o < 32; o <<= 1) {
        int t = __shfl_up_sync(0xffffffffu, x, o);
        if (lane >= o) x += t;
    }
    if (lane == 31) wsum[w] = x;
    __syncthreads();
    if (w == 0) {
        int y = (lane < 8) ? wsum[lane] : 0;
#pragma unroll
        for (int o = 1; o < 8; o <<= 1) {
            int t = __shfl_up_sync(0xffffffffu, y, o);
            if (lane >= o) y += t;
        }
        if (lane < 8) wsum[lane] = y;
    }
    __syncthreads();
    return x + (w > 0 ? wsum[w - 1] : 0);
}

__global__ void scan1_kernel() {                 // grid=SCAN_NB, block=256
    __shared__ int wsum[8];
    int i = blockIdx.x * 256 + threadIdx.x;
    int v = (i < PNUM) ? g_counts[i] : 0;
    int incl = block_inclusive_scan_256(v, wsum);
    if (i < PNUM) g_scantmp[i] = incl;
    if (threadIdx.x == 255) g_blocksums[blockIdx.x] = incl;
}

__global__ void scan2_kernel() {                 // 1 block of 256
    __shared__ int wsum[8];
    int t = threadIdx.x;
    int v = (t < SCAN_NB) ? g_blocksums[t] : 0;
    int incl = block_inclusive_scan_256(v, wsum);
    if (t < SCAN_NB) g_blocksums[t] = incl;
}

__global__ void scan3_kernel() {                 // grid=SCAN_NB, block=256
    int i = blockIdx.x * 256 + threadIdx.x;
    if (i >= PNUM) return;
    int off = (blockIdx.x > 0) ? g_blocksums[blockIdx.x - 1] : 0;
    int incl = off + g_scantmp[i];
    int excl = incl - g_counts[i];
    g_offsets[i] = excl;
    g_cursor[i] = excl;
    if (i == PNUM - 1) g_offsets[PNUM] = incl;
}

__global__ void scatter_kernel(int N) {
    int i = blockIdx.x * blockDim.x + threadIdx.x;
    if (i >= N) return;
    int id = g_ids[i];
    int pos = atomicAdd(&g_cursor[id], 1);
    g_order[pos] = i;
    g_sid[pos] = id;
}

// ---------------- encoder 0 (sorted output space) ----------------
__global__ __launch_bounds__(256) void enc0_kernel(
    const float* __restrict__ x, const float* __restrict__ W0,
    const float* __restrict__ b0, const float* __restrict__ g0,
    const float* __restrict__ be0, float* __restrict__ out, int N)
{
    int spos = (blockIdx.x * blockDim.x + threadIdx.x) >> 5;
    int lane = threadIdx.x & 31;
    if (spos >= N) return;
    int srow = g_order[spos];

    float xv = (lane < 9) ? x[(size_t)srow * 9 + lane] : 0.f;
    float z[4];
#pragma unroll
    for (int c = 0; c < 4; c++) z[c] = b0[lane + 32 * c];
#pragma unroll
    for (int k = 0; k < 9; k++) {
        float xk = __shfl_sync(0xffffffffu, xv, k);
#pragma unroll
        for (int c = 0; c < 4; c++)
            z[c] = fmaf(xk, W0[k * HDIM + lane + 32 * c], z[c]);
    }
    float s  = z[0] + z[1] + z[2] + z[3];
    float s2 = z[0]*z[0] + z[1]*z[1] + z[2]*z[2] + z[3]*z[3];
#pragma unroll
    for (int o = 16; o > 0; o >>= 1) {
        s  += __shfl_xor_sync(0xffffffffu, s, o);
        s2 += __shfl_xor_sync(0xffffffffu, s2, o);
    }
    float mu  = s * (1.f / HDIM);
    float var = fmaf(s2, 1.f / HDIM, -mu * mu);
    float rs  = rsqrtf(var + LN_EPS);
#pragma unroll
    for (int c = 0; c < 4; c++) {
        int j = lane + 32 * c;
        float v = fmaf((z[c] - mu) * rs, g0[j], be0[j]);
        out[(size_t)spos * HDIM + j] = fmaxf(v, 0.f);
    }
}

// ---------------- segmented max (used once, for h0) ----------------
__global__ __launch_bounds__(256) void segmax_kernel(
    const float* __restrict__ h, float* __restrict__ out, int P)
{
    int p    = (blockIdx.x * blockDim.x + threadIdx.x) >> 5;
    int lane = threadIdx.x & 31;
    if (p >= P) return;
    int beg = g_offsets[p], end = g_offsets[p + 1];
    float4 m1 = make_float4(0.f, 0.f, 0.f, 0.f);
    float4 m2 = make_float4(0.f, 0.f, 0.f, 0.f);
    int i = beg;
    for (; i + 1 < end; i += 2) {
        float4 v1 = *(const float4*)(h + (size_t)i * HDIM + lane * 4);
        float4 v2 = *(const float4*)(h + (size_t)(i + 1) * HDIM + lane * 4);
        m1.x = fmaxf(m1.x, v1.x); m1.y = fmaxf(m1.y, v1.y);
        m1.z = fmaxf(m1.z, v1.z); m1.w = fmaxf(m1.w, v1.w);
        m2.x = fmaxf(m2.x, v2.x); m2.y = fmaxf(m2.y, v2.y);
        m2.z = fmaxf(m2.z, v2.z); m2.w = fmaxf(m2.w, v2.w);
    }
    if (i < end) {
        float4 v = *(const float4*)(h + (size_t)i * HDIM + lane * 4);
        m1.x = fmaxf(m1.x, v.x); m1.y = fmaxf(m1.y, v.y);
        m1.z = fmaxf(m1.z, v.z); m1.w = fmaxf(m1.w, v.w);
    }
    m1.x = fmaxf(m1.x, m2.x); m1.y = fmaxf(m1.y, m2.y);
    m1.z = fmaxf(m1.z, m2.z); m1.w = fmaxf(m1.w, m2.w);
    *(float4*)(out + (size_t)p * HDIM + lane * 4) = m1;
}

// ---------------- tf32 mma.sync helpers ----------------
__device__ __forceinline__ void cp_async16(float* s, const float* g) {
    unsigned sa = (unsigned)__cvta_generic_to_shared(s);
    asm volatile("cp.async.cg.shared.global [%0], [%1], 16;\n" :: "r"(sa), "l"(g));
}
__device__ __forceinline__ void cp_commit() {
    asm volatile("cp.async.commit_group;\n" ::: "memory");
}
template<int n> __device__ __forceinline__ void cp_wait() {
    asm volatile("cp.async.wait_group %0;\n" :: "n"(n) : "memory");
}
__device__ __forceinline__ void mma_tf32(float acc[4], const unsigned a[4], const unsigned b[2]) {
    asm volatile(
        "mma.sync.aligned.m16n8k8.row.col.f32.tf32.tf32.f32 "
        "{%0,%1,%2,%3},{%4,%5,%6,%7},{%8,%9},{%0,%1,%2,%3};\n"
        : "+f"(acc[0]), "+f"(acc[1]), "+f"(acc[2]), "+f"(acc[3])
        : "r"(a[0]), "r"(a[1]), "r"(a[2]), "r"(a[3]), "r"(b[0]), "r"(b[1]));
}

#define AS_STRIDE 36
#define WS_STRIDE 136
#define AS_BUF (128 * AS_STRIDE)
#define WS_BUF (32 * WS_STRIDE)
#define STAGE_STRIDE 132
#define ENC_SMEM_FLOATS (2*AS_BUF + 2*WS_BUF + 512 + 128)
#define ENC_SMEM_BYTES (ENC_SMEM_FLOATS * 4)

// ---------------- aggw kernel: aggW = bias + agg @ W_bot  (P x 128, K=128) ---
__global__ __launch_bounds__(256, 2) void aggw_kernel(
    const float* __restrict__ agg, const float* __restrict__ Wb,
    const float* __restrict__ b, float* __restrict__ aggw, int P)
{
    extern __shared__ float sm[];
    float* As  = sm;
    float* Wsm = sm + 2 * AS_BUF;

    const int tid = threadIdx.x;
    const int lane = tid & 31;
    const int quad_r = lane >> 2, quad_c = lane & 3;
    const int warp = tid >> 5;
    const int warp_m = warp >> 1, warp_n = warp & 1;
    const int row0 = blockIdx.x * 128;

    float acc[2][8][4];
#pragma unroll
    for (int nt = 0; nt < 8; nt++) {
        float2 bv = *(const float2*)&b[warp_n * 64 + nt * 8 + quad_c * 2];
#pragma unroll
        for (int mf = 0; mf < 2; mf++) {
            acc[mf][nt][0] = bv.x; acc[mf][nt][1] = bv.y;
            acc[mf][nt][2] = bv.x; acc[mf][nt][3] = bv.y;
        }
    }

    auto issue_chunk = [&](int kc, int buf) {
        float* Ab = As + buf * AS_BUF;
        float* Wc = Wsm + buf * WS_BUF;
#pragma unroll
        for (int i = 0; i < 4; i++) {
            int idx = tid + i * 256;
            int r = idx >> 3, f = idx & 7;
            int gr = row0 + r; if (gr >= P) gr = P - 1;
            cp_async16(Ab + r * AS_STRIDE + f * 4,
                       agg + (size_t)gr * HDIM + kc * 32 + f * 4);
        }
#pragma unroll
        for (int i = 0; i < 4; i++) {
            int idx = tid + i * 256;
            int k = idx >> 5, f = idx & 31;
            cp_async16(Wc + k * WS_STRIDE + f * 4,
                       Wb + (size_t)(kc * 32 + k) * HDIM + f * 4);
        }
        cp_commit();
    };

    issue_chunk(0, 0);

#pragma unroll 1
    for (int kc = 0; kc < 4; kc++) {
        if (kc < 3) { issue_chunk(kc + 1, (kc + 1) & 1); cp_wait<1>(); }
        else        { cp_wait<0>(); }
        __syncthreads();
        const float* Ab = As + (kc & 1) * AS_BUF;
        const float* Wc = Wsm + (kc & 1) * WS_BUF;
#pragma unroll
        for (int ks = 0; ks < 4; ks++) {
            const int kk = ks * 8;
            unsigned afr[2][4];
#pragma unroll
            for (int mf = 0; mf < 2; mf++) {
                const float* p = Ab + (warp_m * 32 + mf * 16 + quad_r) * AS_STRIDE
                                    + kk + quad_c;
                afr[mf][0] = __float_as_uint(p[0]);
                afr[mf][1] = __float_as_uint(p[8 * AS_STRIDE]);
                afr[mf][2] = __float_as_uint(p[4]);
                afr[mf][3] = __float_as_uint(p[8 * AS_STRIDE + 4]);
            }
            unsigned bfr[8][2];
#pragma unroll
            for (int nt = 0; nt < 8; nt++) {
                const float* p = Wc + (kk + quad_c) * WS_STRIDE
                                    + warp_n * 64 + nt * 8 + quad_r;
                bfr[nt][0] = __float_as_uint(p[0]);
                bfr[nt][1] = __float_as_uint(p[4 * WS_STRIDE]);
            }
#pragma unroll
            for (int mf = 0; mf < 2; mf++)
#pragma unroll
                for (int nt = 0; nt < 8; nt++)
                    mma_tf32(acc[mf][nt], afr[mf], bfr[nt]);
        }
        __syncthreads();
    }

#pragma unroll
    for (int nt = 0; nt < 8; nt++) {
        int col = warp_n * 64 + nt * 8 + quad_c * 2;
#pragma unroll
        for (int mf = 0; mf < 2; mf++)
#pragma unroll
            for (int h = 0; h < 2; h++) {
                int grow = row0 + warp_m * 32 + mf * 16 + h * 8 + quad_r;
                if (grow < P)
                    *(float2*)(aggw + (size_t)grow * HDIM + col) =
                        make_float2(acc[mf][nt][2 * h], acc[mf][nt][2 * h + 1]);
            }
    }
}

// ---------------- encoder 1/2 with fused segmented max -----------------------
__global__ __launch_bounds__(256, 2) void enc_kernel(
    const float* __restrict__ hprev, const float* __restrict__ aggw,
    const float* __restrict__ Wt, const float* __restrict__ gw,
    const float* __restrict__ be, float* __restrict__ hout,
    float* __restrict__ maxout, int N)
{
    extern __shared__ float sm[];
    float* As   = sm;
    float* Wsm  = sm + 2 * AS_BUF;
    float* stage = sm;                                   // reused post-mainloop
    float2* red2 = (float2*)(sm + 2*AS_BUF + 2*WS_BUF);  // 512 floats
    int*   sidp = (int*)(sm + 2*AS_BUF + 2*WS_BUF + 512); // 128 ints

    const int tid = threadIdx.x;
    const int lane = tid & 31;
    const int quad_r = lane >> 2, quad_c = lane & 3;
    const int warp = tid >> 5;
    const int warp_m = warp >> 1, warp_n = warp & 1;
    const int row0 = blockIdx.x * 128;

    if (tid < 128) {
        int r = row0 + tid;
        sidp[tid] = g_sid[(r < N) ? r : (N - 1)];
    }
    __syncthreads();

    auto issue_chunk = [&](int kc, int buf) {
        float* Ab = As + buf * AS_BUF;
        float* Wc = Wsm + buf * WS_BUF;
#pragma unroll
        for (int i = 0; i < 4; i++) {
            int idx = tid + i * 256;
            int r = idx >> 3, f = idx & 7;
            int gr = row0 + r; if (gr >= N) gr = N - 1;
            cp_async16(Ab + r * AS_STRIDE + f * 4,
                       hprev + (size_t)gr * HDIM + kc * 32 + f * 4);
        }
#pragma unroll
        for (int i = 0; i < 4; i++) {
            int idx = tid + i * 256;
            int k = idx >> 5, f = idx & 31;
            cp_async16(Wc + k * WS_STRIDE + f * 4,
                       Wt + (size_t)(kc * 32 + k) * HDIM + f * 4);
        }
        cp_commit();
    };

    issue_chunk(0, 0);

    // accumulator init = aggW[sid] gather (L2-resident table)
    float acc[2][8][4];
#pragma unroll
    for (int mf = 0; mf < 2; mf++)
#pragma unroll
        for (int h = 0; h < 2; h++) {
            int rl = warp_m * 32 + mf * 16 + h * 8 + quad_r;
            const float* base = aggw + (size_t)sidp[rl] * HDIM;
#pragma unroll
            for (int nt = 0; nt < 8; nt++) {
                float2 v = *(const float2*)(base + warp_n * 64 + nt * 8 + quad_c * 2);
                acc[mf][nt][2 * h]     = v.x;
                acc[mf][nt][2 * h + 1] = v.y;
            }
        }

#pragma unroll 1
    for (int kc = 0; kc < 4; kc++) {
        if (kc < 3) { issue_chunk(kc + 1, (kc + 1) & 1); cp_wait<1>(); }
        else        { cp_wait<0>(); }
        __syncthreads();

        const float* Ab = As + (kc & 1) * AS_BUF;
        const float* Wc = Wsm + (kc & 1) * WS_BUF;
#pragma unroll
        for (int ks = 0; ks < 4; ks++) {
            const int kk = ks * 8;
            unsigned afr[2][4];
#pragma unroll
            for (int mf = 0; mf < 2; mf++) {
                const float* p = Ab + (warp_m * 32 + mf * 16 + quad_r) * AS_STRIDE
                                    + kk + quad_c;
                afr[mf][0] = __float_as_uint(p[0]);
                afr[mf][1] = __float_as_uint(p[8 * AS_STRIDE]);
                afr[mf][2] = __float_as_uint(p[4]);
                afr[mf][3] = __float_as_uint(p[8 * AS_STRIDE + 4]);
            }
            unsigned bfr[8][2];
#pragma unroll
            for (int nt = 0; nt < 8; nt++) {
                const float* p = Wc + (kk + quad_c) * WS_STRIDE
                                    + warp_n * 64 + nt * 8 + quad_r;
                bfr[nt][0] = __float_as_uint(p[0]);
                bfr[nt][1] = __float_as_uint(p[4 * WS_STRIDE]);
            }
#pragma unroll
            for (int mf = 0; mf < 2; mf++)
#pragma unroll
                for (int nt = 0; nt < 8; nt++)
                    mma_tf32(acc[mf][nt], afr[mf], bfr[nt]);
        }
        __syncthreads();
    }

    // ---- LayerNorm statistics ----
    float s[2][2], q[2][2];
#pragma unroll
    for (int mf = 0; mf < 2; mf++)
#pragma unroll
        for (int h = 0; h < 2; h++) {
            float ss = 0.f, qq = 0.f;
#pragma unroll
            for (int nt = 0; nt < 8; nt++) {
                float z0 = acc[mf][nt][2 * h], z1 = acc[mf][nt][2 * h + 1];
                ss += z0 + z1;
                qq += z0 * z0 + z1 * z1;
            }
            s[mf][h] = ss; q[mf][h] = qq;
        }
#pragma unroll
    for (int mk = 1; mk <= 2; mk <<= 1)
#pragma unroll
        for (int mf = 0; mf < 2; mf++)
#pragma unroll
            for (int h = 0; h < 2; h++) {
                s[mf][h] += __shfl_xor_sync(0xffffffffu, s[mf][h], mk);
                q[mf][h] += __shfl_xor_sync(0xffffffffu, q[mf][h], mk);
            }
    if (quad_c == 0) {
#pragma unroll
        for (int mf = 0; mf < 2; mf++)
#pragma unroll
            for (int h = 0; h < 2; h++) {
                int rl = warp_m * 32 + mf * 16 + h * 8 + quad_r;
                red2[rl * 2 + warp_n] = make_float2(s[mf][h], q[mf][h]);
            }
    }
    __syncthreads();
    float mu[2][2], rs[2][2];
#pragma unroll
    for (int mf = 0; mf < 2; mf++)
#pragma unroll
        for (int h = 0; h < 2; h++) {
            int rl = warp_m * 32 + mf * 16 + h * 8 + quad_r;
            float2 r0 = red2[rl * 2 + 0], r1 = red2[rl * 2 + 1];
            float ss = r0.x + r1.x, qq = r0.y + r1.y;
            float m = ss * (1.f / HDIM);
            float var = fmaf(qq, 1.f / HDIM, -m * m);
            mu[mf][h] = m;
            rs[mf][h] = rsqrtf(var + LN_EPS);
        }
    __syncthreads();   // all warps done with As/Wsm/red2 before staging

    // ---- normalize + ReLU: store to hout (optional) and stage for segmax ----
#pragma unroll
    for (int nt = 0; nt < 8; nt++) {
        int col = warp_n * 64 + nt * 8 + quad_c * 2;
        float2 gv = *(const float2*)&gw[col];
        float2 ev = *(const float2*)&be[col];
#pragma unroll
        for (int mf = 0; mf < 2; mf++)
#pragma unroll
            for (int h = 0; h < 2; h++) {
                int rl = warp_m * 32 + mf * 16 + h * 8 + quad_r;
                float z0 = acc[mf][nt][2 * h], z1 = acc[mf][nt][2 * h + 1];
                float2 o;
                o.x = fmaxf(fmaf((z0 - mu[mf][h]) * rs[mf][h], gv.x, ev.x), 0.f);
                o.y = fmaxf(fmaf((z1 - mu[mf][h]) * rs[mf][h], gv.y, ev.y), 0.f);
                *(float2*)&stage[rl * STAGE_STRIDE + col] = o;
                int grow = row0 + rl;
                if (hout && grow < N)
                    *(float2*)(hout + (size_t)grow * HDIM + col) = o;
            }
    }
    __syncthreads();

    // ---- fused segmented max: warp-per-segment over the staged tile ----
    {
        const int p_first = sidp[0];
        const int p_last  = sidp[127];
        for (int seg = p_first + warp; seg <= p_last; seg += 8) {
            int b = g_offsets[seg], e = g_offsets[seg + 1];
            int r0 = b - row0; if (r0 < 0) r0 = 0;
            int r1 = e - row0; if (r1 > 128) r1 = 128;
            if (r1 <= r0) continue;                     // empty segment
            float4 m = make_float4(0.f, 0.f, 0.f, 0.f);
            for (int r = r0; r < r1; r++) {
                float4 v = *(const float4*)&stage[r * STAGE_STRIDE + lane * 4];
                m.x = fmaxf(m.x, v.x); m.y = fmaxf(m.y, v.y);
                m.z = fmaxf(m.z, v.z); m.w = fmaxf(m.w, v.w);
            }
            float* dst = maxout + (size_t)seg * HDIM + lane * 4;
            bool bnd = (b < row0) || (e > row0 + 128);
            if (bnd) {
                atomicMax((int*)dst + 0, __float_as_int(m.x));
                atomicMax((int*)dst + 1, __float_as_int(m.y));
                atomicMax((int*)dst + 2, __float_as_int(m.z));
                atomicMax((int*)dst + 3, __float_as_int(m.w));
            } else {
                *(float4*)dst = m;
            }
        }
    }
}

// ---------------- output tail ----------------
__global__ void tail_kernel(float* out, int tail) {
    int i = blockIdx.x * blockDim.x + threadIdx.x;
    float* base = out + (size_t)PNUM * HDIM;
    if (tail == PNUM) {
        if (i < PNUM) base[i] = (float)i;
    } else if (tail == 2 * PNUM) {
        if (i < PNUM) ((long long*)base)[i] = (long long)i;
    } else {
        if (i < tail) base[i] = (float)i;
    }
}

// ---------------- launch ----------------
extern "C" void kernel_launch(void* const* d_in, const int* in_sizes, int n_in,
                              void* d_out, int out_size) {
    const float* x   = (const float*)d_in[0];
    const void*  ids = d_in[1];
    const float* W0  = (const float*)d_in[2];
    const float* b0  = (const float*)d_in[3];
    const float* g0  = (const float*)d_in[4];
    const float* be0 = (const float*)d_in[5];
    const float* W1  = (const float*)d_in[6];
    const float* b1  = (const float*)d_in[7];
    const float* g1  = (const float*)d_in[8];
    const float* be1 = (const float*)d_in[9];
    const float* W2  = (const float*)d_in[10];
    const float* b2  = (const float*)d_in[11];
    const float* g2  = (const float*)d_in[12];
    const float* be2 = (const float*)d_in[13];

    const int N = in_sizes[0] / 9;
    const int P = PNUM;
    float* out = (float*)d_out;

    float *h0, *h1, *agg, *agg2, *aggw;
    int* counts;
    cudaGetSymbolAddress((void**)&h0,   g_h0);
    cudaGetSymbolAddress((void**)&h1,   g_h1);
    cudaGetSymbolAddress((void**)&agg,  g_agg);
    cudaGetSymbolAddress((void**)&agg2, g_agg2);
    cudaGetSymbolAddress((void**)&aggw, g_aggw);
    cudaGetSymbolAddress((void**)&counts, g_counts);

    cudaFuncSetAttribute(enc_kernel,
        cudaFuncAttributeMaxDynamicSharedMemorySize, ENC_SMEM_BYTES);
    cudaFuncSetAttribute(aggw_kernel,
        cudaFuncAttributeMaxDynamicSharedMemorySize, ENC_SMEM_BYTES);

    // 0) independent zero-inits + tail, issued first (no upstream deps)
    cudaMemsetAsync(agg2, 0, (size_t)P * HDIM * sizeof(float));
    cudaMemsetAsync(out,  0, (size_t)P * HDIM * sizeof(float));
    cudaMemsetAsync(counts, 0, (size_t)P * sizeof(int));
    int tail = out_size - P * HDIM;
    if (tail > 0) {
        int elems = (tail == 2 * PNUM) ? PNUM : tail;
        tail_kernel<<<(elems + 255) / 256, 256>>>(out, tail);
    }

    // 1) id normalization + CSR build (three-phase parallel scan)
    detect_ids_kernel<<<1, 1>>>(ids);
    prep_kernel<<<(N + 255) / 256, 256>>>(ids, N);
    scan1_kernel<<<SCAN_NB, 256>>>();
    scan2_kernel<<<1, 256>>>();
    scan3_kernel<<<SCAN_NB, 256>>>();
    scatter_kernel<<<(N + 255) / 256, 256>>>(N);

    // 2) enc0 -> h0 (sorted space)
    enc0_kernel<<<(N + 7) / 8, 256>>>(x, W0, b0, g0, be0, h0, N);

    // 3) layer 1: seg_max(h0) -> agg; aggW; enc1 -> h1 + fused seg_max -> agg2
    segmax_kernel<<<(P + 7) / 8, 256>>>(h0, agg, P);
    aggw_kernel<<<(P + 127) / 128, 256, ENC_SMEM_BYTES>>>(
        agg, W1 + (size_t)HDIM * HDIM, b1, aggw, P);
    enc_kernel<<<(N + 127) / 128, 256, ENC_SMEM_BYTES>>>(
        h0, aggw, W1, g1, be1, h1, agg2, N);

    // 4) layer 2: aggW(agg2); enc2 (no h store) + fused seg_max -> out
    aggw_kernel<<<(P + 127) / 128, 256, ENC_SMEM_BYTES>>>(
        agg2, W2 + (size_t)HDIM * HDIM, b2, aggw, P);
    enc_kernel<<<(N + 127) / 128, 256, ENC_SMEM_BYTES>>>(
        h1, aggw, W2, g2, be2, nullptr, out, N);
}

// round 10
// speedup vs baseline: 1.3780x; 1.0859x over previous
#include <cuda_runtime.h>
#include <cstdint>

#define HDIM 128
#define NMAX 500000
#define PNUM 50000
#define LN_EPS 1e-5f
#define SCAN_NB ((PNUM + 255) / 256)   // 196

// ---------------- scratch (static __device__; no allocation) ----------------
__device__ float g_h0[(size_t)NMAX * HDIM];
__device__ float g_h1[(size_t)NMAX * HDIM];
__device__ float g_agg[(size_t)PNUM * HDIM];
__device__ float g_agg2[(size_t)PNUM * HDIM];
__device__ float g_aggw[(size_t)PNUM * HDIM];
__device__ int   g_counts[PNUM];
__device__ int   g_scantmp[PNUM];
__device__ int   g_blocksums[SCAN_NB];
__device__ int   g_offsets[PNUM + 1];
__device__ int   g_cursor[PNUM];
__device__ int   g_order[NMAX];   // sorted position -> original row
__device__ int   g_ids[NMAX];     // original row -> id
__device__ int   g_sid[NMAX];     // sorted position -> id (non-decreasing)
__device__ int   g_ids64;

// ---------------- id dtype detection ----------------
__global__ void detect_ids_kernel(const void* idsraw) {
    const long long* a = (const long long*)idsraw;
    int ok = 1;
    for (int i = 0; i < 16; i++) {
        long long v = a[i];
        if (v < 0 || v >= PNUM) ok = 0;
    }
    g_ids64 = ok;
}

__global__ void prep_kernel(const void* idsraw, int N) {
    int i = blockIdx.x * blockDim.x + threadIdx.x;
    if (i >= N) return;
    int v = g_ids64 ? (int)((const long long*)idsraw)[i]
                    : ((const int*)idsraw)[i];
    g_ids[i] = v;
    atomicAdd(&g_counts[v], 1);
}

// ---------------- three-phase scan over g_counts ----------------
__device__ __forceinline__ int block_inclusive_scan_256(int v, int* wsum) {
    int lane = threadIdx.x & 31, w = threadIdx.x >> 5;
    int x = v;
#pragma unroll
    for (int o = 1; o < 32; o <<= 1) {
        int t = __shfl_up_sync(0xffffffffu, x, o);
        if (lane >= o) x += t;
    }
    if (lane == 31) wsum[w] = x;
    __syncthreads();
    if (w == 0) {
        int y = (lane < 8) ? wsum[lane] : 0;
#pragma unroll
        for (int o = 1; o < 8; o <<= 1) {
            int t = __shfl_up_sync(0xffffffffu, y, o);
            if (lane >= o) y += t;
        }
        if (lane < 8) wsum[lane] = y;
    }
    __syncthreads();
    return x + (w > 0 ? wsum[w - 1] : 0);
}

__global__ void scan1_kernel() {
    __shared__ int wsum[8];
    int i = blockIdx.x * 256 + threadIdx.x;
    int v = (i < PNUM) ? g_counts[i] : 0;
    int incl = block_inclusive_scan_256(v, wsum);
    if (i < PNUM) g_scantmp[i] = incl;
    if (threadIdx.x == 255) g_blocksums[blockIdx.x] = incl;
}

__global__ void scan2_kernel() {
    __shared__ int wsum[8];
    int t = threadIdx.x;
    int v = (t < SCAN_NB) ? g_blocksums[t] : 0;
    int incl = block_inclusive_scan_256(v, wsum);
    if (t < SCAN_NB) g_blocksums[t] = incl;
}

__global__ void scan3_kernel() {
    int i = blockIdx.x * 256 + threadIdx.x;
    if (i >= PNUM) return;
    int off = (blockIdx.x > 0) ? g_blocksums[blockIdx.x - 1] : 0;
    int incl = off + g_scantmp[i];
    int excl = incl - g_counts[i];
    g_offsets[i] = excl;
    g_cursor[i] = excl;
    if (i == PNUM - 1) g_offsets[PNUM] = incl;
}

__global__ void scatter_kernel(int N) {
    int i = blockIdx.x * blockDim.x + threadIdx.x;
    if (i >= N) return;
    int id = g_ids[i];
    int pos = atomicAdd(&g_cursor[id], 1);
    g_order[pos] = i;
    g_sid[pos] = id;
}

#define STAGE_STRIDE 132
#define ENC0_SMEM_FLOATS (128 * STAGE_STRIDE + 128)
#define ENC0_SMEM_BYTES (ENC0_SMEM_FLOATS * 4)

// ---------------- encoder 0 with fused segmented max -------------------------
// 128 rows/CTA; each warp computes 16 rows (warp-per-row math), stages the
// normalized tile in smem, writes h0, then warp-per-segment max -> agg.
__global__ __launch_bounds__(256, 2) void enc0_kernel(
    const float* __restrict__ x, const float* __restrict__ W0,
    const float* __restrict__ b0, const float* __restrict__ g0,
    const float* __restrict__ be0, float* __restrict__ out,
    float* __restrict__ maxout, int N)
{
    extern __shared__ float sm[];
    float* stage = sm;
    int* sidp = (int*)(sm + 128 * STAGE_STRIDE);

    const int tid = threadIdx.x;
    const int lane = tid & 31;
    const int warp = tid >> 5;
    const int row0 = blockIdx.x * 128;

    if (tid < 128) {
        int r = row0 + tid;
        sidp[tid] = g_sid[(r < N) ? r : (N - 1)];
    }

    // hoist weights: W0 [9][4] per lane, plus b0/g0/be0 [4]
    float w[9][4], bb[4], gg[4], ee[4];
#pragma unroll
    for (int k = 0; k < 9; k++)
#pragma unroll
        for (int c = 0; c < 4; c++)
            w[k][c] = W0[k * HDIM + lane + 32 * c];
#pragma unroll
    for (int c = 0; c < 4; c++) {
        bb[c] = b0[lane + 32 * c];
        gg[c] = g0[lane + 32 * c];
        ee[c] = be0[lane + 32 * c];
    }

#pragma unroll 1
    for (int rr = 0; rr < 16; rr++) {
        int rl = warp * 16 + rr;
        int spos = row0 + rl;
        int sp = (spos < N) ? spos : (N - 1);
        int srow = g_order[sp];

        float xv = (lane < 9) ? x[(size_t)srow * 9 + lane] : 0.f;
        float z[4] = {bb[0], bb[1], bb[2], bb[3]};
#pragma unroll
        for (int k = 0; k < 9; k++) {
            float xk = __shfl_sync(0xffffffffu, xv, k);
#pragma unroll
            for (int c = 0; c < 4; c++)
                z[c] = fmaf(xk, w[k][c], z[c]);
        }
        float s  = z[0] + z[1] + z[2] + z[3];
        float s2 = z[0]*z[0] + z[1]*z[1] + z[2]*z[2] + z[3]*z[3];
#pragma unroll
        for (int o = 16; o > 0; o >>= 1) {
            s  += __shfl_xor_sync(0xffffffffu, s, o);
            s2 += __shfl_xor_sync(0xffffffffu, s2, o);
        }
        float mu  = s * (1.f / HDIM);
        float var = fmaf(s2, 1.f / HDIM, -mu * mu);
        float rs  = rsqrtf(var + LN_EPS);
        float v[4];
#pragma unroll
        for (int c = 0; c < 4; c++)
            v[c] = fmaxf(fmaf((z[c] - mu) * rs, gg[c], ee[c]), 0.f);
#pragma unroll
        for (int c = 0; c < 4; c++)
            stage[rl * STAGE_STRIDE + lane + 32 * c] = v[c];
        if (spos < N) {
#pragma unroll
            for (int c = 0; c < 4; c++)
                out[(size_t)spos * HDIM + lane + 32 * c] = v[c];
        }
    }
    __syncthreads();

    // ---- fused segmented max: warp-per-segment over the staged tile ----
    {
        const int p_first = sidp[0];
        const int p_last  = sidp[127];
        for (int seg = p_first + warp; seg <= p_last; seg += 8) {
            int b = g_offsets[seg], e = g_offsets[seg + 1];
            int r0 = b - row0; if (r0 < 0) r0 = 0;
            int r1 = e - row0; if (r1 > 128) r1 = 128;
            if (r1 <= r0) continue;
            float4 m = make_float4(0.f, 0.f, 0.f, 0.f);
            for (int r = r0; r < r1; r++) {
                float4 vv = *(const float4*)&stage[r * STAGE_STRIDE + lane * 4];
                m.x = fmaxf(m.x, vv.x); m.y = fmaxf(m.y, vv.y);
                m.z = fmaxf(m.z, vv.z); m.w = fmaxf(m.w, vv.w);
            }
            float* dst = maxout + (size_t)seg * HDIM + lane * 4;
            bool bnd = (b < row0) || (e > row0 + 128);
            if (bnd) {
                atomicMax((int*)dst + 0, __float_as_int(m.x));
                atomicMax((int*)dst + 1, __float_as_int(m.y));
                atomicMax((int*)dst + 2, __float_as_int(m.z));
                atomicMax((int*)dst + 3, __float_as_int(m.w));
            } else {
                *(float4*)dst = m;
            }
        }
    }
}

// ---------------- tf32 mma.sync helpers ----------------
__device__ __forceinline__ void cp_async16(float* s, const float* g) {
    unsigned sa = (unsigned)__cvta_generic_to_shared(s);
    asm volatile("cp.async.cg.shared.global [%0], [%1], 16;\n" :: "r"(sa), "l"(g));
}
__device__ __forceinline__ void cp_commit() {
    asm volatile("cp.async.commit_group;\n" ::: "memory");
}
template<int n> __device__ __forceinline__ void cp_wait() {
    asm volatile("cp.async.wait_group %0;\n" :: "n"(n) : "memory");
}
__device__ __forceinline__ void mma_tf32(float acc[4], const unsigned a[4], const unsigned b[2]) {
    asm volatile(
        "mma.sync.aligned.m16n8k8.row.col.f32.tf32.tf32.f32 "
        "{%0,%1,%2,%3},{%4,%5,%6,%7},{%8,%9},{%0,%1,%2,%3};\n"
        : "+f"(acc[0]), "+f"(acc[1]), "+f"(acc[2]), "+f"(acc[3])
        : "r"(a[0]), "r"(a[1]), "r"(a[2]), "r"(a[3]), "r"(b[0]), "r"(b[1]));
}

#define AS_STRIDE 36
#define WS_STRIDE 136
#define AS_BUF (128 * AS_STRIDE)
#define WS_BUF (32 * WS_STRIDE)
#define ENC_SMEM_FLOATS (2*AS_BUF + 2*WS_BUF + 512 + 128)
#define ENC_SMEM_BYTES (ENC_SMEM_FLOATS * 4)

// ---------------- aggw kernel: aggW = bias + agg @ W_bot  (P x 128, K=128) ---
__global__ __launch_bounds__(256, 2) void aggw_kernel(
    const float* __restrict__ agg, const float* __restrict__ Wb,
    const float* __restrict__ b, float* __restrict__ aggw, int P)
{
    extern __shared__ float sm[];
    float* As  = sm;
    float* Wsm = sm + 2 * AS_BUF;

    const int tid = threadIdx.x;
    const int lane = tid & 31;
    const int quad_r = lane >> 2, quad_c = lane & 3;
    const int warp = tid >> 5;
    const int warp_m = warp >> 1, warp_n = warp & 1;
    const int row0 = blockIdx.x * 128;

    float acc[2][8][4];
#pragma unroll
    for (int nt = 0; nt < 8; nt++) {
        float2 bv = *(const float2*)&b[warp_n * 64 + nt * 8 + quad_c * 2];
#pragma unroll
        for (int mf = 0; mf < 2; mf++) {
            acc[mf][nt][0] = bv.x; acc[mf][nt][1] = bv.y;
            acc[mf][nt][2] = bv.x; acc[mf][nt][3] = bv.y;
        }
    }

    auto issue_chunk = [&](int kc, int buf) {
        float* Ab = As + buf * AS_BUF;
        float* Wc = Wsm + buf * WS_BUF;
#pragma unroll
        for (int i = 0; i < 4; i++) {
            int idx = tid + i * 256;
            int r = idx >> 3, f = idx & 7;
            int gr = row0 + r; if (gr >= P) gr = P - 1;
            cp_async16(Ab + r * AS_STRIDE + f * 4,
                       agg + (size_t)gr * HDIM + kc * 32 + f * 4);
        }
#pragma unroll
        for (int i = 0; i < 4; i++) {
            int idx = tid + i * 256;
            int k = idx >> 5, f = idx & 31;
            cp_async16(Wc + k * WS_STRIDE + f * 4,
                       Wb + (size_t)(kc * 32 + k) * HDIM + f * 4);
        }
        cp_commit();
    };

    issue_chunk(0, 0);

#pragma unroll 1
    for (int kc = 0; kc < 4; kc++) {
        if (kc < 3) { issue_chunk(kc + 1, (kc + 1) & 1); cp_wait<1>(); }
        else        { cp_wait<0>(); }
        __syncthreads();
        const float* Ab = As + (kc & 1) * AS_BUF;
        const float* Wc = Wsm + (kc & 1) * WS_BUF;
#pragma unroll
        for (int ks = 0; ks < 4; ks++) {
            const int kk = ks * 8;
            unsigned afr[2][4];
#pragma unroll
            for (int mf = 0; mf < 2; mf++) {
                const float* p = Ab + (warp_m * 32 + mf * 16 + quad_r) * AS_STRIDE
                                    + kk + quad_c;
                afr[mf][0] = __float_as_uint(p[0]);
                afr[mf][1] = __float_as_uint(p[8 * AS_STRIDE]);
                afr[mf][2] = __float_as_uint(p[4]);
                afr[mf][3] = __float_as_uint(p[8 * AS_STRIDE + 4]);
            }
            unsigned bfr[8][2];
#pragma unroll
            for (int nt = 0; nt < 8; nt++) {
                const float* p = Wc + (kk + quad_c) * WS_STRIDE
                                    + warp_n * 64 + nt * 8 + quad_r;
                bfr[nt][0] = __float_as_uint(p[0]);
                bfr[nt][1] = __float_as_uint(p[4 * WS_STRIDE]);
            }
#pragma unroll
            for (int mf = 0; mf < 2; mf++)
#pragma unroll
                for (int nt = 0; nt < 8; nt++)
                    mma_tf32(acc[mf][nt], afr[mf], bfr[nt]);
        }
        __syncthreads();
    }

#pragma unroll
    for (int nt = 0; nt < 8; nt++) {
        int col = warp_n * 64 + nt * 8 + quad_c * 2;
#pragma unroll
        for (int mf = 0; mf < 2; mf++)
#pragma unroll
            for (int h = 0; h < 2; h++) {
                int grow = row0 + warp_m * 32 + mf * 16 + h * 8 + quad_r;
                if (grow < P)
                    *(float2*)(aggw + (size_t)grow * HDIM + col) =
                        make_float2(acc[mf][nt][2 * h], acc[mf][nt][2 * h + 1]);
            }
    }
}

// ---------------- encoder 1/2 with fused segmented max -----------------------
__global__ __launch_bounds__(256, 2) void enc_kernel(
    const float* __restrict__ hprev, const float* __restrict__ aggw,
    const float* __restrict__ Wt, const float* __restrict__ gw,
    const float* __restrict__ be, float* __restrict__ hout,
    float* __restrict__ maxout, int N)
{
    extern __shared__ float sm[];
    float* As   = sm;
    float* Wsm  = sm + 2 * AS_BUF;
    float* stage = sm;                                   // reused post-mainloop
    float2* red2 = (float2*)(sm + 2*AS_BUF + 2*WS_BUF);  // 512 floats
    int*   sidp = (int*)(sm + 2*AS_BUF + 2*WS_BUF + 512); // 128 ints

    const int tid = threadIdx.x;
    const int lane = tid & 31;
    const int quad_r = lane >> 2, quad_c = lane & 3;
    const int warp = tid >> 5;
    const int warp_m = warp >> 1, warp_n = warp & 1;
    const int row0 = blockIdx.x * 128;

    if (tid < 128) {
        int r = row0 + tid;
        sidp[tid] = g_sid[(r < N) ? r : (N - 1)];
    }
    __syncthreads();

    auto issue_chunk = [&](int kc, int buf) {
        float* Ab = As + buf * AS_BUF;
        float* Wc = Wsm + buf * WS_BUF;
#pragma unroll
        for (int i = 0; i < 4; i++) {
            int idx = tid + i * 256;
            int r = idx >> 3, f = idx & 7;
            int gr = row0 + r; if (gr >= N) gr = N - 1;
            cp_async16(Ab + r * AS_STRIDE + f * 4,
                       hprev + (size_t)gr * HDIM + kc * 32 + f * 4);
        }
#pragma unroll
        for (int i = 0; i < 4; i++) {
            int idx = tid + i * 256;
            int k = idx >> 5, f = idx & 31;
            cp_async16(Wc + k * WS_STRIDE + f * 4,
                       Wt + (size_t)(kc * 32 + k) * HDIM + f * 4);
        }
        cp_commit();
    };

    issue_chunk(0, 0);

    // accumulator init = aggW[sid] gather (L2-resident table)
    float acc[2][8][4];
#pragma unroll
    for (int mf = 0; mf < 2; mf++)
#pragma unroll
        for (int h = 0; h < 2; h++) {
            int rl = warp_m * 32 + mf * 16 + h * 8 + quad_r;
            const float* base = aggw + (size_t)sidp[rl] * HDIM;
#pragma unroll
            for (int nt = 0; nt < 8; nt++) {
                float2 v = *(const float2*)(base + warp_n * 64 + nt * 8 + quad_c * 2);
                acc[mf][nt][2 * h]     = v.x;
                acc[mf][nt][2 * h + 1] = v.y;
            }
        }

#pragma unroll 1
    for (int kc = 0; kc < 4; kc++) {
        if (kc < 3) { issue_chunk(kc + 1, (kc + 1) & 1); cp_wait<1>(); }
        else        { cp_wait<0>(); }
        __syncthreads();

        const float* Ab = As + (kc & 1) * AS_BUF;
        const float* Wc = Wsm + (kc & 1) * WS_BUF;
#pragma unroll
        for (int ks = 0; ks < 4; ks++) {
            const int kk = ks * 8;
            unsigned afr[2][4];
#pragma unroll
            for (int mf = 0; mf < 2; mf++) {
                const float* p = Ab + (warp_m * 32 + mf * 16 + quad_r) * AS_STRIDE
                                    + kk + quad_c;
                afr[mf][0] = __float_as_uint(p[0]);
                afr[mf][1] = __float_as_uint(p[8 * AS_STRIDE]);
                afr[mf][2] = __float_as_uint(p[4]);
                afr[mf][3] = __float_as_uint(p[8 * AS_STRIDE + 4]);
            }
            unsigned bfr[8][2];
#pragma unroll
            for (int nt = 0; nt < 8; nt++) {
                const float* p = Wc + (kk + quad_c) * WS_STRIDE
                                    + warp_n * 64 + nt * 8 + quad_r;
                bfr[nt][0] = __float_as_uint(p[0]);
                bfr[nt][1] = __float_as_uint(p[4 * WS_STRIDE]);
            }
#pragma unroll
            for (int mf = 0; mf < 2; mf++)
#pragma unroll
                for (int nt = 0; nt < 8; nt++)
                    mma_tf32(acc[mf][nt], afr[mf], bfr[nt]);
        }
        __syncthreads();
    }

    // ---- LayerNorm statistics ----
    float s[2][2], q[2][2];
#pragma unroll
    for (int mf = 0; mf < 2; mf++)
#pragma unroll
        for (int h = 0; h < 2; h++) {
            float ss = 0.f, qq = 0.f;
#pragma unroll
            for (int nt = 0; nt < 8; nt++) {
                float z0 = acc[mf][nt][2 * h], z1 = acc[mf][nt][2 * h + 1];
                ss += z0 + z1;
                qq += z0 * z0 + z1 * z1;
            }
            s[mf][h] = ss; q[mf][h] = qq;
        }
#pragma unroll
    for (int mk = 1; mk <= 2; mk <<= 1)
#pragma unroll
        for (int mf = 0; mf < 2; mf++)
#pragma unroll
            for (int h = 0; h < 2; h++) {
                s[mf][h] += __shfl_xor_sync(0xffffffffu, s[mf][h], mk);
                q[mf][h] += __shfl_xor_sync(0xffffffffu, q[mf][h], mk);
            }
    if (quad_c == 0) {
#pragma unroll
        for (int mf = 0; mf < 2; mf++)
#pragma unroll
            for (int h = 0; h < 2; h++) {
                int rl = warp_m * 32 + mf * 16 + h * 8 + quad_r;
                red2[rl * 2 + warp_n] = make_float2(s[mf][h], q[mf][h]);
            }
    }
    __syncthreads();
    float mu[2][2], rs[2][2];
#pragma unroll
    for (int mf = 0; mf < 2; mf++)
#pragma unroll
        for (int h = 0; h < 2; h++) {
            int rl = warp_m * 32 + mf * 16 + h * 8 + quad_r;
            float2 r0 = red2[rl * 2 + 0], r1 = red2[rl * 2 + 1];
            float ss = r0.x + r1.x, qq = r0.y + r1.y;
            float m = ss * (1.f / HDIM);
            float var = fmaf(qq, 1.f / HDIM, -m * m);
            mu[mf][h] = m;
            rs[mf][h] = rsqrtf(var + LN_EPS);
        }
    __syncthreads();   // all warps done with As/Wsm/red2 before staging

    // ---- normalize + ReLU: store to hout (optional) and stage for segmax ----
#pragma unroll
    for (int nt = 0; nt < 8; nt++) {
        int col = warp_n * 64 + nt * 8 + quad_c * 2;
        float2 gv = *(const float2*)&gw[col];
        float2 ev = *(const float2*)&be[col];
#pragma unroll
        for (int mf = 0; mf < 2; mf++)
#pragma unroll
            for (int h = 0; h < 2; h++) {
                int rl = warp_m * 32 + mf * 16 + h * 8 + quad_r;
                float z0 = acc[mf][nt][2 * h], z1 = acc[mf][nt][2 * h + 1];
                float2 o;
                o.x = fmaxf(fmaf((z0 - mu[mf][h]) * rs[mf][h], gv.x, ev.x), 0.f);
                o.y = fmaxf(fmaf((z1 - mu[mf][h]) * rs[mf][h], gv.y, ev.y), 0.f);
                *(float2*)&stage[rl * STAGE_STRIDE + col] = o;
                int grow = row0 + rl;
                if (hout && grow < N)
                    *(float2*)(hout + (size_t)grow * HDIM + col) = o;
            }
    }
    __syncthreads();

    // ---- fused segmented max: warp-per-segment over the staged tile ----
    {
        const int p_first = sidp[0];
        const int p_last  = sidp[127];
        for (int seg = p_first + warp; seg <= p_last; seg += 8) {
            int b = g_offsets[seg], e = g_offsets[seg + 1];
            int r0 = b - row0; if (r0 < 0) r0 = 0;
            int r1 = e - row0; if (r1 > 128) r1 = 128;
            if (r1 <= r0) continue;
            float4 m = make_float4(0.f, 0.f, 0.f, 0.f);
            for (int r = r0; r < r1; r++) {
                float4 v = *(const float4*)&stage[r * STAGE_STRIDE + lane * 4];
                m.x = fmaxf(m.x, v.x); m.y = fmaxf(m.y, v.y);
                m.z = fmaxf(m.z, v.z); m.w = fmaxf(m.w, v.w);
            }
            float* dst = maxout + (size_t)seg * HDIM + lane * 4;
            bool bnd = (b < row0) || (e > row0 + 128);
            if (bnd) {
                atomicMax((int*)dst + 0, __float_as_int(m.x));
                atomicMax((int*)dst + 1, __float_as_int(m.y));
                atomicMax((int*)dst + 2, __float_as_int(m.z));
                atomicMax((int*)dst + 3, __float_as_int(m.w));
            } else {
                *(float4*)dst = m;
            }
        }
    }
}

// ---------------- output tail ----------------
__global__ void tail_kernel(float* out, int tail) {
    int i = blockIdx.x * blockDim.x + threadIdx.x;
    float* base = out + (size_t)PNUM * HDIM;
    if (tail == PNUM) {
        if (i < PNUM) base[i] = (float)i;
    } else if (tail == 2 * PNUM) {
        if (i < PNUM) ((long long*)base)[i] = (long long)i;
    } else {
        if (i < tail) base[i] = (float)i;
    }
}

// ---------------- launch ----------------
extern "C" void kernel_launch(void* const* d_in, const int* in_sizes, int n_in,
                              void* d_out, int out_size) {
    const float* x   = (const float*)d_in[0];
    const void*  ids = d_in[1];
    const float* W0  = (const float*)d_in[2];
    const float* b0  = (const float*)d_in[3];
    const float* g0  = (const float*)d_in[4];
    const float* be0 = (const float*)d_in[5];
    const float* W1  = (const float*)d_in[6];
    const float* b1  = (const float*)d_in[7];
    const float* g1  = (const float*)d_in[8];
    const float* be1 = (const float*)d_in[9];
    const float* W2  = (const float*)d_in[10];
    const float* b2  = (const float*)d_in[11];
    const float* g2  = (const float*)d_in[12];
    const float* be2 = (const float*)d_in[13];

    const int N = in_sizes[0] / 9;
    const int P = PNUM;
    float* out = (float*)d_out;

    float *h0, *h1, *agg, *agg2, *aggw;
    int* counts;
    cudaGetSymbolAddress((void**)&h0,   g_h0);
    cudaGetSymbolAddress((void**)&h1,   g_h1);
    cudaGetSymbolAddress((void**)&agg,  g_agg);
    cudaGetSymbolAddress((void**)&agg2, g_agg2);
    cudaGetSymbolAddress((void**)&aggw, g_aggw);
    cudaGetSymbolAddress((void**)&counts, g_counts);

    cudaFuncSetAttribute(enc_kernel,
        cudaFuncAttributeMaxDynamicSharedMemorySize, ENC_SMEM_BYTES);
    cudaFuncSetAttribute(aggw_kernel,
        cudaFuncAttributeMaxDynamicSharedMemorySize, ENC_SMEM_BYTES);
    cudaFuncSetAttribute(enc0_kernel,
        cudaFuncAttributeMaxDynamicSharedMemorySize, ENC0_SMEM_BYTES);

    // 0) independent zero-inits + tail, issued first (no upstream deps)
    cudaMemsetAsync(agg,  0, (size_t)P * HDIM * sizeof(float));
    cudaMemsetAsync(agg2, 0, (size_t)P * HDIM * sizeof(float));
    cudaMemsetAsync(out,  0, (size_t)P * HDIM * sizeof(float));
    cudaMemsetAsync(counts, 0, (size_t)P * sizeof(int));
    int tail = out_size - P * HDIM;
    if (tail > 0) {
        int elems = (tail == 2 * PNUM) ? PNUM : tail;
        tail_kernel<<<(elems + 255) / 256, 256>>>(out, tail);
    }

    // 1) id normalization + CSR build (three-phase parallel scan)
    detect_ids_kernel<<<1, 1>>>(ids);
    prep_kernel<<<(N + 255) / 256, 256>>>(ids, N);
    scan1_kernel<<<SCAN_NB, 256>>>();
    scan2_kernel<<<1, 256>>>();
    scan3_kernel<<<SCAN_NB, 256>>>();
    scatter_kernel<<<(N + 255) / 256, 256>>>(N);

    // 2) enc0 -> h0 + fused seg_max -> agg
    enc0_kernel<<<(N + 127) / 128, 256, ENC0_SMEM_BYTES>>>(
        x, W0, b0, g0, be0, h0, agg, N);

    // 3) layer 1: aggW(agg); enc1 -> h1 + fused seg_max -> agg2
    aggw_kernel<<<(P + 127) / 128, 256, ENC_SMEM_BYTES>>>(
        agg, W1 + (size_t)HDIM * HDIM, b1, aggw, P);
    enc_kernel<<<(N + 127) / 128, 256, ENC_SMEM_BYTES>>>(
        h0, aggw, W1, g1, be1, h1, agg2, N);

    // 4) layer 2: aggW(agg2); enc2 (no h store) + fused seg_max -> out
    aggw_kernel<<<(P + 127) / 128, 256, ENC_SMEM_BYTES>>>(
        agg2, W2 + (size_t)HDIM * HDIM, b2, aggw, P);
    enc_kernel<<<(N + 127) / 128, 256, ENC_SMEM_BYTES>>>(
        h1, aggw, W2, g2, be2, nullptr, out, N);
}

// round 11
// speedup vs baseline: 1.4105x; 1.0236x over previous
#include <cuda_runtime.h>
#include <cstdint>

#define HDIM 128
#define NMAX 500000
#define PNUM 50000
#define LN_EPS 1e-5f
#define SCAN_NB ((PNUM + 255) / 256)   // 196

// ---------------- scratch (static __device__; no allocation) ----------------
__device__ float g_h0[(size_t)NMAX * HDIM];
__device__ float g_h1[(size_t)NMAX * HDIM];
__device__ float g_agg[(size_t)PNUM * HDIM];
__device__ float g_agg2[(size_t)PNUM * HDIM];
__device__ float g_aggw[(size_t)PNUM * HDIM];
__device__ int   g_counts[PNUM];
__device__ int   g_scantmp[PNUM];
__device__ int   g_blocksums[SCAN_NB];
__device__ int   g_offsets[PNUM + 1];
__device__ int   g_cursor[PNUM];
__device__ int   g_order[NMAX];   // sorted position -> original row
__device__ int   g_sid[NMAX];     // sorted position -> id (non-decreasing)
__device__ int   g_ids[NMAX];     // original row -> id

// ---------------- prep: per-block dtype detect + convert + histogram --------
__global__ void prep_kernel(const void* idsraw, int N) {
    __shared__ int s_ok;
    const long long* a64 = (const long long*)idsraw;
    int lane_ok = 1;
    if (threadIdx.x < 16) {
        long long v = a64[threadIdx.x];
        lane_ok = (v >= 0 && v < PNUM);
    }
    if (threadIdx.x < 32) {
        unsigned m = __ballot_sync(0xffffffffu, lane_ok);
        if (threadIdx.x == 0) s_ok = ((m & 0xffffu) == 0xffffu) ? 1 : 0;
    }
    __syncthreads();
    int ids64 = s_ok;
    int i = blockIdx.x * blockDim.x + threadIdx.x;
    if (i >= N) return;
    int v = ids64 ? (int)a64[i] : ((const int*)idsraw)[i];
    g_ids[i] = v;
    atomicAdd(&g_counts[v], 1);
}

// ---------------- scan over g_counts (2 kernels) ----------------
__device__ __forceinline__ int block_inclusive_scan_256(int v, int* wsum) {
    int lane = threadIdx.x & 31, w = threadIdx.x >> 5;
    int x = v;
#pragma unroll
    for (int o = 1; o < 32; o <<= 1) {
        int t = __shfl_up_sync(0xffffffffu, x, o);
        if (lane >= o) x += t;
    }
    if (lane == 31) wsum[w] = x;
    __syncthreads();
    if (w == 0) {
        int y = (lane < 8) ? wsum[lane] : 0;
#pragma unroll
        for (int o = 1; o < 8; o <<= 1) {
            int t = __shfl_up_sync(0xffffffffu, y, o);
            if (lane >= o) y += t;
        }
        if (lane < 8) wsum[lane] = y;
    }
    __syncthreads();
    return x + (w > 0 ? wsum[w - 1] : 0);
}

__global__ void scan1_kernel() {
    __shared__ int wsum[8];
    int i = blockIdx.x * 256 + threadIdx.x;
    int v = (i < PNUM) ? g_counts[i] : 0;
    int incl = block_inclusive_scan_256(v, wsum);
    if (i < PNUM) g_scantmp[i] = incl;
    if (threadIdx.x == 255) g_blocksums[blockIdx.x] = incl;
}

// merged scan2+scan3: every block redundantly scans the 196 block sums
__global__ void scan23_kernel() {
    __shared__ int wsum[8];
    __shared__ int bs[256];
    int t = threadIdx.x;
    int v = (t < SCAN_NB) ? g_blocksums[t] : 0;
    int incl = block_inclusive_scan_256(v, wsum);
    bs[t] = incl;
    __syncthreads();
    int i = blockIdx.x * 256 + t;
    if (i >= PNUM) return;
    int off = (blockIdx.x > 0) ? bs[blockIdx.x - 1] : 0;
    int inclv = off + g_scantmp[i];
    int excl = inclv - g_counts[i];
    g_offsets[i] = excl;
    g_cursor[i] = excl;
    if (i == PNUM - 1) g_offsets[PNUM] = inclv;
}

__global__ void scatter_kernel(int N) {
    int i = blockIdx.x * blockDim.x + threadIdx.x;
    if (i >= N) return;
    int id = g_ids[i];
    int pos = atomicAdd(&g_cursor[id], 1);
    g_order[pos] = i;
    g_sid[pos] = id;
}

#define STAGE_STRIDE 132
#define ENC0_SMEM_FLOATS (128 * STAGE_STRIDE + 128)
#define ENC0_SMEM_BYTES (ENC0_SMEM_FLOATS * 4)

// ---------------- encoder 0 with fused segmented max -------------------------
__global__ __launch_bounds__(256, 2) void enc0_kernel(
    const float* __restrict__ x, const float* __restrict__ W0,
    const float* __restrict__ b0, const float* __restrict__ g0,
    const float* __restrict__ be0, float* __restrict__ out,
    float* __restrict__ maxout, int N)
{
    extern __shared__ float sm[];
    float* stage = sm;
    int* sidp = (int*)(sm + 128 * STAGE_STRIDE);

    const int tid = threadIdx.x;
    const int lane = tid & 31;
    const int warp = tid >> 5;
    const int row0 = blockIdx.x * 128;

    if (tid < 128) {
        int r = row0 + tid;
        sidp[tid] = g_sid[(r < N) ? r : (N - 1)];
    }

    float w[9][4], bb[4], gg[4], ee[4];
#pragma unroll
    for (int k = 0; k < 9; k++)
#pragma unroll
        for (int c = 0; c < 4; c++)
            w[k][c] = W0[k * HDIM + lane + 32 * c];
#pragma unroll
    for (int c = 0; c < 4; c++) {
        bb[c] = b0[lane + 32 * c];
        gg[c] = g0[lane + 32 * c];
        ee[c] = be0[lane + 32 * c];
    }

#pragma unroll 1
    for (int rr = 0; rr < 16; rr++) {
        int rl = warp * 16 + rr;
        int spos = row0 + rl;
        int sp = (spos < N) ? spos : (N - 1);
        int srow = g_order[sp];

        float xv = (lane < 9) ? x[(size_t)srow * 9 + lane] : 0.f;
        float z[4] = {bb[0], bb[1], bb[2], bb[3]};
#pragma unroll
        for (int k = 0; k < 9; k++) {
            float xk = __shfl_sync(0xffffffffu, xv, k);
#pragma unroll
            for (int c = 0; c < 4; c++)
                z[c] = fmaf(xk, w[k][c], z[c]);
        }
        float s  = z[0] + z[1] + z[2] + z[3];
        float s2 = z[0]*z[0] + z[1]*z[1] + z[2]*z[2] + z[3]*z[3];
#pragma unroll
        for (int o = 16; o > 0; o >>= 1) {
            s  += __shfl_xor_sync(0xffffffffu, s, o);
            s2 += __shfl_xor_sync(0xffffffffu, s2, o);
        }
        float mu  = s * (1.f / HDIM);
        float var = fmaf(s2, 1.f / HDIM, -mu * mu);
        float rs  = rsqrtf(var + LN_EPS);
#pragma unroll
        for (int c = 0; c < 4; c++)
            stage[rl * STAGE_STRIDE + lane + 32 * c] =
                fmaxf(fmaf((z[c] - mu) * rs, gg[c], ee[c]), 0.f);
    }
    __syncthreads();

    // coalesced h0 writes from stage (1 STG.128 per row per warp-iter)
#pragma unroll 1
    for (int rr = 0; rr < 16; rr++) {
        int rl = warp * 16 + rr;
        int spos = row0 + rl;
        if (spos < N) {
            float4 v = *(const float4*)&stage[rl * STAGE_STRIDE + lane * 4];
            *(float4*)(out + (size_t)spos * HDIM + lane * 4) = v;
        }
    }

    // fused segmented max: warp-per-segment
    {
        const int p_first = sidp[0];
        const int p_last  = sidp[127];
        for (int seg = p_first + warp; seg <= p_last; seg += 8) {
            int b = g_offsets[seg], e = g_offsets[seg + 1];
            int r0 = b - row0; if (r0 < 0) r0 = 0;
            int r1 = e - row0; if (r1 > 128) r1 = 128;
            if (r1 <= r0) continue;
            float4 m = make_float4(0.f, 0.f, 0.f, 0.f);
            for (int r = r0; r < r1; r++) {
                float4 vv = *(const float4*)&stage[r * STAGE_STRIDE + lane * 4];
                m.x = fmaxf(m.x, vv.x); m.y = fmaxf(m.y, vv.y);
                m.z = fmaxf(m.z, vv.z); m.w = fmaxf(m.w, vv.w);
            }
            float* dst = maxout + (size_t)seg * HDIM + lane * 4;
            bool bnd = (b < row0) || (e > row0 + 128);
            if (bnd) {
                atomicMax((int*)dst + 0, __float_as_int(m.x));
                atomicMax((int*)dst + 1, __float_as_int(m.y));
                atomicMax((int*)dst + 2, __float_as_int(m.z));
                atomicMax((int*)dst + 3, __float_as_int(m.w));
            } else {
                *(float4*)dst = m;
            }
        }
    }
}

// ---------------- tf32 mma.sync helpers ----------------
__device__ __forceinline__ void cp_async16(float* s, const float* g) {
    unsigned sa = (unsigned)__cvta_generic_to_shared(s);
    asm volatile("cp.async.cg.shared.global [%0], [%1], 16;\n" :: "r"(sa), "l"(g));
}
__device__ __forceinline__ void cp_commit() {
    asm volatile("cp.async.commit_group;\n" ::: "memory");
}
template<int n> __device__ __forceinline__ void cp_wait() {
    asm volatile("cp.async.wait_group %0;\n" :: "n"(n) : "memory");
}
__device__ __forceinline__ void mma_tf32(float acc[4], const unsigned a[4], const unsigned b[2]) {
    asm volatile(
        "mma.sync.aligned.m16n8k8.row.col.f32.tf32.tf32.f32 "
        "{%0,%1,%2,%3},{%4,%5,%6,%7},{%8,%9},{%0,%1,%2,%3};\n"
        : "+f"(acc[0]), "+f"(acc[1]), "+f"(acc[2]), "+f"(acc[3])
        : "r"(a[0]), "r"(a[1]), "r"(a[2]), "r"(a[3]), "r"(b[0]), "r"(b[1]));
}

#define AS_STRIDE 36
#define WS_STRIDE 136
#define AS_BUF (128 * AS_STRIDE)
#define WS_BUF (32 * WS_STRIDE)
#define ENC_SMEM_FLOATS (2*AS_BUF + 2*WS_BUF + 512 + 128)
#define ENC_SMEM_BYTES (ENC_SMEM_FLOATS * 4)

// ---------------- aggw kernel: aggW = bias + agg @ W_bot  (P x 128, K=128) ---
__global__ __launch_bounds__(256, 2) void aggw_kernel(
    const float* __restrict__ agg, const float* __restrict__ Wb,
    const float* __restrict__ b, float* __restrict__ aggw, int P)
{
    extern __shared__ float sm[];
    float* As  = sm;
    float* Wsm = sm + 2 * AS_BUF;

    const int tid = threadIdx.x;
    const int lane = tid & 31;
    const int quad_r = lane >> 2, quad_c = lane & 3;
    const int warp = tid >> 5;
    const int warp_m = warp >> 1, warp_n = warp & 1;
    const int row0 = blockIdx.x * 128;

    float acc[2][8][4];
#pragma unroll
    for (int nt = 0; nt < 8; nt++) {
        float2 bv = *(const float2*)&b[warp_n * 64 + nt * 8 + quad_c * 2];
#pragma unroll
        for (int mf = 0; mf < 2; mf++) {
            acc[mf][nt][0] = bv.x; acc[mf][nt][1] = bv.y;
            acc[mf][nt][2] = bv.x; acc[mf][nt][3] = bv.y;
        }
    }

    auto issue_chunk = [&](int kc, int buf) {
        float* Ab = As + buf * AS_BUF;
        float* Wc = Wsm + buf * WS_BUF;
#pragma unroll
        for (int i = 0; i < 4; i++) {
            int idx = tid + i * 256;
            int r = idx >> 3, f = idx & 7;
            int gr = row0 + r; if (gr >= P) gr = P - 1;
            cp_async16(Ab + r * AS_STRIDE + f * 4,
                       agg + (size_t)gr * HDIM + kc * 32 + f * 4);
        }
#pragma unroll
        for (int i = 0; i < 4; i++) {
            int idx = tid + i * 256;
            int k = idx >> 5, f = idx & 31;
            cp_async16(Wc + k * WS_STRIDE + f * 4,
                       Wb + (size_t)(kc * 32 + k) * HDIM + f * 4);
        }
        cp_commit();
    };

    issue_chunk(0, 0);

#pragma unroll 1
    for (int kc = 0; kc < 4; kc++) {
        if (kc < 3) { issue_chunk(kc + 1, (kc + 1) & 1); cp_wait<1>(); }
        else        { cp_wait<0>(); }
        __syncthreads();
        const float* Ab = As + (kc & 1) * AS_BUF;
        const float* Wc = Wsm + (kc & 1) * WS_BUF;
#pragma unroll
        for (int ks = 0; ks < 4; ks++) {
            const int kk = ks * 8;
            unsigned afr[2][4];
#pragma unroll
            for (int mf = 0; mf < 2; mf++) {
                const float* p = Ab + (warp_m * 32 + mf * 16 + quad_r) * AS_STRIDE
                                    + kk + quad_c;
                afr[mf][0] = __float_as_uint(p[0]);
                afr[mf][1] = __float_as_uint(p[8 * AS_STRIDE]);
                afr[mf][2] = __float_as_uint(p[4]);
                afr[mf][3] = __float_as_uint(p[8 * AS_STRIDE + 4]);
            }
            unsigned bfr[8][2];
#pragma unroll
            for (int nt = 0; nt < 8; nt++) {
                const float* p = Wc + (kk + quad_c) * WS_STRIDE
                                    + warp_n * 64 + nt * 8 + quad_r;
                bfr[nt][0] = __float_as_uint(p[0]);
                bfr[nt][1] = __float_as_uint(p[4 * WS_STRIDE]);
            }
#pragma unroll
            for (int mf = 0; mf < 2; mf++)
#pragma unroll
                for (int nt = 0; nt < 8; nt++)
                    mma_tf32(acc[mf][nt], afr[mf], bfr[nt]);
        }
        __syncthreads();
    }

#pragma unroll
    for (int nt = 0; nt < 8; nt++) {
        int col = warp_n * 64 + nt * 8 + quad_c * 2;
#pragma unroll
        for (int mf = 0; mf < 2; mf++)
#pragma unroll
            for (int h = 0; h < 2; h++) {
                int grow = row0 + warp_m * 32 + mf * 16 + h * 8 + quad_r;
                if (grow < P)
                    *(float2*)(aggw + (size_t)grow * HDIM + col) =
                        make_float2(acc[mf][nt][2 * h], acc[mf][nt][2 * h + 1]);
            }
    }
}

// ---------------- encoder 1/2 with fused segmented max -----------------------
__global__ __launch_bounds__(256, 2) void enc_kernel(
    const float* __restrict__ hprev, const float* __restrict__ aggw,
    const float* __restrict__ Wt, const float* __restrict__ gw,
    const float* __restrict__ be, float* __restrict__ hout,
    float* __restrict__ maxout, int N)
{
    extern __shared__ float sm[];
    float* As   = sm;
    float* Wsm  = sm + 2 * AS_BUF;
    float* stage = sm;                                   // reused post-mainloop
    float2* red2 = (float2*)(sm + 2*AS_BUF + 2*WS_BUF);  // 512 floats
    int*   sidp = (int*)(sm + 2*AS_BUF + 2*WS_BUF + 512); // 128 ints

    const int tid = threadIdx.x;
    const int lane = tid & 31;
    const int quad_r = lane >> 2, quad_c = lane & 3;
    const int warp = tid >> 5;
    const int warp_m = warp >> 1, warp_n = warp & 1;
    const int row0 = blockIdx.x * 128;

    if (tid < 128) {
        int r = row0 + tid;
        sidp[tid] = g_sid[(r < N) ? r : (N - 1)];
    }
    __syncthreads();

    auto issue_chunk = [&](int kc, int buf) {
        float* Ab = As + buf * AS_BUF;
        float* Wc = Wsm + buf * WS_BUF;
#pragma unroll
        for (int i = 0; i < 4; i++) {
            int idx = tid + i * 256;
            int r = idx >> 3, f = idx & 7;
            int gr = row0 + r; if (gr >= N) gr = N - 1;
            cp_async16(Ab + r * AS_STRIDE + f * 4,
                       hprev + (size_t)gr * HDIM + kc * 32 + f * 4);
        }
#pragma unroll
        for (int i = 0; i < 4; i++) {
            int idx = tid + i * 256;
            int k = idx >> 5, f = idx & 31;
            cp_async16(Wc + k * WS_STRIDE + f * 4,
                       Wt + (size_t)(kc * 32 + k) * HDIM + f * 4);
        }
        cp_commit();
    };

    issue_chunk(0, 0);

    // accumulator init = aggW[sid] gather (L2-resident table)
    float acc[2][8][4];
#pragma unroll
    for (int mf = 0; mf < 2; mf++)
#pragma unroll
        for (int h = 0; h < 2; h++) {
            int rl = warp_m * 32 + mf * 16 + h * 8 + quad_r;
            const float* base = aggw + (size_t)sidp[rl] * HDIM;
#pragma unroll
            for (int nt = 0; nt < 8; nt++) {
                float2 v = *(const float2*)(base + warp_n * 64 + nt * 8 + quad_c * 2);
                acc[mf][nt][2 * h]     = v.x;
                acc[mf][nt][2 * h + 1] = v.y;
            }
        }

#pragma unroll 1
    for (int kc = 0; kc < 4; kc++) {
        if (kc < 3) { issue_chunk(kc + 1, (kc + 1) & 1); cp_wait<1>(); }
        else        { cp_wait<0>(); }
        __syncthreads();

        const float* Ab = As + (kc & 1) * AS_BUF;
        const float* Wc = Wsm + (kc & 1) * WS_BUF;
#pragma unroll
        for (int ks = 0; ks < 4; ks++) {
            const int kk = ks * 8;
            unsigned afr[2][4];
#pragma unroll
            for (int mf = 0; mf < 2; mf++) {
                const float* p = Ab + (warp_m * 32 + mf * 16 + quad_r) * AS_STRIDE
                                    + kk + quad_c;
                afr[mf][0] = __float_as_uint(p[0]);
                afr[mf][1] = __float_as_uint(p[8 * AS_STRIDE]);
                afr[mf][2] = __float_as_uint(p[4]);
                afr[mf][3] = __float_as_uint(p[8 * AS_STRIDE + 4]);
            }
            unsigned bfr[8][2];
#pragma unroll
            for (int nt = 0; nt < 8; nt++) {
                const float* p = Wc + (kk + quad_c) * WS_STRIDE
                                    + warp_n * 64 + nt * 8 + quad_r;
                bfr[nt][0] = __float_as_uint(p[0]);
                bfr[nt][1] = __float_as_uint(p[4 * WS_STRIDE]);
            }
#pragma unroll
            for (int mf = 0; mf < 2; mf++)
#pragma unroll
                for (int nt = 0; nt < 8; nt++)
                    mma_tf32(acc[mf][nt], afr[mf], bfr[nt]);
        }
        __syncthreads();
    }

    // ---- LayerNorm statistics ----
    float s[2][2], q[2][2];
#pragma unroll
    for (int mf = 0; mf < 2; mf++)
#pragma unroll
        for (int h = 0; h < 2; h++) {
            float ss = 0.f, qq = 0.f;
#pragma unroll
            for (int nt = 0; nt < 8; nt++) {
                float z0 = acc[mf][nt][2 * h], z1 = acc[mf][nt][2 * h + 1];
                ss += z0 + z1;
                qq += z0 * z0 + z1 * z1;
            }
            s[mf][h] = ss; q[mf][h] = qq;
        }
#pragma unroll
    for (int mk = 1; mk <= 2; mk <<= 1)
#pragma unroll
        for (int mf = 0; mf < 2; mf++)
#pragma unroll
            for (int h = 0; h < 2; h++) {
                s[mf][h] += __shfl_xor_sync(0xffffffffu, s[mf][h], mk);
                q[mf][h] += __shfl_xor_sync(0xffffffffu, q[mf][h], mk);
            }
    if (quad_c == 0) {
#pragma unroll
        for (int mf = 0; mf < 2; mf++)
#pragma unroll
            for (int h = 0; h < 2; h++) {
                int rl = warp_m * 32 + mf * 16 + h * 8 + quad_r;
                red2[rl * 2 + warp_n] = make_float2(s[mf][h], q[mf][h]);
            }
    }
    __syncthreads();
    float mu[2][2], rs[2][2];
#pragma unroll
    for (int mf = 0; mf < 2; mf++)
#pragma unroll
        for (int h = 0; h < 2; h++) {
            int rl = warp_m * 32 + mf * 16 + h * 8 + quad_r;
            float2 r0 = red2[rl * 2 + 0], r1 = red2[rl * 2 + 1];
            float ss = r0.x + r1.x, qq = r0.y + r1.y;
            float m = ss * (1.f / HDIM);
            float var = fmaf(qq, 1.f / HDIM, -m * m);
            mu[mf][h] = m;
            rs[mf][h] = rsqrtf(var + LN_EPS);
        }
    __syncthreads();   // all warps done with As/Wsm/red2 before staging

    // ---- normalize + ReLU into stage ----
#pragma unroll
    for (int nt = 0; nt < 8; nt++) {
        int col = warp_n * 64 + nt * 8 + quad_c * 2;
        float2 gv = *(const float2*)&gw[col];
        float2 ev = *(const float2*)&be[col];
#pragma unroll
        for (int mf = 0; mf < 2; mf++)
#pragma unroll
            for (int h = 0; h < 2; h++) {
                int rl = warp_m * 32 + mf * 16 + h * 8 + quad_r;
                float z0 = acc[mf][nt][2 * h], z1 = acc[mf][nt][2 * h + 1];
                float2 o;
                o.x = fmaxf(fmaf((z0 - mu[mf][h]) * rs[mf][h], gv.x, ev.x), 0.f);
                o.y = fmaxf(fmaf((z1 - mu[mf][h]) * rs[mf][h], gv.y, ev.y), 0.f);
                *(float2*)&stage[rl * STAGE_STRIDE + col] = o;
            }
    }
    __syncthreads();

    // ---- coalesced hout writes from stage (1 STG.128 per row per warp-iter) --
    if (hout) {
#pragma unroll 1
        for (int rr = 0; rr < 16; rr++) {
            int rl = warp * 16 + rr;
            int grow = row0 + rl;
            if (grow < N) {
                float4 v = *(const float4*)&stage[rl * STAGE_STRIDE + lane * 4];
                *(float4*)(hout + (size_t)grow * HDIM + lane * 4) = v;
            }
        }
    }

    // ---- fused segmented max: warp-per-segment over the staged tile ----
    {
        const int p_first = sidp[0];
        const int p_last  = sidp[127];
        for (int seg = p_first + warp; seg <= p_last; seg += 8) {
            int b = g_offsets[seg], e = g_offsets[seg + 1];
            int r0 = b - row0; if (r0 < 0) r0 = 0;
            int r1 = e - row0; if (r1 > 128) r1 = 128;
            if (r1 <= r0) continue;
            float4 m = make_float4(0.f, 0.f, 0.f, 0.f);
            for (int r = r0; r < r1; r++) {
                float4 v = *(const float4*)&stage[r * STAGE_STRIDE + lane * 4];
                m.x = fmaxf(m.x, v.x); m.y = fmaxf(m.y, v.y);
                m.z = fmaxf(m.z, v.z); m.w = fmaxf(m.w, v.w);
            }
            float* dst = maxout + (size_t)seg * HDIM + lane * 4;
            bool bnd = (b < row0) || (e > row0 + 128);
            if (bnd) {
                atomicMax((int*)dst + 0, __float_as_int(m.x));
                atomicMax((int*)dst + 1, __float_as_int(m.y));
                atomicMax((int*)dst + 2, __float_as_int(m.z));
                atomicMax((int*)dst + 3, __float_as_int(m.w));
            } else {
                *(float4*)dst = m;
            }
        }
    }
}

// ---------------- output tail ----------------
__global__ void tail_kernel(float* out, int tail) {
    int i = blockIdx.x * blockDim.x + threadIdx.x;
    float* base = out + (size_t)PNUM * HDIM;
    if (tail == PNUM) {
        if (i < PNUM) base[i] = (float)i;
    } else if (tail == 2 * PNUM) {
        if (i < PNUM) ((long long*)base)[i] = (long long)i;
    } else {
        if (i < tail) base[i] = (float)i;
    }
}

// ---------------- launch ----------------
extern "C" void kernel_launch(void* const* d_in, const int* in_sizes, int n_in,
                              void* d_out, int out_size) {
    const float* x   = (const float*)d_in[0];
    const void*  ids = d_in[1];
    const float* W0  = (const float*)d_in[2];
    const float* b0  = (const float*)d_in[3];
    const float* g0  = (const float*)d_in[4];
    const float* be0 = (const float*)d_in[5];
    const float* W1  = (const float*)d_in[6];
    const float* b1  = (const float*)d_in[7];
    const float* g1  = (const float*)d_in[8];
    const float* be1 = (const float*)d_in[9];
    const float* W2  = (const float*)d_in[10];
    const float* b2  = (const float*)d_in[11];
    const float* g2  = (const float*)d_in[12];
    const float* be2 = (const float*)d_in[13];

    const int N = in_sizes[0] / 9;
    const int P = PNUM;
    float* out = (float*)d_out;

    float *h0, *h1, *agg, *agg2, *aggw;
    int* counts;
    cudaGetSymbolAddress((void**)&h0,   g_h0);
    cudaGetSymbolAddress((void**)&h1,   g_h1);
    cudaGetSymbolAddress((void**)&agg,  g_agg);
    cudaGetSymbolAddress((void**)&agg2, g_agg2);
    cudaGetSymbolAddress((void**)&aggw, g_aggw);
    cudaGetSymbolAddress((void**)&counts, g_counts);

    cudaFuncSetAttribute(enc_kernel,
        cudaFuncAttributeMaxDynamicSharedMemorySize, ENC_SMEM_BYTES);
    cudaFuncSetAttribute(aggw_kernel,
        cudaFuncAttributeMaxDynamicSharedMemorySize, ENC_SMEM_BYTES);
    cudaFuncSetAttribute(enc0_kernel,
        cudaFuncAttributeMaxDynamicSharedMemorySize, ENC0_SMEM_BYTES);

    // 0) independent zero-inits + tail, issued first (no upstream deps)
    cudaMemsetAsync(agg,  0, (size_t)P * HDIM * sizeof(float));
    cudaMemsetAsync(agg2, 0, (size_t)P * HDIM * sizeof(float));
    cudaMemsetAsync(out,  0, (size_t)P * HDIM * sizeof(float));
    cudaMemsetAsync(counts, 0, (size_t)P * sizeof(int));
    int tail = out_size - P * HDIM;
    if (tail > 0) {
        int elems = (tail == 2 * PNUM) ? PNUM : tail;
        tail_kernel<<<(elems + 255) / 256, 256>>>(out, tail);
    }

    // 1) CSR build: prep (detect folded in), scan1, scan23, scatter
    prep_kernel<<<(N + 255) / 256, 256>>>(ids, N);
    scan1_kernel<<<SCAN_NB, 256>>>();
    scan23_kernel<<<SCAN_NB, 256>>>();
    scatter_kernel<<<(N + 255) / 256, 256>>>(N);

    // 2) enc0 -> h0 + fused seg_max -> agg
    enc0_kernel<<<(N + 127) / 128, 256, ENC0_SMEM_BYTES>>>(
        x, W0, b0, g0, be0, h0, agg, N);

    // 3) layer 1: aggW(agg); enc1 -> h1 + fused seg_max -> agg2
    aggw_kernel<<<(P + 127) / 128, 256, ENC_SMEM_BYTES>>>(
        agg, W1 + (size_t)HDIM * HDIM, b1, aggw, P);
    enc_kernel<<<(N + 127) / 128, 256, ENC_SMEM_BYTES>>>(
        h0, aggw, W1, g1, be1, h1, agg2, N);

    // 4) layer 2: aggW(agg2); enc2 (no h store) + fused seg_max -> out
    aggw_kernel<<<(P + 127) / 128, 256, ENC_SMEM_BYTES>>>(
        agg2, W2 + (size_t)HDIM * HDIM, b2, aggw, P);
    enc_kernel<<<(N + 127) / 128, 256, ENC_SMEM_BYTES>>>(
        h1, aggw, W2, g2, be2, nullptr, out, N);
}

// round 12
// speedup vs baseline: 1.6375x; 1.1609x over previous
#include <cuda_runtime.h>
#include <cuda_fp16.h>
#include <cstdint>

#define HDIM 128
#define NMAX 500000
#define PNUM 50000
#define LN_EPS 1e-5f
#define SCAN_NB ((PNUM + 255) / 256)   // 196

// ---------------- scratch (static __device__; no allocation) ----------------
__device__ __half g_h0[(size_t)NMAX * HDIM];
__device__ __half g_h1[(size_t)NMAX * HDIM];
__device__ __half g_WT1[HDIM * HDIM];   // W1_top^T fp16 [n][k]
__device__ __half g_WT2[HDIM * HDIM];   // W2_top^T fp16 [n][k]
__device__ float g_agg[(size_t)PNUM * HDIM];
__device__ float g_agg2[(size_t)PNUM * HDIM];
__device__ float g_aggw[(size_t)PNUM * HDIM];
__device__ int   g_counts[PNUM];
__device__ int   g_scantmp[PNUM];
__device__ int   g_blocksums[SCAN_NB];
__device__ int   g_offsets[PNUM + 1];
__device__ int   g_cursor[PNUM];
__device__ int   g_order[NMAX];
__device__ int   g_sid[NMAX];
__device__ int   g_ids[NMAX];

// ---------------- W^T fp16 conversion (off critical path) ----------------
__global__ void wconv_kernel(const float* __restrict__ W1t,
                             const float* __restrict__ W2t) {
    int k = blockIdx.x;      // 0..127
    int n = threadIdx.x;     // 0..127
    g_WT1[n * HDIM + k] = __float2half(W1t[(size_t)k * HDIM + n]);
    g_WT2[n * HDIM + k] = __float2half(W2t[(size_t)k * HDIM + n]);
}

// ---------------- prep: per-block dtype detect + convert + histogram --------
__global__ void prep_kernel(const void* idsraw, int N) {
    __shared__ int s_ok;
    const long long* a64 = (const long long*)idsraw;
    int lane_ok = 1;
    if (threadIdx.x < 16) {
        long long v = a64[threadIdx.x];
        lane_ok = (v >= 0 && v < PNUM);
    }
    if (threadIdx.x < 32) {
        unsigned m = __ballot_sync(0xffffffffu, lane_ok);
        if (threadIdx.x == 0) s_ok = ((m & 0xffffu) == 0xffffu) ? 1 : 0;
    }
    __syncthreads();
    int ids64 = s_ok;
    int i = blockIdx.x * blockDim.x + threadIdx.x;
    if (i >= N) return;
    int v = ids64 ? (int)a64[i] : ((const int*)idsraw)[i];
    g_ids[i] = v;
    atomicAdd(&g_counts[v], 1);
}

// ---------------- scan over g_counts ----------------
__device__ __forceinline__ int block_inclusive_scan_256(int v, int* wsum) {
    int lane = threadIdx.x & 31, w = threadIdx.x >> 5;
    int x = v;
#pragma unroll
    for (int o = 1; o < 32; o <<= 1) {
        int t = __shfl_up_sync(0xffffffffu, x, o);
        if (lane >= o) x += t;
    }
    if (lane == 31) wsum[w] = x;
    __syncthreads();
    if (w == 0) {
        int y = (lane < 8) ? wsum[lane] : 0;
#pragma unroll
        for (int o = 1; o < 8; o <<= 1) {
            int t = __shfl_up_sync(0xffffffffu, y, o);
            if (lane >= o) y += t;
        }
        if (lane < 8) wsum[lane] = y;
    }
    __syncthreads();
    return x + (w > 0 ? wsum[w - 1] : 0);
}

__global__ void scan1_kernel() {
    __shared__ int wsum[8];
    int i = blockIdx.x * 256 + threadIdx.x;
    int v = (i < PNUM) ? g_counts[i] : 0;
    int incl = block_inclusive_scan_256(v, wsum);
    if (i < PNUM) g_scantmp[i] = incl;
    if (threadIdx.x == 255) g_blocksums[blockIdx.x] = incl;
}

__global__ void scan23_kernel() {
    __shared__ int wsum[8];
    __shared__ int bs[256];
    int t = threadIdx.x;
    int v = (t < SCAN_NB) ? g_blocksums[t] : 0;
    int incl = block_inclusive_scan_256(v, wsum);
    bs[t] = incl;
    __syncthreads();
    int i = blockIdx.x * 256 + t;
    if (i >= PNUM) return;
    int off = (blockIdx.x > 0) ? bs[blockIdx.x - 1] : 0;
    int inclv = off + g_scantmp[i];
    int excl = inclv - g_counts[i];
    g_offsets[i] = excl;
    g_cursor[i] = excl;
    if (i == PNUM - 1) g_offsets[PNUM] = inclv;
}

__global__ void scatter_kernel(int N) {
    int i = blockIdx.x * blockDim.x + threadIdx.x;
    if (i >= N) return;
    int id = g_ids[i];
    int pos = atomicAdd(&g_cursor[id], 1);
    g_order[pos] = i;
    g_sid[pos] = id;
}

#define STAGE_STRIDE 132
#define ENC0_SMEM_FLOATS (128 * STAGE_STRIDE + 128)
#define ENC0_SMEM_BYTES (ENC0_SMEM_FLOATS * 4)

// ---------------- encoder 0 with fused segmented max -------------------------
__global__ __launch_bounds__(256, 2) void enc0_kernel(
    const float* __restrict__ x, const float* __restrict__ W0,
    const float* __restrict__ b0, const float* __restrict__ g0,
    const float* __restrict__ be0, __half* __restrict__ out,
    float* __restrict__ maxout, int N)
{
    extern __shared__ float sm[];
    float* stage = sm;
    int* sidp = (int*)(sm + 128 * STAGE_STRIDE);

    const int tid = threadIdx.x;
    const int lane = tid & 31;
    const int warp = tid >> 5;
    const int row0 = blockIdx.x * 128;

    if (tid < 128) {
        int r = row0 + tid;
        sidp[tid] = g_sid[(r < N) ? r : (N - 1)];
    }

    float w[9][4], bb[4], gg[4], ee[4];
#pragma unroll
    for (int k = 0; k < 9; k++)
#pragma unroll
        for (int c = 0; c < 4; c++)
            w[k][c] = W0[k * HDIM + lane + 32 * c];
#pragma unroll
    for (int c = 0; c < 4; c++) {
        bb[c] = b0[lane + 32 * c];
        gg[c] = g0[lane + 32 * c];
        ee[c] = be0[lane + 32 * c];
    }

#pragma unroll 1
    for (int rr = 0; rr < 16; rr++) {
        int rl = warp * 16 + rr;
        int spos = row0 + rl;
        int sp = (spos < N) ? spos : (N - 1);
        int srow = g_order[sp];

        float xv = (lane < 9) ? x[(size_t)srow * 9 + lane] : 0.f;
        float z[4] = {bb[0], bb[1], bb[2], bb[3]};
#pragma unroll
        for (int k = 0; k < 9; k++) {
            float xk = __shfl_sync(0xffffffffu, xv, k);
#pragma unroll
            for (int c = 0; c < 4; c++)
                z[c] = fmaf(xk, w[k][c], z[c]);
        }
        float s  = z[0] + z[1] + z[2] + z[3];
        float s2 = z[0]*z[0] + z[1]*z[1] + z[2]*z[2] + z[3]*z[3];
#pragma unroll
        for (int o = 16; o > 0; o >>= 1) {
            s  += __shfl_xor_sync(0xffffffffu, s, o);
            s2 += __shfl_xor_sync(0xffffffffu, s2, o);
        }
        float mu  = s * (1.f / HDIM);
        float var = fmaf(s2, 1.f / HDIM, -mu * mu);
        float rs  = rsqrtf(var + LN_EPS);
#pragma unroll
        for (int c = 0; c < 4; c++)
            stage[rl * STAGE_STRIDE + lane + 32 * c] =
                fmaxf(fmaf((z[c] - mu) * rs, gg[c], ee[c]), 0.f);
    }
    __syncthreads();

    // coalesced h0 writes (fp16): 8B per lane per row
#pragma unroll 1
    for (int rr = 0; rr < 16; rr++) {
        int rl = warp * 16 + rr;
        int spos = row0 + rl;
        if (spos < N) {
            float4 v = *(const float4*)&stage[rl * STAGE_STRIDE + lane * 4];
            __half2 h0v = __floats2half2_rn(v.x, v.y);
            __half2 h1v = __floats2half2_rn(v.z, v.w);
            uint2 pk = make_uint2(*(unsigned*)&h0v, *(unsigned*)&h1v);
            *(uint2*)(out + (size_t)spos * HDIM + lane * 4) = pk;
        }
    }

    // fused segmented max: warp-per-segment
    {
        const int p_first = sidp[0];
        const int p_last  = sidp[127];
        for (int seg = p_first + warp; seg <= p_last; seg += 8) {
            int b = g_offsets[seg], e = g_offsets[seg + 1];
            int r0 = b - row0; if (r0 < 0) r0 = 0;
            int r1 = e - row0; if (r1 > 128) r1 = 128;
            if (r1 <= r0) continue;
            float4 m = make_float4(0.f, 0.f, 0.f, 0.f);
            for (int r = r0; r < r1; r++) {
                float4 vv = *(const float4*)&stage[r * STAGE_STRIDE + lane * 4];
                m.x = fmaxf(m.x, vv.x); m.y = fmaxf(m.y, vv.y);
                m.z = fmaxf(m.z, vv.z); m.w = fmaxf(m.w, vv.w);
            }
            float* dst = maxout + (size_t)seg * HDIM + lane * 4;
            bool bnd = (b < row0) || (e > row0 + 128);
            if (bnd) {
                atomicMax((int*)dst + 0, __float_as_int(m.x));
                atomicMax((int*)dst + 1, __float_as_int(m.y));
                atomicMax((int*)dst + 2, __float_as_int(m.z));
                atomicMax((int*)dst + 3, __float_as_int(m.w));
            } else {
                *(float4*)dst = m;
            }
        }
    }
}

// ---------------- mma helpers ----------------
__device__ __forceinline__ void cp_async16(void* s, const void* g) {
    unsigned sa = (unsigned)__cvta_generic_to_shared(s);
    asm volatile("cp.async.cg.shared.global [%0], [%1], 16;\n" :: "r"(sa), "l"(g));
}
__device__ __forceinline__ void cp_commit() {
    asm volatile("cp.async.commit_group;\n" ::: "memory");
}
template<int n> __device__ __forceinline__ void cp_wait() {
    asm volatile("cp.async.wait_group %0;\n" :: "n"(n) : "memory");
}
__device__ __forceinline__ void mma_tf32(float acc[4], const unsigned a[4], const unsigned b[2]) {
    asm volatile(
        "mma.sync.aligned.m16n8k8.row.col.f32.tf32.tf32.f32 "
        "{%0,%1,%2,%3},{%4,%5,%6,%7},{%8,%9},{%0,%1,%2,%3};\n"
        : "+f"(acc[0]), "+f"(acc[1]), "+f"(acc[2]), "+f"(acc[3])
        : "r"(a[0]), "r"(a[1]), "r"(a[2]), "r"(a[3]), "r"(b[0]), "r"(b[1]));
}
__device__ __forceinline__ void mma_f16(float acc[4], const unsigned a[4], const unsigned b[2]) {
    asm volatile(
        "mma.sync.aligned.m16n8k16.row.col.f32.f16.f16.f32 "
        "{%0,%1,%2,%3},{%4,%5,%6,%7},{%8,%9},{%0,%1,%2,%3};\n"
        : "+f"(acc[0]), "+f"(acc[1]), "+f"(acc[2]), "+f"(acc[3])
        : "r"(a[0]), "r"(a[1]), "r"(a[2]), "r"(a[3]), "r"(b[0]), "r"(b[1]));
}

// ---------------- aggw kernel (unchanged tf32/fp32) ----------------
#define AS_STRIDE 36
#define WS_STRIDE 136
#define AS_BUF (128 * AS_STRIDE)
#define WS_BUF (32 * WS_STRIDE)
#define AGW_SMEM_FLOATS (2*AS_BUF + 2*WS_BUF + 64)
#define AGW_SMEM_BYTES (AGW_SMEM_FLOATS * 4)

__global__ __launch_bounds__(256, 2) void aggw_kernel(
    const float* __restrict__ agg, const float* __restrict__ Wb,
    const float* __restrict__ b, float* __restrict__ aggw, int P)
{
    extern __shared__ float sm[];
    float* As  = sm;
    float* Wsm = sm + 2 * AS_BUF;

    const int tid = threadIdx.x;
    const int lane = tid & 31;
    const int quad_r = lane >> 2, quad_c = lane & 3;
    const int warp = tid >> 5;
    const int warp_m = warp >> 1, warp_n = warp & 1;
    const int row0 = blockIdx.x * 128;

    float acc[2][8][4];
#pragma unroll
    for (int nt = 0; nt < 8; nt++) {
        float2 bv = *(const float2*)&b[warp_n * 64 + nt * 8 + quad_c * 2];
#pragma unroll
        for (int mf = 0; mf < 2; mf++) {
            acc[mf][nt][0] = bv.x; acc[mf][nt][1] = bv.y;
            acc[mf][nt][2] = bv.x; acc[mf][nt][3] = bv.y;
        }
    }

    auto issue_chunk = [&](int kc, int buf) {
        float* Ab = As + buf * AS_BUF;
        float* Wc = Wsm + buf * WS_BUF;
#pragma unroll
        for (int i = 0; i < 4; i++) {
            int idx = tid + i * 256;
            int r = idx >> 3, f = idx & 7;
            int gr = row0 + r; if (gr >= P) gr = P - 1;
            cp_async16(Ab + r * AS_STRIDE + f * 4,
                       agg + (size_t)gr * HDIM + kc * 32 + f * 4);
        }
#pragma unroll
        for (int i = 0; i < 4; i++) {
            int idx = tid + i * 256;
            int k = idx >> 5, f = idx & 31;
            cp_async16(Wc + k * WS_STRIDE + f * 4,
                       Wb + (size_t)(kc * 32 + k) * HDIM + f * 4);
        }
        cp_commit();
    };

    issue_chunk(0, 0);

#pragma unroll 1
    for (int kc = 0; kc < 4; kc++) {
        if (kc < 3) { issue_chunk(kc + 1, (kc + 1) & 1); cp_wait<1>(); }
        else        { cp_wait<0>(); }
        __syncthreads();
        const float* Ab = As + (kc & 1) * AS_BUF;
        const float* Wc = Wsm + (kc & 1) * WS_BUF;
#pragma unroll
        for (int ks = 0; ks < 4; ks++) {
            const int kk = ks * 8;
            unsigned afr[2][4];
#pragma unroll
            for (int mf = 0; mf < 2; mf++) {
                const float* p = Ab + (warp_m * 32 + mf * 16 + quad_r) * AS_STRIDE
                                    + kk + quad_c;
                afr[mf][0] = __float_as_uint(p[0]);
                afr[mf][1] = __float_as_uint(p[8 * AS_STRIDE]);
                afr[mf][2] = __float_as_uint(p[4]);
                afr[mf][3] = __float_as_uint(p[8 * AS_STRIDE + 4]);
            }
            unsigned bfr[8][2];
#pragma unroll
            for (int nt = 0; nt < 8; nt++) {
                const float* p = Wc + (kk + quad_c) * WS_STRIDE
                                    + warp_n * 64 + nt * 8 + quad_r;
                bfr[nt][0] = __float_as_uint(p[0]);
                bfr[nt][1] = __float_as_uint(p[4 * WS_STRIDE]);
            }
#pragma unroll
            for (int mf = 0; mf < 2; mf++)
#pragma unroll
                for (int nt = 0; nt < 8; nt++)
                    mma_tf32(acc[mf][nt], afr[mf], bfr[nt]);
        }
        __syncthreads();
    }

#pragma unroll
    for (int nt = 0; nt < 8; nt++) {
        int col = warp_n * 64 + nt * 8 + quad_c * 2;
#pragma unroll
        for (int mf = 0; mf < 2; mf++)
#pragma unroll
            for (int h = 0; h < 2; h++) {
                int grow = row0 + warp_m * 32 + mf * 16 + h * 8 + quad_r;
                if (grow < P)
                    *(float2*)(aggw + (size_t)grow * HDIM + col) =
                        make_float2(acc[mf][nt][2 * h], acc[mf][nt][2 * h + 1]);
            }
    }
}

// ---------------- encoder 1/2: fp16 mma + fused segmented max ----------------
// A smem: fp16 [2][128][40]; W^T smem: fp16 [2][128][40] ([n][k]).
// stage fp32 [128][132] overlaps the mainloop buffers (used post-mainloop).
#define AH_STRIDE 40
#define AH_BUF (128 * AH_STRIDE)            // halves
#define ENCH_STAGE_FLOATS (128 * STAGE_STRIDE)
#define ENCH_SMEM_FLOATS (ENCH_STAGE_FLOATS + 512 + 128)
#define ENCH_SMEM_BYTES (ENCH_SMEM_FLOATS * 4)

__global__ __launch_bounds__(256, 2) void enc_kernel(
    const __half* __restrict__ hprev, const float* __restrict__ aggw,
    const __half* __restrict__ WT, const float* __restrict__ gw,
    const float* __restrict__ be, __half* __restrict__ hout,
    float* __restrict__ maxout, int N)
{
    extern __shared__ float sm[];
    __half* Ash = (__half*)sm;                       // [2][128][40]
    __half* Wsh = (__half*)sm + 2 * AH_BUF;          // [2][128][40]
    float* stage = sm;                               // reused post-mainloop
    float2* red2 = (float2*)(sm + ENCH_STAGE_FLOATS);   // 512 floats
    int*   sidp = (int*)(sm + ENCH_STAGE_FLOATS + 512); // 128 ints

    const int tid = threadIdx.x;
    const int lane = tid & 31;
    const int quad_r = lane >> 2, quad_c = lane & 3;
    const int warp = tid >> 5;
    const int warp_m = warp >> 1, warp_n = warp & 1;
    const int row0 = blockIdx.x * 128;

    if (tid < 128) {
        int r = row0 + tid;
        sidp[tid] = g_sid[(r < N) ? r : (N - 1)];
    }
    __syncthreads();

    auto issue_chunk = [&](int kc, int buf) {
        __half* Ab = Ash + buf * AH_BUF;
        __half* Wb = Wsh + buf * AH_BUF;
#pragma unroll
        for (int i = 0; i < 2; i++) {
            int idx = tid + i * 256;        // 0..511
            int r = idx >> 2, f = idx & 3;
            int gr = row0 + r; if (gr >= N) gr = N - 1;
            cp_async16(Ab + r * AH_STRIDE + f * 8,
                       hprev + (size_t)gr * HDIM + kc * 32 + f * 8);
        }
#pragma unroll
        for (int i = 0; i < 2; i++) {
            int idx = tid + i * 256;
            int n = idx >> 2, f = idx & 3;
            cp_async16(Wb + n * AH_STRIDE + f * 8,
                       WT + (size_t)n * HDIM + kc * 32 + f * 8);
        }
        cp_commit();
    };

    issue_chunk(0, 0);

    // accumulator init = aggW[sid] gather (L2-resident table)
    float acc[2][8][4];
#pragma unroll
    for (int mf = 0; mf < 2; mf++)
#pragma unroll
        for (int h = 0; h < 2; h++) {
            int rl = warp_m * 32 + mf * 16 + h * 8 + quad_r;
            const float* base = aggw + (size_t)sidp[rl] * HDIM;
#pragma unroll
            for (int nt = 0; nt < 8; nt++) {
                float2 v = *(const float2*)(base + warp_n * 64 + nt * 8 + quad_c * 2);
                acc[mf][nt][2 * h]     = v.x;
                acc[mf][nt][2 * h + 1] = v.y;
            }
        }

#pragma unroll 1
    for (int kc = 0; kc < 4; kc++) {
        if (kc < 3) { issue_chunk(kc + 1, (kc + 1) & 1); cp_wait<1>(); }
        else        { cp_wait<0>(); }
        __syncthreads();

        const __half* Ab = Ash + (kc & 1) * AH_BUF;
        const __half* Wb = Wsh + (kc & 1) * AH_BUF;
#pragma unroll
        for (int ks = 0; ks < 2; ks++) {
            const int kk = ks * 16;
            unsigned afr[2][4];
#pragma unroll
            for (int mf = 0; mf < 2; mf++) {
                const __half* p = Ab + (warp_m * 32 + mf * 16 + quad_r) * AH_STRIDE
                                     + kk + 2 * quad_c;
                afr[mf][0] = *(const unsigned*)(p);
                afr[mf][1] = *(const unsigned*)(p + 8 * AH_STRIDE);
                afr[mf][2] = *(const unsigned*)(p + 8);
                afr[mf][3] = *(const unsigned*)(p + 8 * AH_STRIDE + 8);
            }
            unsigned bfr[8][2];
#pragma unroll
            for (int nt = 0; nt < 8; nt++) {
                const __half* p = Wb + (warp_n * 64 + nt * 8 + quad_r) * AH_STRIDE
                                     + kk + 2 * quad_c;
                bfr[nt][0] = *(const unsigned*)(p);
                bfr[nt][1] = *(const unsigned*)(p + 8);
            }
#pragma unroll
            for (int mf = 0; mf < 2; mf++)
#pragma unroll
                for (int nt = 0; nt < 8; nt++)
                    mma_f16(acc[mf][nt], afr[mf], bfr[nt]);
        }
        __syncthreads();
    }

    // ---- LayerNorm statistics ----
    float s[2][2], q[2][2];
#pragma unroll
    for (int mf = 0; mf < 2; mf++)
#pragma unroll
        for (int h = 0; h < 2; h++) {
            float ss = 0.f, qq = 0.f;
#pragma unroll
            for (int nt = 0; nt < 8; nt++) {
                float z0 = acc[mf][nt][2 * h], z1 = acc[mf][nt][2 * h + 1];
                ss += z0 + z1;
                qq += z0 * z0 + z1 * z1;
            }
            s[mf][h] = ss; q[mf][h] = qq;
        }
#pragma unroll
    for (int mk = 1; mk <= 2; mk <<= 1)
#pragma unroll
        for (int mf = 0; mf < 2; mf++)
#pragma unroll
            for (int h = 0; h < 2; h++) {
                s[mf][h] += __shfl_xor_sync(0xffffffffu, s[mf][h], mk);
                q[mf][h] += __shfl_xor_sync(0xffffffffu, q[mf][h], mk);
            }
    if (quad_c == 0) {
#pragma unroll
        for (int mf = 0; mf < 2; mf++)
#pragma unroll
            for (int h = 0; h < 2; h++) {
                int rl = warp_m * 32 + mf * 16 + h * 8 + quad_r;
                red2[rl * 2 + warp_n] = make_float2(s[mf][h], q[mf][h]);
            }
    }
    __syncthreads();
    float mu[2][2], rs[2][2];
#pragma unroll
    for (int mf = 0; mf < 2; mf++)
#pragma unroll
        for (int h = 0; h < 2; h++) {
            int rl = warp_m * 32 + mf * 16 + h * 8 + quad_r;
            float2 r0 = red2[rl * 2 + 0], r1 = red2[rl * 2 + 1];
            float ss = r0.x + r1.x, qq = r0.y + r1.y;
            float m = ss * (1.f / HDIM);
            float var = fmaf(qq, 1.f / HDIM, -m * m);
            mu[mf][h] = m;
            rs[mf][h] = rsqrtf(var + LN_EPS);
        }
    __syncthreads();   // mainloop buffers free before staging

    // ---- normalize + ReLU into stage ----
#pragma unroll
    for (int nt = 0; nt < 8; nt++) {
        int col = warp_n * 64 + nt * 8 + quad_c * 2;
        float2 gv = *(const float2*)&gw[col];
        float2 ev = *(const float2*)&be[col];
#pragma unroll
        for (int mf = 0; mf < 2; mf++)
#pragma unroll
            for (int h = 0; h < 2; h++) {
                int rl = warp_m * 32 + mf * 16 + h * 8 + quad_r;
                float z0 = acc[mf][nt][2 * h], z1 = acc[mf][nt][2 * h + 1];
                float2 o;
                o.x = fmaxf(fmaf((z0 - mu[mf][h]) * rs[mf][h], gv.x, ev.x), 0.f);
                o.y = fmaxf(fmaf((z1 - mu[mf][h]) * rs[mf][h], gv.y, ev.y), 0.f);
                *(float2*)&stage[rl * STAGE_STRIDE + col] = o;
            }
    }
    __syncthreads();

    // ---- coalesced hout writes (fp16) ----
    if (hout) {
#pragma unroll 1
        for (int rr = 0; rr < 16; rr++) {
            int rl = warp * 16 + rr;
            int grow = row0 + rl;
            if (grow < N) {
                float4 v = *(const float4*)&stage[rl * STAGE_STRIDE + lane * 4];
                __half2 h0v = __floats2half2_rn(v.x, v.y);
                __half2 h1v = __floats2half2_rn(v.z, v.w);
                uint2 pk = make_uint2(*(unsigned*)&h0v, *(unsigned*)&h1v);
                *(uint2*)(hout + (size_t)grow * HDIM + lane * 4) = pk;
            }
        }
    }

    // ---- fused segmented max: warp-per-segment over the staged tile ----
    {
        const int p_first = sidp[0];
        const int p_last  = sidp[127];
        for (int seg = p_first + warp; seg <= p_last; seg += 8) {
            int b = g_offsets[seg], e = g_offsets[seg + 1];
            int r0 = b - row0; if (r0 < 0) r0 = 0;
            int r1 = e - row0; if (r1 > 128) r1 = 128;
            if (r1 <= r0) continue;
            float4 m = make_float4(0.f, 0.f, 0.f, 0.f);
            for (int r = r0; r < r1; r++) {
                float4 v = *(const float4*)&stage[r * STAGE_STRIDE + lane * 4];
                m.x = fmaxf(m.x, v.x); m.y = fmaxf(m.y, v.y);
                m.z = fmaxf(m.z, v.z); m.w = fmaxf(m.w, v.w);
            }
            float* dst = maxout + (size_t)seg * HDIM + lane * 4;
            bool bnd = (b < row0) || (e > row0 + 128);
            if (bnd) {
                atomicMax((int*)dst + 0, __float_as_int(m.x));
                atomicMax((int*)dst + 1, __float_as_int(m.y));
                atomicMax((int*)dst + 2, __float_as_int(m.z));
                atomicMax((int*)dst + 3, __float_as_int(m.w));
            } else {
                *(float4*)dst = m;
            }
        }
    }
}

// ---------------- output tail ----------------
__global__ void tail_kernel(float* out, int tail) {
    int i = blockIdx.x * blockDim.x + threadIdx.x;
    float* base = out + (size_t)PNUM * HDIM;
    if (tail == PNUM) {
        if (i < PNUM) base[i] = (float)i;
    } else if (tail == 2 * PNUM) {
        if (i < PNUM) ((long long*)base)[i] = (long long)i;
    } else {
        if (i < tail) base[i] = (float)i;
    }
}

// ---------------- launch ----------------
extern "C" void kernel_launch(void* const* d_in, const int* in_sizes, int n_in,
                              void* d_out, int out_size) {
    const float* x   = (const float*)d_in[0];
    const void*  ids = d_in[1];
    const float* W0  = (const float*)d_in[2];
    const float* b0  = (const float*)d_in[3];
    const float* g0  = (const float*)d_in[4];
    const float* be0 = (const float*)d_in[5];
    const float* W1  = (const float*)d_in[6];
    const float* b1  = (const float*)d_in[7];
    const float* g1  = (const float*)d_in[8];
    const float* be1 = (const float*)d_in[9];
    const float* W2  = (const float*)d_in[10];
    const float* b2  = (const float*)d_in[11];
    const float* g2  = (const float*)d_in[12];
    const float* be2 = (const float*)d_in[13];

    const int N = in_sizes[0] / 9;
    const int P = PNUM;
    float* out = (float*)d_out;

    __half *h0, *h1, *WT1, *WT2;
    float *agg, *agg2, *aggw;
    int* counts;
    cudaGetSymbolAddress((void**)&h0,   g_h0);
    cudaGetSymbolAddress((void**)&h1,   g_h1);
    cudaGetSymbolAddress((void**)&WT1,  g_WT1);
    cudaGetSymbolAddress((void**)&WT2,  g_WT2);
    cudaGetSymbolAddress((void**)&agg,  g_agg);
    cudaGetSymbolAddress((void**)&agg2, g_agg2);
    cudaGetSymbolAddress((void**)&aggw, g_aggw);
    cudaGetSymbolAddress((void**)&counts, g_counts);

    cudaFuncSetAttribute(enc_kernel,
        cudaFuncAttributeMaxDynamicSharedMemorySize, ENCH_SMEM_BYTES);
    cudaFuncSetAttribute(aggw_kernel,
        cudaFuncAttributeMaxDynamicSharedMemorySize, AGW_SMEM_BYTES);
    cudaFuncSetAttribute(enc0_kernel,
        cudaFuncAttributeMaxDynamicSharedMemorySize, ENC0_SMEM_BYTES);

    // 0) independent work first: W^T fp16 conversion, zero-inits, tail
    wconv_kernel<<<HDIM, HDIM>>>(W1, W2);
    cudaMemsetAsync(agg,  0, (size_t)P * HDIM * sizeof(float));
    cudaMemsetAsync(agg2, 0, (size_t)P * HDIM * sizeof(float));
    cudaMemsetAsync(out,  0, (size_t)P * HDIM * sizeof(float));
    cudaMemsetAsync(counts, 0, (size_t)P * sizeof(int));
    int tail = out_size - P * HDIM;
    if (tail > 0) {
        int elems = (tail == 2 * PNUM) ? PNUM : tail;
        tail_kernel<<<(elems + 255) / 256, 256>>>(out, tail);
    }

    // 1) CSR build
    prep_kernel<<<(N + 255) / 256, 256>>>(ids, N);
    scan1_kernel<<<SCAN_NB, 256>>>();
    scan23_kernel<<<SCAN_NB, 256>>>();
    scatter_kernel<<<(N + 255) / 256, 256>>>(N);

    // 2) enc0 -> h0 (fp16) + fused seg_max -> agg
    enc0_kernel<<<(N + 127) / 128, 256, ENC0_SMEM_BYTES>>>(
        x, W0, b0, g0, be0, h0, agg, N);

    // 3) layer 1: aggW(agg); enc1 -> h1 (fp16) + fused seg_max -> agg2
    aggw_kernel<<<(P + 127) / 128, 256, AGW_SMEM_BYTES>>>(
        agg, W1 + (size_t)HDIM * HDIM, b1, aggw, P);
    enc_kernel<<<(N + 127) / 128, 256, ENCH_SMEM_BYTES>>>(
        h0, aggw, WT1, g1, be1, h1, agg2, N);

    // 4) layer 2: aggW(agg2); enc2 (no h store) + fused seg_max -> out
    aggw_kernel<<<(P + 127) / 128, 256, AGW_SMEM_BYTES>>>(
        agg2, W2 + (size_t)HDIM * HDIM, b2, aggw, P);
    enc_kernel<<<(N + 127) / 128, 256, ENCH_SMEM_BYTES>>>(
        h1, aggw, WT2, g2, be2, nullptr, out, N);
}

// round 13
// speedup vs baseline: 1.6612x; 1.0145x over previous
#include <cuda_runtime.h>
#include <cuda_fp16.h>
#include <cstdint>

#define HDIM 128
#define NMAX 500000
#define PNUM 50000
#define LN_EPS 1e-5f
#define SCAN_NB ((PNUM + 255) / 256)   // 196

// ---------------- scratch (static __device__; no allocation) ----------------
__device__ __half g_h0[(size_t)NMAX * HDIM];
__device__ __half g_h1[(size_t)NMAX * HDIM];
__device__ __half g_WT1[HDIM * HDIM];   // W1_top^T fp16 [n][k]
__device__ __half g_WT2[HDIM * HDIM];   // W2_top^T fp16 [n][k]
__device__ __half g_WB1[HDIM * HDIM];   // W1_bot^T fp16 [n][k]
__device__ __half g_WB2[HDIM * HDIM];   // W2_bot^T fp16 [n][k]
__device__ float g_agg[(size_t)PNUM * HDIM];
__device__ float g_agg2[(size_t)PNUM * HDIM];
__device__ float g_aggw[(size_t)PNUM * HDIM];
__device__ int   g_counts[PNUM];
__device__ int   g_scantmp[PNUM];
__device__ int   g_blocksums[SCAN_NB];
__device__ int   g_offsets[PNUM + 1];
__device__ int   g_cursor[PNUM];
__device__ int   g_order[NMAX];
__device__ int   g_sid[NMAX];
__device__ int   g_ids[NMAX];

// ---------------- W^T fp16 conversion (off critical path) ----------------
__global__ void wconv_kernel(const float* __restrict__ W1t,
                             const float* __restrict__ W2t) {
    int k = blockIdx.x;      // 0..127
    int n = threadIdx.x;     // 0..127
    g_WT1[n * HDIM + k] = __float2half(W1t[(size_t)k * HDIM + n]);
    g_WT2[n * HDIM + k] = __float2half(W2t[(size_t)k * HDIM + n]);
    g_WB1[n * HDIM + k] = __float2half(W1t[(size_t)(k + HDIM) * HDIM + n]);
    g_WB2[n * HDIM + k] = __float2half(W2t[(size_t)(k + HDIM) * HDIM + n]);
}

// ---------------- prep: per-block dtype detect + convert + histogram --------
__global__ void prep_kernel(const void* idsraw, int N) {
    __shared__ int s_ok;
    const long long* a64 = (const long long*)idsraw;
    int lane_ok = 1;
    if (threadIdx.x < 16) {
        long long v = a64[threadIdx.x];
        lane_ok = (v >= 0 && v < PNUM);
    }
    if (threadIdx.x < 32) {
        unsigned m = __ballot_sync(0xffffffffu, lane_ok);
        if (threadIdx.x == 0) s_ok = ((m & 0xffffu) == 0xffffu) ? 1 : 0;
    }
    __syncthreads();
    int ids64 = s_ok;
    int i = blockIdx.x * blockDim.x + threadIdx.x;
    if (i >= N) return;
    int v = ids64 ? (int)a64[i] : ((const int*)idsraw)[i];
    g_ids[i] = v;
    atomicAdd(&g_counts[v], 1);
}

// ---------------- scan over g_counts ----------------
__device__ __forceinline__ int block_inclusive_scan_256(int v, int* wsum) {
    int lane = threadIdx.x & 31, w = threadIdx.x >> 5;
    int x = v;
#pragma unroll
    for (int o = 1; o < 32; o <<= 1) {
        int t = __shfl_up_sync(0xffffffffu, x, o);
        if (lane >= o) x += t;
    }
    if (lane == 31) wsum[w] = x;
    __syncthreads();
    if (w == 0) {
        int y = (lane < 8) ? wsum[lane] : 0;
#pragma unroll
        for (int o = 1; o < 8; o <<= 1) {
            int t = __shfl_up_sync(0xffffffffu, y, o);
            if (lane >= o) y += t;
        }
        if (lane < 8) wsum[lane] = y;
    }
    __syncthreads();
    return x + (w > 0 ? wsum[w - 1] : 0);
}

__global__ void scan1_kernel() {
    __shared__ int wsum[8];
    int i = blockIdx.x * 256 + threadIdx.x;
    int v = (i < PNUM) ? g_counts[i] : 0;
    int incl = block_inclusive_scan_256(v, wsum);
    if (i < PNUM) g_scantmp[i] = incl;
    if (threadIdx.x == 255) g_blocksums[blockIdx.x] = incl;
}

__global__ void scan23_kernel() {
    __shared__ int wsum[8];
    __shared__ int bs[256];
    int t = threadIdx.x;
    int v = (t < SCAN_NB) ? g_blocksums[t] : 0;
    int incl = block_inclusive_scan_256(v, wsum);
    bs[t] = incl;
    __syncthreads();
    int i = blockIdx.x * 256 + t;
    if (i >= PNUM) return;
    int off = (blockIdx.x > 0) ? bs[blockIdx.x - 1] : 0;
    int inclv = off + g_scantmp[i];
    int excl = inclv - g_counts[i];
    g_offsets[i] = excl;
    g_cursor[i] = excl;
    if (i == PNUM - 1) g_offsets[PNUM] = inclv;
}

__global__ void scatter_kernel(int N) {
    int i = blockIdx.x * blockDim.x + threadIdx.x;
    if (i >= N) return;
    int id = g_ids[i];
    int pos = atomicAdd(&g_cursor[id], 1);
    g_order[pos] = i;
    g_sid[pos] = id;
}

#define STAGE_STRIDE 132
#define ENC0_SMEM_FLOATS (128 * STAGE_STRIDE + 128)
#define ENC0_SMEM_BYTES (ENC0_SMEM_FLOATS * 4)

// ---------------- encoder 0 with fused segmented max -------------------------
__global__ __launch_bounds__(256, 2) void enc0_kernel(
    const float* __restrict__ x, const float* __restrict__ W0,
    const float* __restrict__ b0, const float* __restrict__ g0,
    const float* __restrict__ be0, __half* __restrict__ out,
    float* __restrict__ maxout, int N)
{
    extern __shared__ float sm[];
    float* stage = sm;
    int* sidp = (int*)(sm + 128 * STAGE_STRIDE);

    const int tid = threadIdx.x;
    const int lane = tid & 31;
    const int warp = tid >> 5;
    const int row0 = blockIdx.x * 128;

    if (tid < 128) {
        int r = row0 + tid;
        sidp[tid] = g_sid[(r < N) ? r : (N - 1)];
    }

    float w[9][4], bb[4], gg[4], ee[4];
#pragma unroll
    for (int k = 0; k < 9; k++)
#pragma unroll
        for (int c = 0; c < 4; c++)
            w[k][c] = W0[k * HDIM + lane + 32 * c];
#pragma unroll
    for (int c = 0; c < 4; c++) {
        bb[c] = b0[lane + 32 * c];
        gg[c] = g0[lane + 32 * c];
        ee[c] = be0[lane + 32 * c];
    }

#pragma unroll 1
    for (int rr = 0; rr < 16; rr++) {
        int rl = warp * 16 + rr;
        int spos = row0 + rl;
        int sp = (spos < N) ? spos : (N - 1);
        int srow = g_order[sp];

        float xv = (lane < 9) ? x[(size_t)srow * 9 + lane] : 0.f;
        float z[4] = {bb[0], bb[1], bb[2], bb[3]};
#pragma unroll
        for (int k = 0; k < 9; k++) {
            float xk = __shfl_sync(0xffffffffu, xv, k);
#pragma unroll
            for (int c = 0; c < 4; c++)
                z[c] = fmaf(xk, w[k][c], z[c]);
        }
        float s  = z[0] + z[1] + z[2] + z[3];
        float s2 = z[0]*z[0] + z[1]*z[1] + z[2]*z[2] + z[3]*z[3];
#pragma unroll
        for (int o = 16; o > 0; o >>= 1) {
            s  += __shfl_xor_sync(0xffffffffu, s, o);
            s2 += __shfl_xor_sync(0xffffffffu, s2, o);
        }
        float mu  = s * (1.f / HDIM);
        float var = fmaf(s2, 1.f / HDIM, -mu * mu);
        float rs  = rsqrtf(var + LN_EPS);
#pragma unroll
        for (int c = 0; c < 4; c++)
            stage[rl * STAGE_STRIDE + lane + 32 * c] =
                fmaxf(fmaf((z[c] - mu) * rs, gg[c], ee[c]), 0.f);
    }
    __syncthreads();

    // coalesced h0 writes (fp16)
#pragma unroll 1
    for (int rr = 0; rr < 16; rr++) {
        int rl = warp * 16 + rr;
        int spos = row0 + rl;
        if (spos < N) {
            float4 v = *(const float4*)&stage[rl * STAGE_STRIDE + lane * 4];
            __half2 h0v = __floats2half2_rn(v.x, v.y);
            __half2 h1v = __floats2half2_rn(v.z, v.w);
            uint2 pk = make_uint2(*(unsigned*)&h0v, *(unsigned*)&h1v);
            *(uint2*)(out + (size_t)spos * HDIM + lane * 4) = pk;
        }
    }

    // fused segmented max: warp-per-segment
    {
        const int p_first = sidp[0];
        const int p_last  = sidp[127];
        for (int seg = p_first + warp; seg <= p_last; seg += 8) {
            int b = g_offsets[seg], e = g_offsets[seg + 1];
            int r0 = b - row0; if (r0 < 0) r0 = 0;
            int r1 = e - row0; if (r1 > 128) r1 = 128;
            if (r1 <= r0) continue;
            float4 m = make_float4(0.f, 0.f, 0.f, 0.f);
            for (int r = r0; r < r1; r++) {
                float4 vv = *(const float4*)&stage[r * STAGE_STRIDE + lane * 4];
                m.x = fmaxf(m.x, vv.x); m.y = fmaxf(m.y, vv.y);
                m.z = fmaxf(m.z, vv.z); m.w = fmaxf(m.w, vv.w);
            }
            float* dst = maxout + (size_t)seg * HDIM + lane * 4;
            bool bnd = (b < row0) || (e > row0 + 128);
            if (bnd) {
                atomicMax((int*)dst + 0, __float_as_int(m.x));
                atomicMax((int*)dst + 1, __float_as_int(m.y));
                atomicMax((int*)dst + 2, __float_as_int(m.z));
                atomicMax((int*)dst + 3, __float_as_int(m.w));
            } else {
                *(float4*)dst = m;
            }
        }
    }
}

// ---------------- mma helpers ----------------
__device__ __forceinline__ void cp_async16(void* s, const void* g) {
    unsigned sa = (unsigned)__cvta_generic_to_shared(s);
    asm volatile("cp.async.cg.shared.global [%0], [%1], 16;\n" :: "r"(sa), "l"(g));
}
__device__ __forceinline__ void cp_commit() {
    asm volatile("cp.async.commit_group;\n" ::: "memory");
}
template<int n> __device__ __forceinline__ void cp_wait() {
    asm volatile("cp.async.wait_group %0;\n" :: "n"(n) : "memory");
}
__device__ __forceinline__ void mma_f16(float acc[4], const unsigned a[4], const unsigned b[2]) {
    asm volatile(
        "mma.sync.aligned.m16n8k16.row.col.f32.f16.f16.f32 "
        "{%0,%1,%2,%3},{%4,%5,%6,%7},{%8,%9},{%0,%1,%2,%3};\n"
        : "+f"(acc[0]), "+f"(acc[1]), "+f"(acc[2]), "+f"(acc[3])
        : "r"(a[0]), "r"(a[1]), "r"(a[2]), "r"(a[3]), "r"(b[0]), "r"(b[1]));
}

// ---------------- aggw16: aggW = bias + agg @ W_bot, fp16 MMA, K=128 resident
#define AGH_STRIDE 136                      // halves per row (128 + 8 pad)
#define AGH_BUF (128 * AGH_STRIDE)          // halves
#define AGW16_SMEM_BYTES (2 * AGH_BUF * 2)  // 69632 B

__global__ __launch_bounds__(256, 2) void aggw16_kernel(
    const float* __restrict__ agg, const __half* __restrict__ WB,
    const float* __restrict__ b, float* __restrict__ aggw, int P)
{
    extern __shared__ float sm[];
    __half* Ah = (__half*)sm;               // [128][136]
    __half* Wh = Ah + AGH_BUF;              // [128][136]

    const int tid = threadIdx.x;
    const int lane = tid & 31;
    const int quad_r = lane >> 2, quad_c = lane & 3;
    const int warp = tid >> 5;
    const int warp_m = warp >> 1, warp_n = warp & 1;
    const int row0 = blockIdx.x * 128;

    // W^T fp16 load via cp.async (128 rows x 128 halves)
#pragma unroll
    for (int i = 0; i < 8; i++) {
        int idx = tid + i * 256;            // 0..2047 (16B chunks)
        int n = idx >> 4, f = idx & 15;
        cp_async16(Wh + n * AGH_STRIDE + f * 8, WB + (size_t)n * HDIM + f * 8);
    }
    cp_commit();

    // A load: agg fp32 -> fp16 inline conversion
#pragma unroll
    for (int i = 0; i < 16; i++) {
        int idx = tid + i * 256;            // 0..4095 (float4 chunks)
        int r = idx >> 5, f = idx & 31;
        int gr = row0 + r; if (gr >= P) gr = P - 1;
        float4 v = *(const float4*)(agg + (size_t)gr * HDIM + f * 4);
        __half2 p0 = __floats2half2_rn(v.x, v.y);
        __half2 p1 = __floats2half2_rn(v.z, v.w);
        uint2 pk = make_uint2(*(unsigned*)&p0, *(unsigned*)&p1);
        *(uint2*)(Ah + r * AGH_STRIDE + f * 4) = pk;
    }

    // bias init
    float acc[2][8][4];
#pragma unroll
    for (int nt = 0; nt < 8; nt++) {
        float2 bv = *(const float2*)&b[warp_n * 64 + nt * 8 + quad_c * 2];
#pragma unroll
        for (int mf = 0; mf < 2; mf++) {
            acc[mf][nt][0] = bv.x; acc[mf][nt][1] = bv.y;
            acc[mf][nt][2] = bv.x; acc[mf][nt][3] = bv.y;
        }
    }

    cp_wait<0>();
    __syncthreads();

#pragma unroll 1
    for (int ks = 0; ks < 8; ks++) {
        const int kk = ks * 16;
        unsigned afr[2][4];
#pragma unroll
        for (int mf = 0; mf < 2; mf++) {
            const __half* p = Ah + (warp_m * 32 + mf * 16 + quad_r) * AGH_STRIDE
                                 + kk + 2 * quad_c;
            afr[mf][0] = *(const unsigned*)(p);
            afr[mf][1] = *(const unsigned*)(p + 8 * AGH_STRIDE);
            afr[mf][2] = *(const unsigned*)(p + 8);
            afr[mf][3] = *(const unsigned*)(p + 8 * AGH_STRIDE + 8);
        }
        unsigned bfr[8][2];
#pragma unroll
        for (int nt = 0; nt < 8; nt++) {
            const __half* p = Wh + (warp_n * 64 + nt * 8 + quad_r) * AGH_STRIDE
                                 + kk + 2 * quad_c;
            bfr[nt][0] = *(const unsigned*)(p);
            bfr[nt][1] = *(const unsigned*)(p + 8);
        }
#pragma unroll
        for (int mf = 0; mf < 2; mf++)
#pragma unroll
            for (int nt = 0; nt < 8; nt++)
                mma_f16(acc[mf][nt], afr[mf], bfr[nt]);
    }

#pragma unroll
    for (int nt = 0; nt < 8; nt++) {
        int col = warp_n * 64 + nt * 8 + quad_c * 2;
#pragma unroll
        for (int mf = 0; mf < 2; mf++)
#pragma unroll
            for (int h = 0; h < 2; h++) {
                int grow = row0 + warp_m * 32 + mf * 16 + h * 8 + quad_r;
                if (grow < P)
                    *(float2*)(aggw + (size_t)grow * HDIM + col) =
                        make_float2(acc[mf][nt][2 * h], acc[mf][nt][2 * h + 1]);
            }
    }
}

// ---------------- encoder 1/2: fp16 mma + fused segmented max ----------------
#define AH_STRIDE 40
#define AH_BUF (128 * AH_STRIDE)
#define ENCH_STAGE_FLOATS (128 * STAGE_STRIDE)
#define ENCH_SMEM_FLOATS (ENCH_STAGE_FLOATS + 512 + 128)
#define ENCH_SMEM_BYTES (ENCH_SMEM_FLOATS * 4)

__global__ __launch_bounds__(256, 2) void enc_kernel(
    const __half* __restrict__ hprev, const float* __restrict__ aggw,
    const __half* __restrict__ WT, const float* __restrict__ gw,
    const float* __restrict__ be, __half* __restrict__ hout,
    float* __restrict__ maxout, int N)
{
    extern __shared__ float sm[];
    __half* Ash = (__half*)sm;
    __half* Wsh = (__half*)sm + 2 * AH_BUF;
    float* stage = sm;
    float2* red2 = (float2*)(sm + ENCH_STAGE_FLOATS);
    int*   sidp = (int*)(sm + ENCH_STAGE_FLOATS + 512);

    const int tid = threadIdx.x;
    const int lane = tid & 31;
    const int quad_r = lane >> 2, quad_c = lane & 3;
    const int warp = tid >> 5;
    const int warp_m = warp >> 1, warp_n = warp & 1;
    const int row0 = blockIdx.x * 128;

    if (tid < 128) {
        int r = row0 + tid;
        sidp[tid] = g_sid[(r < N) ? r : (N - 1)];
    }
    __syncthreads();

    auto issue_chunk = [&](int kc, int buf) {
        __half* Ab = Ash + buf * AH_BUF;
        __half* Wb = Wsh + buf * AH_BUF;
#pragma unroll
        for (int i = 0; i < 2; i++) {
            int idx = tid + i * 256;
            int r = idx >> 2, f = idx & 3;
            int gr = row0 + r; if (gr >= N) gr = N - 1;
            cp_async16(Ab + r * AH_STRIDE + f * 8,
                       hprev + (size_t)gr * HDIM + kc * 32 + f * 8);
        }
#pragma unroll
        for (int i = 0; i < 2; i++) {
            int idx = tid + i * 256;
            int n = idx >> 2, f = idx & 3;
            cp_async16(Wb + n * AH_STRIDE + f * 8,
                       WT + (size_t)n * HDIM + kc * 32 + f * 8);
        }
        cp_commit();
    };

    issue_chunk(0, 0);

    float acc[2][8][4];
#pragma unroll
    for (int mf = 0; mf < 2; mf++)
#pragma unroll
        for (int h = 0; h < 2; h++) {
            int rl = warp_m * 32 + mf * 16 + h * 8 + quad_r;
            const float* base = aggw + (size_t)sidp[rl] * HDIM;
#pragma unroll
            for (int nt = 0; nt < 8; nt++) {
                float2 v = *(const float2*)(base + warp_n * 64 + nt * 8 + quad_c * 2);
                acc[mf][nt][2 * h]     = v.x;
                acc[mf][nt][2 * h + 1] = v.y;
            }
        }

#pragma unroll 1
    for (int kc = 0; kc < 4; kc++) {
        if (kc < 3) { issue_chunk(kc + 1, (kc + 1) & 1); cp_wait<1>(); }
        else        { cp_wait<0>(); }
        __syncthreads();

        const __half* Ab = Ash + (kc & 1) * AH_BUF;
        const __half* Wb = Wsh + (kc & 1) * AH_BUF;
#pragma unroll
        for (int ks = 0; ks < 2; ks++) {
            const int kk = ks * 16;
            unsigned afr[2][4];
#pragma unroll
            for (int mf = 0; mf < 2; mf++) {
                const __half* p = Ab + (warp_m * 32 + mf * 16 + quad_r) * AH_STRIDE
                                     + kk + 2 * quad_c;
                afr[mf][0] = *(const unsigned*)(p);
                afr[mf][1] = *(const unsigned*)(p + 8 * AH_STRIDE);
                afr[mf][2] = *(const unsigned*)(p + 8);
                afr[mf][3] = *(const unsigned*)(p + 8 * AH_STRIDE + 8);
            }
            unsigned bfr[8][2];
#pragma unroll
            for (int nt = 0; nt < 8; nt++) {
                const __half* p = Wb + (warp_n * 64 + nt * 8 + quad_r) * AH_STRIDE
                                     + kk + 2 * quad_c;
                bfr[nt][0] = *(const unsigned*)(p);
                bfr[nt][1] = *(const unsigned*)(p + 8);
            }
#pragma unroll
            for (int mf = 0; mf < 2; mf++)
#pragma unroll
                for (int nt = 0; nt < 8; nt++)
                    mma_f16(acc[mf][nt], afr[mf], bfr[nt]);
        }
        __syncthreads();
    }

    // ---- LayerNorm statistics ----
    float s[2][2], q[2][2];
#pragma unroll
    for (int mf = 0; mf < 2; mf++)
#pragma unroll
        for (int h = 0; h < 2; h++) {
            float ss = 0.f, qq = 0.f;
#pragma unroll
            for (int nt = 0; nt < 8; nt++) {
                float z0 = acc[mf][nt][2 * h], z1 = acc[mf][nt][2 * h + 1];
                ss += z0 + z1;
                qq += z0 * z0 + z1 * z1;
            }
            s[mf][h] = ss; q[mf][h] = qq;
        }
#pragma unroll
    for (int mk = 1; mk <= 2; mk <<= 1)
#pragma unroll
        for (int mf = 0; mf < 2; mf++)
#pragma unroll
            for (int h = 0; h < 2; h++) {
                s[mf][h] += __shfl_xor_sync(0xffffffffu, s[mf][h], mk);
                q[mf][h] += __shfl_xor_sync(0xffffffffu, q[mf][h], mk);
            }
    if (quad_c == 0) {
#pragma unroll
        for (int mf = 0; mf < 2; mf++)
#pragma unroll
            for (int h = 0; h < 2; h++) {
                int rl = warp_m * 32 + mf * 16 + h * 8 + quad_r;
                red2[rl * 2 + warp_n] = make_float2(s[mf][h], q[mf][h]);
            }
    }
    __syncthreads();
    float mu[2][2], rs[2][2];
#pragma unroll
    for (int mf = 0; mf < 2; mf++)
#pragma unroll
        for (int h = 0; h < 2; h++) {
            int rl = warp_m * 32 + mf * 16 + h * 8 + quad_r;
            float2 r0 = red2[rl * 2 + 0], r1 = red2[rl * 2 + 1];
            float ss = r0.x + r1.x, qq = r0.y + r1.y;
            float m = ss * (1.f / HDIM);
            float var = fmaf(qq, 1.f / HDIM, -m * m);
            mu[mf][h] = m;
            rs[mf][h] = rsqrtf(var + LN_EPS);
        }
    __syncthreads();

    // ---- normalize + ReLU into stage ----
#pragma unroll
    for (int nt = 0; nt < 8; nt++) {
        int col = warp_n * 64 + nt * 8 + quad_c * 2;
        float2 gv = *(const float2*)&gw[col];
        float2 ev = *(const float2*)&be[col];
#pragma unroll
        for (int mf = 0; mf < 2; mf++)
#pragma unroll
            for (int h = 0; h < 2; h++) {
                int rl = warp_m * 32 + mf * 16 + h * 8 + quad_r;
                float z0 = acc[mf][nt][2 * h], z1 = acc[mf][nt][2 * h + 1];
                float2 o;
                o.x = fmaxf(fmaf((z0 - mu[mf][h]) * rs[mf][h], gv.x, ev.x), 0.f);
                o.y = fmaxf(fmaf((z1 - mu[mf][h]) * rs[mf][h], gv.y, ev.y), 0.f);
                *(float2*)&stage[rl * STAGE_STRIDE + col] = o;
            }
    }
    __syncthreads();

    // ---- coalesced hout writes (fp16) ----
    if (hout) {
#pragma unroll 1
        for (int rr = 0; rr < 16; rr++) {
            int rl = warp * 16 + rr;
            int grow = row0 + rl;
            if (grow < N) {
                float4 v = *(const float4*)&stage[rl * STAGE_STRIDE + lane * 4];
                __half2 h0v = __floats2half2_rn(v.x, v.y);
                __half2 h1v = __floats2half2_rn(v.z, v.w);
                uint2 pk = make_uint2(*(unsigned*)&h0v, *(unsigned*)&h1v);
                *(uint2*)(hout + (size_t)grow * HDIM + lane * 4) = pk;
            }
        }
    }

    // ---- fused segmented max ----
    {
        const int p_first = sidp[0];
        const int p_last  = sidp[127];
        for (int seg = p_first + warp; seg <= p_last; seg += 8) {
            int b = g_offsets[seg], e = g_offsets[seg + 1];
            int r0 = b - row0; if (r0 < 0) r0 = 0;
            int r1 = e - row0; if (r1 > 128) r1 = 128;
            if (r1 <= r0) continue;
            float4 m = make_float4(0.f, 0.f, 0.f, 0.f);
            for (int r = r0; r < r1; r++) {
                float4 v = *(const float4*)&stage[r * STAGE_STRIDE + lane * 4];
                m.x = fmaxf(m.x, v.x); m.y = fmaxf(m.y, v.y);
                m.z = fmaxf(m.z, v.z); m.w = fmaxf(m.w, v.w);
            }
            float* dst = maxout + (size_t)seg * HDIM + lane * 4;
            bool bnd = (b < row0) || (e > row0 + 128);
            if (bnd) {
                atomicMax((int*)dst + 0, __float_as_int(m.x));
                atomicMax((int*)dst + 1, __float_as_int(m.y));
                atomicMax((int*)dst + 2, __float_as_int(m.z));
                atomicMax((int*)dst + 3, __float_as_int(m.w));
            } else {
                *(float4*)dst = m;
            }
        }
    }
}

// ---------------- output tail ----------------
__global__ void tail_kernel(float* out, int tail) {
    int i = blockIdx.x * blockDim.x + threadIdx.x;
    float* base = out + (size_t)PNUM * HDIM;
    if (tail == PNUM) {
        if (i < PNUM) base[i] = (float)i;
    } else if (tail == 2 * PNUM) {
        if (i < PNUM) ((long long*)base)[i] = (long long)i;
    } else {
        if (i < tail) base[i] = (float)i;
    }
}

// ---------------- launch ----------------
extern "C" void kernel_launch(void* const* d_in, const int* in_sizes, int n_in,
                              void* d_out, int out_size) {
    const float* x   = (const float*)d_in[0];
    const void*  ids = d_in[1];
    const float* W0  = (const float*)d_in[2];
    const float* b0  = (const float*)d_in[3];
    const float* g0  = (const float*)d_in[4];
    const float* be0 = (const float*)d_in[5];
    const float* W1  = (const float*)d_in[6];
    const float* b1  = (const float*)d_in[7];
    const float* g1  = (const float*)d_in[8];
    const float* be1 = (const float*)d_in[9];
    const float* W2  = (const float*)d_in[10];
    const float* b2  = (const float*)d_in[11];
    const float* g2  = (const float*)d_in[12];
    const float* be2 = (const float*)d_in[13];

    const int N = in_sizes[0] / 9;
    const int P = PNUM;
    float* out = (float*)d_out;

    __half *h0, *h1, *WT1, *WT2, *WB1, *WB2;
    float *agg, *agg2, *aggw;
    int* counts;
    cudaGetSymbolAddress((void**)&h0,   g_h0);
    cudaGetSymbolAddress((void**)&h1,   g_h1);
    cudaGetSymbolAddress((void**)&WT1,  g_WT1);
    cudaGetSymbolAddress((void**)&WT2,  g_WT2);
    cudaGetSymbolAddress((void**)&WB1,  g_WB1);
    cudaGetSymbolAddress((void**)&WB2,  g_WB2);
    cudaGetSymbolAddress((void**)&agg,  g_agg);
    cudaGetSymbolAddress((void**)&agg2, g_agg2);
    cudaGetSymbolAddress((void**)&aggw, g_aggw);
    cudaGetSymbolAddress((void**)&counts, g_counts);

    cudaFuncSetAttribute(enc_kernel,
        cudaFuncAttributeMaxDynamicSharedMemorySize, ENCH_SMEM_BYTES);
    cudaFuncSetAttribute(aggw16_kernel,
        cudaFuncAttributeMaxDynamicSharedMemorySize, AGW16_SMEM_BYTES);
    cudaFuncSetAttribute(enc0_kernel,
        cudaFuncAttributeMaxDynamicSharedMemorySize, ENC0_SMEM_BYTES);

    // 0) independent work first: W^T fp16 conversion, zero-inits, tail
    wconv_kernel<<<HDIM, HDIM>>>(W1, W2);
    cudaMemsetAsync(agg,  0, (size_t)P * HDIM * sizeof(float));
    cudaMemsetAsync(agg2, 0, (size_t)P * HDIM * sizeof(float));
    cudaMemsetAsync(out,  0, (size_t)P * HDIM * sizeof(float));
    cudaMemsetAsync(counts, 0, (size_t)P * sizeof(int));
    int tail = out_size - P * HDIM;
    if (tail > 0) {
        int elems = (tail == 2 * PNUM) ? PNUM : tail;
        tail_kernel<<<(elems + 255) / 256, 256>>>(out, tail);
    }

    // 1) CSR build
    prep_kernel<<<(N + 255) / 256, 256>>>(ids, N);
    scan1_kernel<<<SCAN_NB, 256>>>();
    scan23_kernel<<<SCAN_NB, 256>>>();
    scatter_kernel<<<(N + 255) / 256, 256>>>(N);

    // 2) enc0 -> h0 (fp16) + fused seg_max -> agg
    enc0_kernel<<<(N + 127) / 128, 256, ENC0_SMEM_BYTES>>>(
        x, W0, b0, g0, be0, h0, agg, N);

    // 3) layer 1: aggW(agg) fp16; enc1 -> h1 (fp16) + fused seg_max -> agg2
    aggw16_kernel<<<(P + 127) / 128, 256, AGW16_SMEM_BYTES>>>(
        agg, WB1, b1, aggw, P);
    enc_kernel<<<(N + 127) / 128, 256, ENCH_SMEM_BYTES>>>(
        h0, aggw, WT1, g1, be1, h1, agg2, N);

    // 4) layer 2: aggW(agg2) fp16; enc2 (no h store) + fused seg_max -> out
    aggw16_kernel<<<(P + 127) / 128, 256, AGW16_SMEM_BYTES>>>(
        agg2, WB2, b2, aggw, P);
    enc_kernel<<<(N + 127) / 128, 256, ENCH_SMEM_BYTES>>>(
        h1, aggw, WT2, g2, be2, nullptr, out, N);
}

// round 14
// speedup vs baseline: 1.7361x; 1.0451x over previous
#include <cuda_runtime.h>
#include <cuda_fp16.h>
#include <cstdint>

#define HDIM 128
#define NMAX 500000
#define PNUM 50000
#define LN_EPS 1e-5f
#define SCAN_NB ((PNUM + 255) / 256)   // 196

// ---------------- scratch (static __device__; no allocation) ----------------
__device__ __half g_h0[(size_t)NMAX * HDIM];
__device__ __half g_h1[(size_t)NMAX * HDIM];
__device__ __half g_WT1[HDIM * HDIM];   // W1_top^T fp16 [n][k]
__device__ __half g_WT2[HDIM * HDIM];   // W2_top^T fp16 [n][k]
__device__ __half g_WB1[HDIM * HDIM];   // W1_bot^T fp16 [n][k]
__device__ __half g_WB2[HDIM * HDIM];   // W2_bot^T fp16 [n][k]
__device__ float g_agg[(size_t)PNUM * HDIM];
__device__ float g_agg2[(size_t)PNUM * HDIM];
__device__ __half g_aggw[(size_t)PNUM * HDIM];   // fp16 table
__device__ int   g_counts[PNUM];
__device__ int   g_scantmp[PNUM];
__device__ int   g_blocksums[SCAN_NB];
__device__ int   g_offsets[PNUM + 1];
__device__ int   g_cursor[PNUM];
__device__ int   g_order[NMAX];
__device__ int   g_sid[NMAX];
__device__ int   g_ids[NMAX];

// ---------------- W^T fp16 conversion (off critical path) ----------------
__global__ void wconv_kernel(const float* __restrict__ W1t,
                             const float* __restrict__ W2t) {
    int k = blockIdx.x;      // 0..127
    int n = threadIdx.x;     // 0..127
    g_WT1[n * HDIM + k] = __float2half(W1t[(size_t)k * HDIM + n]);
    g_WT2[n * HDIM + k] = __float2half(W2t[(size_t)k * HDIM + n]);
    g_WB1[n * HDIM + k] = __float2half(W1t[(size_t)(k + HDIM) * HDIM + n]);
    g_WB2[n * HDIM + k] = __float2half(W2t[(size_t)(k + HDIM) * HDIM + n]);
}

// ---------------- prep: per-block dtype detect + convert + histogram --------
__global__ void prep_kernel(const void* idsraw, int N) {
    __shared__ int s_ok;
    const long long* a64 = (const long long*)idsraw;
    int lane_ok = 1;
    if (threadIdx.x < 16) {
        long long v = a64[threadIdx.x];
        lane_ok = (v >= 0 && v < PNUM);
    }
    if (threadIdx.x < 32) {
        unsigned m = __ballot_sync(0xffffffffu, lane_ok);
        if (threadIdx.x == 0) s_ok = ((m & 0xffffu) == 0xffffu) ? 1 : 0;
    }
    __syncthreads();
    int ids64 = s_ok;
    int i = blockIdx.x * blockDim.x + threadIdx.x;
    if (i >= N) return;
    int v = ids64 ? (int)a64[i] : ((const int*)idsraw)[i];
    g_ids[i] = v;
    atomicAdd(&g_counts[v], 1);
}

// ---------------- scan over g_counts ----------------
__device__ __forceinline__ int block_inclusive_scan_256(int v, int* wsum) {
    int lane = threadIdx.x & 31, w = threadIdx.x >> 5;
    int x = v;
#pragma unroll
    for (int o = 1; o < 32; o <<= 1) {
        int t = __shfl_up_sync(0xffffffffu, x, o);
        if (lane >= o) x += t;
    }
    if (lane == 31) wsum[w] = x;
    __syncthreads();
    if (w == 0) {
        int y = (lane < 8) ? wsum[lane] : 0;
#pragma unroll
        for (int o = 1; o < 8; o <<= 1) {
            int t = __shfl_up_sync(0xffffffffu, y, o);
            if (lane >= o) y += t;
        }
        if (lane < 8) wsum[lane] = y;
    }
    __syncthreads();
    return x + (w > 0 ? wsum[w - 1] : 0);
}

__global__ void scan1_kernel() {
    __shared__ int wsum[8];
    int i = blockIdx.x * 256 + threadIdx.x;
    int v = (i < PNUM) ? g_counts[i] : 0;
    int incl = block_inclusive_scan_256(v, wsum);
    if (i < PNUM) g_scantmp[i] = incl;
    if (threadIdx.x == 255) g_blocksums[blockIdx.x] = incl;
}

__global__ void scan23_kernel() {
    __shared__ int wsum[8];
    __shared__ int bs[256];
    int t = threadIdx.x;
    int v = (t < SCAN_NB) ? g_blocksums[t] : 0;
    int incl = block_inclusive_scan_256(v, wsum);
    bs[t] = incl;
    __syncthreads();
    int i = blockIdx.x * 256 + t;
    if (i >= PNUM) return;
    int off = (blockIdx.x > 0) ? bs[blockIdx.x - 1] : 0;
    int inclv = off + g_scantmp[i];
    int excl = inclv - g_counts[i];
    g_offsets[i] = excl;
    g_cursor[i] = excl;
    if (i == PNUM - 1) g_offsets[PNUM] = inclv;
}

__global__ void scatter_kernel(int N) {
    int i = blockIdx.x * blockDim.x + threadIdx.x;
    if (i >= N) return;
    int id = g_ids[i];
    int pos = atomicAdd(&g_cursor[id], 1);
    g_order[pos] = i;
    g_sid[pos] = id;
}

#define STAGE_STRIDE 132
#define ENC0_SMEM_FLOATS (128 * STAGE_STRIDE + 128)
#define ENC0_SMEM_BYTES (ENC0_SMEM_FLOATS * 4)

// ---------------- encoder 0 with fused segmented max -------------------------
__global__ __launch_bounds__(256, 2) void enc0_kernel(
    const float* __restrict__ x, const float* __restrict__ W0,
    const float* __restrict__ b0, const float* __restrict__ g0,
    const float* __restrict__ be0, __half* __restrict__ out,
    float* __restrict__ maxout, int N)
{
    extern __shared__ float sm[];
    float* stage = sm;
    int* sidp = (int*)(sm + 128 * STAGE_STRIDE);

    const int tid = threadIdx.x;
    const int lane = tid & 31;
    const int warp = tid >> 5;
    const int row0 = blockIdx.x * 128;

    if (tid < 128) {
        int r = row0 + tid;
        sidp[tid] = g_sid[(r < N) ? r : (N - 1)];
    }

    float w[9][4], bb[4], gg[4], ee[4];
#pragma unroll
    for (int k = 0; k < 9; k++)
#pragma unroll
        for (int c = 0; c < 4; c++)
            w[k][c] = W0[k * HDIM + lane + 32 * c];
#pragma unroll
    for (int c = 0; c < 4; c++) {
        bb[c] = b0[lane + 32 * c];
        gg[c] = g0[lane + 32 * c];
        ee[c] = be0[lane + 32 * c];
    }

#pragma unroll 1
    for (int rr = 0; rr < 16; rr++) {
        int rl = warp * 16 + rr;
        int spos = row0 + rl;
        int sp = (spos < N) ? spos : (N - 1);
        int srow = g_order[sp];

        float xv = (lane < 9) ? x[(size_t)srow * 9 + lane] : 0.f;
        float z[4] = {bb[0], bb[1], bb[2], bb[3]};
#pragma unroll
        for (int k = 0; k < 9; k++) {
            float xk = __shfl_sync(0xffffffffu, xv, k);
#pragma unroll
            for (int c = 0; c < 4; c++)
                z[c] = fmaf(xk, w[k][c], z[c]);
        }
        float s  = z[0] + z[1] + z[2] + z[3];
        float s2 = z[0]*z[0] + z[1]*z[1] + z[2]*z[2] + z[3]*z[3];
#pragma unroll
        for (int o = 16; o > 0; o >>= 1) {
            s  += __shfl_xor_sync(0xffffffffu, s, o);
            s2 += __shfl_xor_sync(0xffffffffu, s2, o);
        }
        float mu  = s * (1.f / HDIM);
        float var = fmaf(s2, 1.f / HDIM, -mu * mu);
        float rs  = rsqrtf(var + LN_EPS);
#pragma unroll
        for (int c = 0; c < 4; c++)
            stage[rl * STAGE_STRIDE + lane + 32 * c] =
                fmaxf(fmaf((z[c] - mu) * rs, gg[c], ee[c]), 0.f);
    }
    __syncthreads();

    // coalesced h0 writes (fp16)
#pragma unroll 1
    for (int rr = 0; rr < 16; rr++) {
        int rl = warp * 16 + rr;
        int spos = row0 + rl;
        if (spos < N) {
            float4 v = *(const float4*)&stage[rl * STAGE_STRIDE + lane * 4];
            __half2 h0v = __floats2half2_rn(v.x, v.y);
            __half2 h1v = __floats2half2_rn(v.z, v.w);
            uint2 pk = make_uint2(*(unsigned*)&h0v, *(unsigned*)&h1v);
            *(uint2*)(out + (size_t)spos * HDIM + lane * 4) = pk;
        }
    }

    // fused segmented max: warp-per-segment
    {
        const int p_first = sidp[0];
        const int p_last  = sidp[127];
        for (int seg = p_first + warp; seg <= p_last; seg += 8) {
            int b = g_offsets[seg], e = g_offsets[seg + 1];
            int r0 = b - row0; if (r0 < 0) r0 = 0;
            int r1 = e - row0; if (r1 > 128) r1 = 128;
            if (r1 <= r0) continue;
            float4 m = make_float4(0.f, 0.f, 0.f, 0.f);
            for (int r = r0; r < r1; r++) {
                float4 vv = *(const float4*)&stage[r * STAGE_STRIDE + lane * 4];
                m.x = fmaxf(m.x, vv.x); m.y = fmaxf(m.y, vv.y);
                m.z = fmaxf(m.z, vv.z); m.w = fmaxf(m.w, vv.w);
            }
            float* dst = maxout + (size_t)seg * HDIM + lane * 4;
            bool bnd = (b < row0) || (e > row0 + 128);
            if (bnd) {
                atomicMax((int*)dst + 0, __float_as_int(m.x));
                atomicMax((int*)dst + 1, __float_as_int(m.y));
                atomicMax((int*)dst + 2, __float_as_int(m.z));
                atomicMax((int*)dst + 3, __float_as_int(m.w));
            } else {
                *(float4*)dst = m;
            }
        }
    }
}

// ---------------- mma helpers ----------------
__device__ __forceinline__ void cp_async16(void* s, const void* g) {
    unsigned sa = (unsigned)__cvta_generic_to_shared(s);
    asm volatile("cp.async.cg.shared.global [%0], [%1], 16;\n" :: "r"(sa), "l"(g));
}
__device__ __forceinline__ void cp_commit() {
    asm volatile("cp.async.commit_group;\n" ::: "memory");
}
template<int n> __device__ __forceinline__ void cp_wait() {
    asm volatile("cp.async.wait_group %0;\n" :: "n"(n) : "memory");
}
__device__ __forceinline__ void mma_f16(float acc[4], const unsigned a[4], const unsigned b[2]) {
    asm volatile(
        "mma.sync.aligned.m16n8k16.row.col.f32.f16.f16.f32 "
        "{%0,%1,%2,%3},{%4,%5,%6,%7},{%8,%9},{%0,%1,%2,%3};\n"
        : "+f"(acc[0]), "+f"(acc[1]), "+f"(acc[2]), "+f"(acc[3])
        : "r"(a[0]), "r"(a[1]), "r"(a[2]), "r"(a[3]), "r"(b[0]), "r"(b[1]));
}

// ---------------- aggw16: aggW = bias + agg @ W_bot, fp16 MMA, fp16 output ---
#define AGH_STRIDE 136
#define AGH_BUF (128 * AGH_STRIDE)
#define AGW16_SMEM_BYTES (2 * AGH_BUF * 2)

__global__ __launch_bounds__(256, 2) void aggw16_kernel(
    const float* __restrict__ agg, const __half* __restrict__ WB,
    const float* __restrict__ b, __half* __restrict__ aggw, int P)
{
    extern __shared__ float sm[];
    __half* Ah = (__half*)sm;
    __half* Wh = Ah + AGH_BUF;

    const int tid = threadIdx.x;
    const int lane = tid & 31;
    const int quad_r = lane >> 2, quad_c = lane & 3;
    const int warp = tid >> 5;
    const int warp_m = warp >> 1, warp_n = warp & 1;
    const int row0 = blockIdx.x * 128;

#pragma unroll
    for (int i = 0; i < 8; i++) {
        int idx = tid + i * 256;
        int n = idx >> 4, f = idx & 15;
        cp_async16(Wh + n * AGH_STRIDE + f * 8, WB + (size_t)n * HDIM + f * 8);
    }
    cp_commit();

#pragma unroll
    for (int i = 0; i < 16; i++) {
        int idx = tid + i * 256;
        int r = idx >> 5, f = idx & 31;
        int gr = row0 + r; if (gr >= P) gr = P - 1;
        float4 v = *(const float4*)(agg + (size_t)gr * HDIM + f * 4);
        __half2 p0 = __floats2half2_rn(v.x, v.y);
        __half2 p1 = __floats2half2_rn(v.z, v.w);
        uint2 pk = make_uint2(*(unsigned*)&p0, *(unsigned*)&p1);
        *(uint2*)(Ah + r * AGH_STRIDE + f * 4) = pk;
    }

    float acc[2][8][4];
#pragma unroll
    for (int nt = 0; nt < 8; nt++) {
        float2 bv = *(const float2*)&b[warp_n * 64 + nt * 8 + quad_c * 2];
#pragma unroll
        for (int mf = 0; mf < 2; mf++) {
            acc[mf][nt][0] = bv.x; acc[mf][nt][1] = bv.y;
            acc[mf][nt][2] = bv.x; acc[mf][nt][3] = bv.y;
        }
    }

    cp_wait<0>();
    __syncthreads();

#pragma unroll 1
    for (int ks = 0; ks < 8; ks++) {
        const int kk = ks * 16;
        unsigned afr[2][4];
#pragma unroll
        for (int mf = 0; mf < 2; mf++) {
            const __half* p = Ah + (warp_m * 32 + mf * 16 + quad_r) * AGH_STRIDE
                                 + kk + 2 * quad_c;
            afr[mf][0] = *(const unsigned*)(p);
            afr[mf][1] = *(const unsigned*)(p + 8 * AGH_STRIDE);
            afr[mf][2] = *(const unsigned*)(p + 8);
            afr[mf][3] = *(const unsigned*)(p + 8 * AGH_STRIDE + 8);
        }
        unsigned bfr[8][2];
#pragma unroll
        for (int nt = 0; nt < 8; nt++) {
            const __half* p = Wh + (warp_n * 64 + nt * 8 + quad_r) * AGH_STRIDE
                                 + kk + 2 * quad_c;
            bfr[nt][0] = *(const unsigned*)(p);
            bfr[nt][1] = *(const unsigned*)(p + 8);
        }
#pragma unroll
        for (int mf = 0; mf < 2; mf++)
#pragma unroll
            for (int nt = 0; nt < 8; nt++)
                mma_f16(acc[mf][nt], afr[mf], bfr[nt]);
    }

#pragma unroll
    for (int nt = 0; nt < 8; nt++) {
        int col = warp_n * 64 + nt * 8 + quad_c * 2;
#pragma unroll
        for (int mf = 0; mf < 2; mf++)
#pragma unroll
            for (int h = 0; h < 2; h++) {
                int grow = row0 + warp_m * 32 + mf * 16 + h * 8 + quad_r;
                if (grow < P) {
                    __half2 hv = __floats2half2_rn(acc[mf][nt][2 * h],
                                                   acc[mf][nt][2 * h + 1]);
                    *(unsigned*)(aggw + (size_t)grow * HDIM + col) =
                        *(unsigned*)&hv;
                }
            }
    }
}

// ---------------- encoder 1/2: single-shot K=128 fp16 mma + fused segmax -----
// smem layout (bytes): Ah [128][136]h @0 (34816), Wh @34816 (34816);
// stage fp32 [128][132] @0 overlaps A/W post-mainloop;
// red2 @69632 (2048), sidp @71680 (512). Total 72192.
#define EH_STRIDE 136
#define EH_BUF (128 * EH_STRIDE)
#define ENCH_SMEM_BYTES 72192

__global__ __launch_bounds__(256, 2) void enc_kernel(
    const __half* __restrict__ hprev, const __half* __restrict__ aggw,
    const __half* __restrict__ WT, const float* __restrict__ gw,
    const float* __restrict__ be, __half* __restrict__ hout,
    float* __restrict__ maxout, int N)
{
    extern __shared__ char smraw[];
    __half* Ah = (__half*)smraw;
    __half* Wh = Ah + EH_BUF;
    float* stage = (float*)smraw;
    float2* red2 = (float2*)(smraw + 69632);
    int*   sidp = (int*)(smraw + 71680);

    const int tid = threadIdx.x;
    const int lane = tid & 31;
    const int quad_r = lane >> 2, quad_c = lane & 3;
    const int warp = tid >> 5;
    const int warp_m = warp >> 1, warp_n = warp & 1;
    const int row0 = blockIdx.x * 128;

    if (tid < 128) {
        int r = row0 + tid;
        sidp[tid] = g_sid[(r < N) ? r : (N - 1)];
    }

    // single-shot A + W^T load (8 + 8 cp.async per thread)
#pragma unroll
    for (int i = 0; i < 8; i++) {
        int idx = tid + i * 256;
        int r = idx >> 4, f = idx & 15;
        int gr = row0 + r; if (gr >= N) gr = N - 1;
        cp_async16(Ah + r * EH_STRIDE + f * 8,
                   hprev + (size_t)gr * HDIM + f * 8);
    }
#pragma unroll
    for (int i = 0; i < 8; i++) {
        int idx = tid + i * 256;
        int n = idx >> 4, f = idx & 15;
        cp_async16(Wh + n * EH_STRIDE + f * 8, WT + (size_t)n * HDIM + f * 8);
    }
    cp_commit();
    __syncthreads();    // sidp visible (overlaps cp.async flight)

    // accumulator init = aggw[sid] gather (fp16 table, L2-resident)
    float acc[2][8][4];
#pragma unroll
    for (int mf = 0; mf < 2; mf++)
#pragma unroll
        for (int h = 0; h < 2; h++) {
            int rl = warp_m * 32 + mf * 16 + h * 8 + quad_r;
            const __half* base = aggw + (size_t)sidp[rl] * HDIM;
#pragma unroll
            for (int nt = 0; nt < 8; nt++) {
                unsigned u = *(const unsigned*)(base + warp_n * 64 + nt * 8
                                                + quad_c * 2);
                float2 v = __half22float2(*(__half2*)&u);
                acc[mf][nt][2 * h]     = v.x;
                acc[mf][nt][2 * h + 1] = v.y;
            }
        }

    cp_wait<0>();
    __syncthreads();

    // 8 uninterrupted k-steps
#pragma unroll 1
    for (int ks = 0; ks < 8; ks++) {
        const int kk = ks * 16;
        unsigned afr[2][4];
#pragma unroll
        for (int mf = 0; mf < 2; mf++) {
            const __half* p = Ah + (warp_m * 32 + mf * 16 + quad_r) * EH_STRIDE
                                 + kk + 2 * quad_c;
            afr[mf][0] = *(const unsigned*)(p);
            afr[mf][1] = *(const unsigned*)(p + 8 * EH_STRIDE);
            afr[mf][2] = *(const unsigned*)(p + 8);
            afr[mf][3] = *(const unsigned*)(p + 8 * EH_STRIDE + 8);
        }
        unsigned bfr[8][2];
#pragma unroll
        for (int nt = 0; nt < 8; nt++) {
            const __half* p = Wh + (warp_n * 64 + nt * 8 + quad_r) * EH_STRIDE
                                 + kk + 2 * quad_c;
            bfr[nt][0] = *(const unsigned*)(p);
            bfr[nt][1] = *(const unsigned*)(p + 8);
        }
#pragma unroll
        for (int mf = 0; mf < 2; mf++)
#pragma unroll
            for (int nt = 0; nt < 8; nt++)
                mma_f16(acc[mf][nt], afr[mf], bfr[nt]);
    }

    // ---- LayerNorm statistics ----
    float s[2][2], q[2][2];
#pragma unroll
    for (int mf = 0; mf < 2; mf++)
#pragma unroll
        for (int h = 0; h < 2; h++) {
            float ss = 0.f, qq = 0.f;
#pragma unroll
            for (int nt = 0; nt < 8; nt++) {
                float z0 = acc[mf][nt][2 * h], z1 = acc[mf][nt][2 * h + 1];
                ss += z0 + z1;
                qq += z0 * z0 + z1 * z1;
            }
            s[mf][h] = ss; q[mf][h] = qq;
        }
#pragma unroll
    for (int mk = 1; mk <= 2; mk <<= 1)
#pragma unroll
        for (int mf = 0; mf < 2; mf++)
#pragma unroll
            for (int h = 0; h < 2; h++) {
                s[mf][h] += __shfl_xor_sync(0xffffffffu, s[mf][h], mk);
                q[mf][h] += __shfl_xor_sync(0xffffffffu, q[mf][h], mk);
            }
    if (quad_c == 0) {
#pragma unroll
        for (int mf = 0; mf < 2; mf++)
#pragma unroll
            for (int h = 0; h < 2; h++) {
                int rl = warp_m * 32 + mf * 16 + h * 8 + quad_r;
                red2[rl * 2 + warp_n] = make_float2(s[mf][h], q[mf][h]);
            }
    }
    __syncthreads();
    float mu[2][2], rs[2][2];
#pragma unroll
    for (int mf = 0; mf < 2; mf++)
#pragma unroll
        for (int h = 0; h < 2; h++) {
            int rl = warp_m * 32 + mf * 16 + h * 8 + quad_r;
            float2 r0 = red2[rl * 2 + 0], r1 = red2[rl * 2 + 1];
            float ss = r0.x + r1.x, qq = r0.y + r1.y;
            float m = ss * (1.f / HDIM);
            float var = fmaf(qq, 1.f / HDIM, -m * m);
            mu[mf][h] = m;
            rs[mf][h] = rsqrtf(var + LN_EPS);
        }
    __syncthreads();   // all warps done reading Ah/Wh before stage overwrite

    // ---- normalize + ReLU into stage ----
#pragma unroll
    for (int nt = 0; nt < 8; nt++) {
        int col = warp_n * 64 + nt * 8 + quad_c * 2;
        float2 gv = *(const float2*)&gw[col];
        float2 ev = *(const float2*)&be[col];
#pragma unroll
        for (int mf = 0; mf < 2; mf++)
#pragma unroll
            for (int h = 0; h < 2; h++) {
                int rl = warp_m * 32 + mf * 16 + h * 8 + quad_r;
                float z0 = acc[mf][nt][2 * h], z1 = acc[mf][nt][2 * h + 1];
                float2 o;
                o.x = fmaxf(fmaf((z0 - mu[mf][h]) * rs[mf][h], gv.x, ev.x), 0.f);
                o.y = fmaxf(fmaf((z1 - mu[mf][h]) * rs[mf][h], gv.y, ev.y), 0.f);
                *(float2*)&stage[rl * STAGE_STRIDE + col] = o;
            }
    }
    __syncthreads();

    // ---- coalesced hout writes (fp16) ----
    if (hout) {
#pragma unroll 1
        for (int rr = 0; rr < 16; rr++) {
            int rl = warp * 16 + rr;
            int grow = row0 + rl;
            if (grow < N) {
                float4 v = *(const float4*)&stage[rl * STAGE_STRIDE + lane * 4];
                __half2 h0v = __floats2half2_rn(v.x, v.y);
                __half2 h1v = __floats2half2_rn(v.z, v.w);
                uint2 pk = make_uint2(*(unsigned*)&h0v, *(unsigned*)&h1v);
                *(uint2*)(hout + (size_t)grow * HDIM + lane * 4) = pk;
            }
        }
    }

    // ---- fused segmented max ----
    {
        const int p_first = sidp[0];
        const int p_last  = sidp[127];
        for (int seg = p_first + warp; seg <= p_last; seg += 8) {
            int b = g_offsets[seg], e = g_offsets[seg + 1];
            int r0 = b - row0; if (r0 < 0) r0 = 0;
            int r1 = e - row0; if (r1 > 128) r1 = 128;
            if (r1 <= r0) continue;
            float4 m = make_float4(0.f, 0.f, 0.f, 0.f);
            for (int r = r0; r < r1; r++) {
                float4 v = *(const float4*)&stage[r * STAGE_STRIDE + lane * 4];
                m.x = fmaxf(m.x, v.x); m.y = fmaxf(m.y, v.y);
                m.z = fmaxf(m.z, v.z); m.w = fmaxf(m.w, v.w);
            }
            float* dst = maxout + (size_t)seg * HDIM + lane * 4;
            bool bnd = (b < row0) || (e > row0 + 128);
            if (bnd) {
                atomicMax((int*)dst + 0, __float_as_int(m.x));
                atomicMax((int*)dst + 1, __float_as_int(m.y));
                atomicMax((int*)dst + 2, __float_as_int(m.z));
                atomicMax((int*)dst + 3, __float_as_int(m.w));
            } else {
                *(float4*)dst = m;
            }
        }
    }
}

// ---------------- output tail ----------------
__global__ void tail_kernel(float* out, int tail) {
    int i = blockIdx.x * blockDim.x + threadIdx.x;
    float* base = out + (size_t)PNUM * HDIM;
    if (tail == PNUM) {
        if (i < PNUM) base[i] = (float)i;
    } else if (tail == 2 * PNUM) {
        if (i < PNUM) ((long long*)base)[i] = (long long)i;
    } else {
        if (i < tail) base[i] = (float)i;
    }
}

// ---------------- launch ----------------
extern "C" void kernel_launch(void* const* d_in, const int* in_sizes, int n_in,
                              void* d_out, int out_size) {
    const float* x   = (const float*)d_in[0];
    const void*  ids = d_in[1];
    const float* W0  = (const float*)d_in[2];
    const float* b0  = (const float*)d_in[3];
    const float* g0  = (const float*)d_in[4];
    const float* be0 = (const float*)d_in[5];
    const float* W1  = (const float*)d_in[6];
    const float* b1  = (const float*)d_in[7];
    const float* g1  = (const float*)d_in[8];
    const float* be1 = (const float*)d_in[9];
    const float* W2  = (const float*)d_in[10];
    const float* b2  = (const float*)d_in[11];
    const float* g2  = (const float*)d_in[12];
    const float* be2 = (const float*)d_in[13];

    const int N = in_sizes[0] / 9;
    const int P = PNUM;
    float* out = (float*)d_out;

    __half *h0, *h1, *WT1, *WT2, *WB1, *WB2, *aggw;
    float *agg, *agg2;
    int* counts;
    cudaGetSymbolAddress((void**)&h0,   g_h0);
    cudaGetSymbolAddress((void**)&h1,   g_h1);
    cudaGetSymbolAddress((void**)&WT1,  g_WT1);
    cudaGetSymbolAddress((void**)&WT2,  g_WT2);
    cudaGetSymbolAddress((void**)&WB1,  g_WB1);
    cudaGetSymbolAddress((void**)&WB2,  g_WB2);
    cudaGetSymbolAddress((void**)&agg,  g_agg);
    cudaGetSymbolAddress((void**)&agg2, g_agg2);
    cudaGetSymbolAddress((void**)&aggw, g_aggw);
    cudaGetSymbolAddress((void**)&counts, g_counts);

    cudaFuncSetAttribute(enc_kernel,
        cudaFuncAttributeMaxDynamicSharedMemorySize, ENCH_SMEM_BYTES);
    cudaFuncSetAttribute(aggw16_kernel,
        cudaFuncAttributeMaxDynamicSharedMemorySize, AGW16_SMEM_BYTES);
    cudaFuncSetAttribute(enc0_kernel,
        cudaFuncAttributeMaxDynamicSharedMemorySize, ENC0_SMEM_BYTES);

    // 0) independent work first: W^T fp16 conversion, zero-inits, tail
    wconv_kernel<<<HDIM, HDIM>>>(W1, W2);
    cudaMemsetAsync(agg,  0, (size_t)P * HDIM * sizeof(float));
    cudaMemsetAsync(agg2, 0, (size_t)P * HDIM * sizeof(float));
    cudaMemsetAsync(out,  0, (size_t)P * HDIM * sizeof(float));
    cudaMemsetAsync(counts, 0, (size_t)P * sizeof(int));
    int tail = out_size - P * HDIM;
    if (tail > 0) {
        int elems = (tail == 2 * PNUM) ? PNUM : tail;
        tail_kernel<<<(elems + 255) / 256, 256>>>(out, tail);
    }

    // 1) CSR build
    prep_kernel<<<(N + 255) / 256, 256>>>(ids, N);
    scan1_kernel<<<SCAN_NB, 256>>>();
    scan23_kernel<<<SCAN_NB, 256>>>();
    scatter_kernel<<<(N + 255) / 256, 256>>>(N);

    // 2) enc0 -> h0 (fp16) + fused seg_max -> agg
    enc0_kernel<<<(N + 127) / 128, 256, ENC0_SMEM_BYTES>>>(
        x, W0, b0, g0, be0, h0, agg, N);

    // 3) layer 1: aggW(agg) fp16 table; enc1 -> h1 + fused seg_max -> agg2
    aggw16_kernel<<<(P + 127) / 128, 256, AGW16_SMEM_BYTES>>>(
        agg, WB1, b1, aggw, P);
    enc_kernel<<<(N + 127) / 128, 256, ENCH_SMEM_BYTES>>>(
        h0, aggw, WT1, g1, be1, h1, agg2, N);

    // 4) layer 2: aggW(agg2) fp16 table; enc2 (no h store) + fused seg_max -> out
    aggw16_kernel<<<(P + 127) / 128, 256, AGW16_SMEM_BYTES>>>(
        agg2, WB2, b2, aggw, P);
    enc_kernel<<<(N + 127) / 128, 256, ENCH_SMEM_BYTES>>>(
        h1, aggw, WT2, g2, be2, nullptr, out, N);
}

// round 15
// speedup vs baseline: 1.7536x; 1.0101x over previous
#include <cuda_runtime.h>
#include <cuda_fp16.h>
#include <cstdint>

#define HDIM 128
#define NMAX 500000
#define PNUM 50000
#define LN_EPS 1e-5f
#define SCAN_NB ((PNUM + 255) / 256)   // 196

// ---------------- scratch (static __device__; no allocation) ----------------
__device__ __half g_h0[(size_t)NMAX * HDIM];
__device__ __half g_h1[(size_t)NMAX * HDIM];
__device__ __half g_WT1[HDIM * HDIM];
__device__ __half g_WT2[HDIM * HDIM];
__device__ __half g_WB1[HDIM * HDIM];
__device__ __half g_WB2[HDIM * HDIM];
__device__ float g_aggpair[(size_t)2 * PNUM * HDIM];  // [0]=agg, [1]=agg2
__device__ __half g_aggw[(size_t)PNUM * HDIM];
__device__ int   g_counts[PNUM];                       // zero-invariant
__device__ int   g_scantmp[PNUM];
__device__ int   g_blocksums[SCAN_NB];
__device__ int   g_offsets[PNUM + 1];
__device__ int   g_cursor[PNUM];
__device__ int   g_order[NMAX];
__device__ int   g_sid[NMAX];
__device__ int   g_ids[NMAX];

// ---------------- W^T fp16 conversion (off critical path) ----------------
__global__ void wconv_kernel(const float* __restrict__ W1t,
                             const float* __restrict__ W2t) {
    int k = blockIdx.x;
    int n = threadIdx.x;
    g_WT1[n * HDIM + k] = __float2half(W1t[(size_t)k * HDIM + n]);
    g_WT2[n * HDIM + k] = __float2half(W2t[(size_t)k * HDIM + n]);
    g_WB1[n * HDIM + k] = __float2half(W1t[(size_t)(k + HDIM) * HDIM + n]);
    g_WB2[n * HDIM + k] = __float2half(W2t[(size_t)(k + HDIM) * HDIM + n]);
}

// ---------------- prep: per-block dtype detect + convert + histogram --------
__global__ void prep_kernel(const void* idsraw, int N) {
    __shared__ int s_ok;
    const long long* a64 = (const long long*)idsraw;
    int lane_ok = 1;
    if (threadIdx.x < 16) {
        long long v = a64[threadIdx.x];
        lane_ok = (v >= 0 && v < PNUM);
    }
    if (threadIdx.x < 32) {
        unsigned m = __ballot_sync(0xffffffffu, lane_ok);
        if (threadIdx.x == 0) s_ok = ((m & 0xffffu) == 0xffffu) ? 1 : 0;
    }
    __syncthreads();
    int ids64 = s_ok;
    int i = blockIdx.x * blockDim.x + threadIdx.x;
    if (i >= N) return;
    int v = ids64 ? (int)a64[i] : ((const int*)idsraw)[i];
    g_ids[i] = v;
    atomicAdd(&g_counts[v], 1);
}

// ---------------- scan over g_counts ----------------
__device__ __forceinline__ int block_inclusive_scan_256(int v, int* wsum) {
    int lane = threadIdx.x & 31, w = threadIdx.x >> 5;
    int x = v;
#pragma unroll
    for (int o = 1; o < 32; o <<= 1) {
        int t = __shfl_up_sync(0xffffffffu, x, o);
        if (lane >= o) x += t;
    }
    if (lane == 31) wsum[w] = x;
    __syncthreads();
    if (w == 0) {
        int y = (lane < 8) ? wsum[lane] : 0;
#pragma unroll
        for (int o = 1; o < 8; o <<= 1) {
            int t = __shfl_up_sync(0xffffffffu, y, o);
            if (lane >= o) y += t;
        }
        if (lane < 8) wsum[lane] = y;
    }
    __syncthreads();
    return x + (w > 0 ? wsum[w - 1] : 0);
}

__global__ void scan1_kernel() {
    __shared__ int wsum[8];
    int i = blockIdx.x * 256 + threadIdx.x;
    int v = (i < PNUM) ? g_counts[i] : 0;
    int incl = block_inclusive_scan_256(v, wsum);
    if (i < PNUM) g_scantmp[i] = incl;
    if (threadIdx.x == 255) g_blocksums[blockIdx.x] = incl;
}

__global__ void scan23_kernel() {
    __shared__ int wsum[8];
    __shared__ int bs[256];
    int t = threadIdx.x;
    int v = (t < SCAN_NB) ? g_blocksums[t] : 0;
    int incl = block_inclusive_scan_256(v, wsum);
    bs[t] = incl;
    __syncthreads();
    int i = blockIdx.x * 256 + t;
    if (i >= PNUM) return;
    int off = (blockIdx.x > 0) ? bs[blockIdx.x - 1] : 0;
    int inclv = off + g_scantmp[i];
    int excl = inclv - g_counts[i];
    g_counts[i] = 0;           // restore zero-invariant for next run
    g_offsets[i] = excl;
    g_cursor[i] = excl;
    if (i == PNUM - 1) g_offsets[PNUM] = inclv;
}

__global__ void scatter_kernel(int N) {
    int i = blockIdx.x * blockDim.x + threadIdx.x;
    if (i >= N) return;
    int id = g_ids[i];
    int pos = atomicAdd(&g_cursor[id], 1);
    g_order[pos] = i;
    g_sid[pos] = id;
}

#define STAGE_STRIDE 132
#define ENC0_SMEM_FLOATS (128 * STAGE_STRIDE + 128)
#define ENC0_SMEM_BYTES (ENC0_SMEM_FLOATS * 4)

// ---------------- encoder 0 with fused segmented max -------------------------
__global__ __launch_bounds__(256, 2) void enc0_kernel(
    const float* __restrict__ x, const float* __restrict__ W0,
    const float* __restrict__ b0, const float* __restrict__ g0,
    const float* __restrict__ be0, __half* __restrict__ out,
    float* __restrict__ maxout, int N)
{
    extern __shared__ float sm[];
    float* stage = sm;
    int* sidp = (int*)(sm + 128 * STAGE_STRIDE);

    const int tid = threadIdx.x;
    const int lane = tid & 31;
    const int warp = tid >> 5;
    const int row0 = blockIdx.x * 128;

    if (tid < 128) {
        int r = row0 + tid;
        sidp[tid] = g_sid[(r < N) ? r : (N - 1)];
    }

    float w[9][4], bb[4], gg[4], ee[4];
#pragma unroll
    for (int k = 0; k < 9; k++)
#pragma unroll
        for (int c = 0; c < 4; c++)
            w[k][c] = W0[k * HDIM + lane + 32 * c];
#pragma unroll
    for (int c = 0; c < 4; c++) {
        bb[c] = b0[lane + 32 * c];
        gg[c] = g0[lane + 32 * c];
        ee[c] = be0[lane + 32 * c];
    }

#pragma unroll 1
    for (int rr = 0; rr < 16; rr++) {
        int rl = warp * 16 + rr;
        int spos = row0 + rl;
        int sp = (spos < N) ? spos : (N - 1);
        int srow = g_order[sp];

        float xv = (lane < 9) ? x[(size_t)srow * 9 + lane] : 0.f;
        float z[4] = {bb[0], bb[1], bb[2], bb[3]};
#pragma unroll
        for (int k = 0; k < 9; k++) {
            float xk = __shfl_sync(0xffffffffu, xv, k);
#pragma unroll
            for (int c = 0; c < 4; c++)
                z[c] = fmaf(xk, w[k][c], z[c]);
        }
        float s  = z[0] + z[1] + z[2] + z[3];
        float s2 = z[0]*z[0] + z[1]*z[1] + z[2]*z[2] + z[3]*z[3];
#pragma unroll
        for (int o = 16; o > 0; o >>= 1) {
            s  += __shfl_xor_sync(0xffffffffu, s, o);
            s2 += __shfl_xor_sync(0xffffffffu, s2, o);
        }
        float mu  = s * (1.f / HDIM);
        float var = fmaf(s2, 1.f / HDIM, -mu * mu);
        float rs  = rsqrtf(var + LN_EPS);
#pragma unroll
        for (int c = 0; c < 4; c++)
            stage[rl * STAGE_STRIDE + lane + 32 * c] =
                fmaxf(fmaf((z[c] - mu) * rs, gg[c], ee[c]), 0.f);
    }
    __syncthreads();

#pragma unroll 1
    for (int rr = 0; rr < 16; rr++) {
        int rl = warp * 16 + rr;
        int spos = row0 + rl;
        if (spos < N) {
            float4 v = *(const float4*)&stage[rl * STAGE_STRIDE + lane * 4];
            __half2 h0v = __floats2half2_rn(v.x, v.y);
            __half2 h1v = __floats2half2_rn(v.z, v.w);
            uint2 pk = make_uint2(*(unsigned*)&h0v, *(unsigned*)&h1v);
            *(uint2*)(out + (size_t)spos * HDIM + lane * 4) = pk;
        }
    }

    {
        const int p_first = sidp[0];
        const int p_last  = sidp[127];
        for (int seg = p_first + warp; seg <= p_last; seg += 8) {
            int b = g_offsets[seg], e = g_offsets[seg + 1];
            int r0 = b - row0; if (r0 < 0) r0 = 0;
            int r1 = e - row0; if (r1 > 128) r1 = 128;
            if (r1 <= r0) continue;
            float4 m = make_float4(0.f, 0.f, 0.f, 0.f);
            for (int r = r0; r < r1; r++) {
                float4 vv = *(const float4*)&stage[r * STAGE_STRIDE + lane * 4];
                m.x = fmaxf(m.x, vv.x); m.y = fmaxf(m.y, vv.y);
                m.z = fmaxf(m.z, vv.z); m.w = fmaxf(m.w, vv.w);
            }
            float* dst = maxout + (size_t)seg * HDIM + lane * 4;
            bool bnd = (b < row0) || (e > row0 + 128);
            if (bnd) {
                atomicMax((int*)dst + 0, __float_as_int(m.x));
                atomicMax((int*)dst + 1, __float_as_int(m.y));
                atomicMax((int*)dst + 2, __float_as_int(m.z));
                atomicMax((int*)dst + 3, __float_as_int(m.w));
            } else {
                *(float4*)dst = m;
            }
        }
    }
}

// ---------------- mma helpers ----------------
__device__ __forceinline__ void cp_async16(void* s, const void* g) {
    unsigned sa = (unsigned)__cvta_generic_to_shared(s);
    asm volatile("cp.async.cg.shared.global [%0], [%1], 16;\n" :: "r"(sa), "l"(g));
}
__device__ __forceinline__ void cp_commit() {
    asm volatile("cp.async.commit_group;\n" ::: "memory");
}
template<int n> __device__ __forceinline__ void cp_wait() {
    asm volatile("cp.async.wait_group %0;\n" :: "n"(n) : "memory");
}
__device__ __forceinline__ void mma_f16(float acc[4], const unsigned a[4], const unsigned b[2]) {
    asm volatile(
        "mma.sync.aligned.m16n8k16.row.col.f32.f16.f16.f32 "
        "{%0,%1,%2,%3},{%4,%5,%6,%7},{%8,%9},{%0,%1,%2,%3};\n"
        : "+f"(acc[0]), "+f"(acc[1]), "+f"(acc[2]), "+f"(acc[3])
        : "r"(a[0]), "r"(a[1]), "r"(a[2]), "r"(a[3]), "r"(b[0]), "r"(b[1]));
}
__device__ __forceinline__ void ldsm_x4(unsigned r[4], const __half* p) {
    unsigned a = (unsigned)__cvta_generic_to_shared(p);
    asm volatile("ldmatrix.sync.aligned.m8n8.x4.shared.b16 {%0,%1,%2,%3}, [%4];\n"
        : "=r"(r[0]), "=r"(r[1]), "=r"(r[2]), "=r"(r[3]) : "r"(a));
}
__device__ __forceinline__ void ldsm_x2(unsigned r[2], const __half* p) {
    unsigned a = (unsigned)__cvta_generic_to_shared(p);
    asm volatile("ldmatrix.sync.aligned.m8n8.x2.shared.b16 {%0,%1}, [%2];\n"
        : "=r"(r[0]), "=r"(r[1]) : "r"(a));
}

// ---------------- aggw16: aggW = bias + agg @ W_bot, fp16 MMA, fp16 output ---
#define AGH_STRIDE 136
#define AGH_BUF (128 * AGH_STRIDE)
#define AGW16_SMEM_BYTES (2 * AGH_BUF * 2)

__global__ __launch_bounds__(256, 2) void aggw16_kernel(
    const float* __restrict__ agg, const __half* __restrict__ WB,
    const float* __restrict__ b, __half* __restrict__ aggw, int P)
{
    extern __shared__ float sm[];
    __half* Ah = (__half*)sm;
    __half* Wh = Ah + AGH_BUF;

    const int tid = threadIdx.x;
    const int lane = tid & 31;
    const int quad_r = lane >> 2, quad_c = lane & 3;
    const int warp = tid >> 5;
    const int warp_m = warp >> 1, warp_n = warp & 1;
    const int row0 = blockIdx.x * 128;

#pragma unroll
    for (int i = 0; i < 8; i++) {
        int idx = tid + i * 256;
        int n = idx >> 4, f = idx & 15;
        cp_async16(Wh + n * AGH_STRIDE + f * 8, WB + (size_t)n * HDIM + f * 8);
    }
    cp_commit();

#pragma unroll
    for (int i = 0; i < 16; i++) {
        int idx = tid + i * 256;
        int r = idx >> 5, f = idx & 31;
        int gr = row0 + r; if (gr >= P) gr = P - 1;
        float4 v = *(const float4*)(agg + (size_t)gr * HDIM + f * 4);
        __half2 p0 = __floats2half2_rn(v.x, v.y);
        __half2 p1 = __floats2half2_rn(v.z, v.w);
        uint2 pk = make_uint2(*(unsigned*)&p0, *(unsigned*)&p1);
        *(uint2*)(Ah + r * AGH_STRIDE + f * 4) = pk;
    }

    float acc[2][8][4];
#pragma unroll
    for (int nt = 0; nt < 8; nt++) {
        float2 bv = *(const float2*)&b[warp_n * 64 + nt * 8 + quad_c * 2];
#pragma unroll
        for (int mf = 0; mf < 2; mf++) {
            acc[mf][nt][0] = bv.x; acc[mf][nt][1] = bv.y;
            acc[mf][nt][2] = bv.x; acc[mf][nt][3] = bv.y;
        }
    }

    cp_wait<0>();
    __syncthreads();

    // ldmatrix lane-address bases
    const __half* baseA0 = Ah + (warp_m * 32 + (lane & 15)) * AGH_STRIDE
                              + ((lane >> 4) << 3);
    const __half* baseA1 = baseA0 + 16 * AGH_STRIDE;
    const __half* baseB  = Wh + (warp_n * 64 + (lane & 7)) * AGH_STRIDE
                              + (((lane >> 3) & 1) << 3);

#pragma unroll 1
    for (int ks = 0; ks < 8; ks++) {
        const int kk = ks * 16;
        unsigned afr[2][4];
        ldsm_x4(afr[0], baseA0 + kk);
        ldsm_x4(afr[1], baseA1 + kk);
        unsigned bfr[8][2];
#pragma unroll
        for (int nt = 0; nt < 8; nt++)
            ldsm_x2(bfr[nt], baseB + nt * 8 * AGH_STRIDE + kk);
#pragma unroll
        for (int mf = 0; mf < 2; mf++)
#pragma unroll
            for (int nt = 0; nt < 8; nt++)
                mma_f16(acc[mf][nt], afr[mf], bfr[nt]);
    }

#pragma unroll
    for (int nt = 0; nt < 8; nt++) {
        int col = warp_n * 64 + nt * 8 + quad_c * 2;
#pragma unroll
        for (int mf = 0; mf < 2; mf++)
#pragma unroll
            for (int h = 0; h < 2; h++) {
                int grow = row0 + warp_m * 32 + mf * 16 + h * 8 + quad_r;
                if (grow < P) {
                    __half2 hv = __floats2half2_rn(acc[mf][nt][2 * h],
                                                   acc[mf][nt][2 * h + 1]);
                    *(unsigned*)(aggw + (size_t)grow * HDIM + col) =
                        *(unsigned*)&hv;
                }
            }
    }
}

// ---------------- encoder 1/2: single-shot K=128 fp16 mma + fused segmax -----
#define EH_STRIDE 136
#define EH_BUF (128 * EH_STRIDE)
#define ENCH_SMEM_BYTES 72192

__global__ __launch_bounds__(256, 2) void enc_kernel(
    const __half* __restrict__ hprev, const __half* __restrict__ aggw,
    const __half* __restrict__ WT, const float* __restrict__ gw,
    const float* __restrict__ be, __half* __restrict__ hout,
    float* __restrict__ maxout, int N)
{
    extern __shared__ char smraw[];
    __half* Ah = (__half*)smraw;
    __half* Wh = Ah + EH_BUF;
    float* stage = (float*)smraw;
    float2* red2 = (float2*)(smraw + 69632);
    int*   sidp = (int*)(smraw + 71680);

    const int tid = threadIdx.x;
    const int lane = tid & 31;
    const int quad_r = lane >> 2, quad_c = lane & 3;
    const int warp = tid >> 5;
    const int warp_m = warp >> 1, warp_n = warp & 1;
    const int row0 = blockIdx.x * 128;

    if (tid < 128) {
        int r = row0 + tid;
        sidp[tid] = g_sid[(r < N) ? r : (N - 1)];
    }

#pragma unroll
    for (int i = 0; i < 8; i++) {
        int idx = tid + i * 256;
        int r = idx >> 4, f = idx & 15;
        int gr = row0 + r; if (gr >= N) gr = N - 1;
        cp_async16(Ah + r * EH_STRIDE + f * 8,
                   hprev + (size_t)gr * HDIM + f * 8);
    }
#pragma unroll
    for (int i = 0; i < 8; i++) {
        int idx = tid + i * 256;
        int n = idx >> 4, f = idx & 15;
        cp_async16(Wh + n * EH_STRIDE + f * 8, WT + (size_t)n * HDIM + f * 8);
    }
    cp_commit();
    __syncthreads();

    // accumulator init = aggw[sid] gather (fp16 table, L2-resident)
    float acc[2][8][4];
#pragma unroll
    for (int mf = 0; mf < 2; mf++)
#pragma unroll
        for (int h = 0; h < 2; h++) {
            int rl = warp_m * 32 + mf * 16 + h * 8 + quad_r;
            const __half* base = aggw + (size_t)sidp[rl] * HDIM;
#pragma unroll
            for (int nt = 0; nt < 8; nt++) {
                unsigned u = *(const unsigned*)(base + warp_n * 64 + nt * 8
                                                + quad_c * 2);
                float2 v = __half22float2(*(__half2*)&u);
                acc[mf][nt][2 * h]     = v.x;
                acc[mf][nt][2 * h + 1] = v.y;
            }
        }

    cp_wait<0>();
    __syncthreads();

    const __half* baseA0 = Ah + (warp_m * 32 + (lane & 15)) * EH_STRIDE
                              + ((lane >> 4) << 3);
    const __half* baseA1 = baseA0 + 16 * EH_STRIDE;
    const __half* baseB  = Wh + (warp_n * 64 + (lane & 7)) * EH_STRIDE
                              + (((lane >> 3) & 1) << 3);

#pragma unroll 1
    for (int ks = 0; ks < 8; ks++) {
        const int kk = ks * 16;
        unsigned afr[2][4];
        ldsm_x4(afr[0], baseA0 + kk);
        ldsm_x4(afr[1], baseA1 + kk);
        unsigned bfr[8][2];
#pragma unroll
        for (int nt = 0; nt < 8; nt++)
            ldsm_x2(bfr[nt], baseB + nt * 8 * EH_STRIDE + kk);
#pragma unroll
        for (int mf = 0; mf < 2; mf++)
#pragma unroll
            for (int nt = 0; nt < 8; nt++)
                mma_f16(acc[mf][nt], afr[mf], bfr[nt]);
    }

    // ---- LayerNorm statistics ----
    float s[2][2], q[2][2];
#pragma unroll
    for (int mf = 0; mf < 2; mf++)
#pragma unroll
        for (int h = 0; h < 2; h++) {
            float ss = 0.f, qq = 0.f;
#pragma unroll
            for (int nt = 0; nt < 8; nt++) {
                float z0 = acc[mf][nt][2 * h], z1 = acc[mf][nt][2 * h + 1];
                ss += z0 + z1;
                qq += z0 * z0 + z1 * z1;
            }
            s[mf][h] = ss; q[mf][h] = qq;
        }
#pragma unroll
    for (int mk = 1; mk <= 2; mk <<= 1)
#pragma unroll
        for (int mf = 0; mf < 2; mf++)
#pragma unroll
            for (int h = 0; h < 2; h++) {
                s[mf][h] += __shfl_xor_sync(0xffffffffu, s[mf][h], mk);
                q[mf][h] += __shfl_xor_sync(0xffffffffu, q[mf][h], mk);
            }
    if (quad_c == 0) {
#pragma unroll
        for (int mf = 0; mf < 2; mf++)
#pragma unroll
            for (int h = 0; h < 2; h++) {
                int rl = warp_m * 32 + mf * 16 + h * 8 + quad_r;
                red2[rl * 2 + warp_n] = make_float2(s[mf][h], q[mf][h]);
            }
    }
    __syncthreads();
    float mu[2][2], rs[2][2];
#pragma unroll
    for (int mf = 0; mf < 2; mf++)
#pragma unroll
        for (int h = 0; h < 2; h++) {
            int rl = warp_m * 32 + mf * 16 + h * 8 + quad_r;
            float2 r0 = red2[rl * 2 + 0], r1 = red2[rl * 2 + 1];
            float ss = r0.x + r1.x, qq = r0.y + r1.y;
            float m = ss * (1.f / HDIM);
            float var = fmaf(qq, 1.f / HDIM, -m * m);
            mu[mf][h] = m;
            rs[mf][h] = rsqrtf(var + LN_EPS);
        }
    __syncthreads();

    // ---- normalize + ReLU into stage ----
#pragma unroll
    for (int nt = 0; nt < 8; nt++) {
        int col = warp_n * 64 + nt * 8 + quad_c * 2;
        float2 gv = *(const float2*)&gw[col];
        float2 ev = *(const float2*)&be[col];
#pragma unroll
        for (int mf = 0; mf < 2; mf++)
#pragma unroll
            for (int h = 0; h < 2; h++) {
                int rl = warp_m * 32 + mf * 16 + h * 8 + quad_r;
                float z0 = acc[mf][nt][2 * h], z1 = acc[mf][nt][2 * h + 1];
                float2 o;
                o.x = fmaxf(fmaf((z0 - mu[mf][h]) * rs[mf][h], gv.x, ev.x), 0.f);
                o.y = fmaxf(fmaf((z1 - mu[mf][h]) * rs[mf][h], gv.y, ev.y), 0.f);
                *(float2*)&stage[rl * STAGE_STRIDE + col] = o;
            }
    }
    __syncthreads();

    if (hout) {
#pragma unroll 1
        for (int rr = 0; rr < 16; rr++) {
            int rl = warp * 16 + rr;
            int grow = row0 + rl;
            if (grow < N) {
                float4 v = *(const float4*)&stage[rl * STAGE_STRIDE + lane * 4];
                __half2 h0v = __floats2half2_rn(v.x, v.y);
                __half2 h1v = __floats2half2_rn(v.z, v.w);
                uint2 pk = make_uint2(*(unsigned*)&h0v, *(unsigned*)&h1v);
                *(uint2*)(hout + (size_t)grow * HDIM + lane * 4) = pk;
            }
        }
    }

    {
        const int p_first = sidp[0];
        const int p_last  = sidp[127];
        for (int seg = p_first + warp; seg <= p_last; seg += 8) {
            int b = g_offsets[seg], e = g_offsets[seg + 1];
            int r0 = b - row0; if (r0 < 0) r0 = 0;
            int r1 = e - row0; if (r1 > 128) r1 = 128;
            if (r1 <= r0) continue;
            float4 m = make_float4(0.f, 0.f, 0.f, 0.f);
            for (int r = r0; r < r1; r++) {
                float4 v = *(const float4*)&stage[r * STAGE_STRIDE + lane * 4];
                m.x = fmaxf(m.x, v.x); m.y = fmaxf(m.y, v.y);
                m.z = fmaxf(m.z, v.z); m.w = fmaxf(m.w, v.w);
            }
            float* dst = maxout + (size_t)seg * HDIM + lane * 4;
            bool bnd = (b < row0) || (e > row0 + 128);
            if (bnd) {
                atomicMax((int*)dst + 0, __float_as_int(m.x));
                atomicMax((int*)dst + 1, __float_as_int(m.y));
                atomicMax((int*)dst + 2, __float_as_int(m.z));
                atomicMax((int*)dst + 3, __float_as_int(m.w));
            } else {
                *(float4*)dst = m;
            }
        }
    }
}

// ---------------- output tail ----------------
__global__ void tail_kernel(float* out, int tail) {
    int i = blockIdx.x * blockDim.x + threadIdx.x;
    float* base = out + (size_t)PNUM * HDIM;
    if (tail == PNUM) {
        if (i < PNUM) base[i] = (float)i;
    } else if (tail == 2 * PNUM) {
        if (i < PNUM) ((long long*)base)[i] = (long long)i;
    } else {
        if (i < tail) base[i] = (float)i;
    }
}

// ---------------- launch ----------------
extern "C" void kernel_launch(void* const* d_in, const int* in_sizes, int n_in,
                              void* d_out, int out_size) {
    const float* x   = (const float*)d_in[0];
    const void*  ids = d_in[1];
    const float* W0  = (const float*)d_in[2];
    const float* b0  = (const float*)d_in[3];
    const float* g0  = (const float*)d_in[4];
    const float* be0 = (const float*)d_in[5];
    const float* W1  = (const float*)d_in[6];
    const float* b1  = (const float*)d_in[7];
    const float* g1  = (const float*)d_in[8];
    const float* be1 = (const float*)d_in[9];
    const float* W2  = (const float*)d_in[10];
    const float* b2  = (const float*)d_in[11];
    const float* g2  = (const float*)d_in[12];
    const float* be2 = (const float*)d_in[13];

    const int N = in_sizes[0] / 9;
    const int P = PNUM;
    float* out = (float*)d_out;

    __half *h0, *h1, *WT1, *WT2, *WB1, *WB2, *aggw;
    float *aggpair;
    cudaGetSymbolAddress((void**)&h0,   g_h0);
    cudaGetSymbolAddress((void**)&h1,   g_h1);
    cudaGetSymbolAddress((void**)&WT1,  g_WT1);
    cudaGetSymbolAddress((void**)&WT2,  g_WT2);
    cudaGetSymbolAddress((void**)&WB1,  g_WB1);
    cudaGetSymbolAddress((void**)&WB2,  g_WB2);
    cudaGetSymbolAddress((void**)&aggw, g_aggw);
    cudaGetSymbolAddress((void**)&aggpair, g_aggpair);
    float* agg  = aggpair;
    float* agg2 = aggpair + (size_t)P * HDIM;

    cudaFuncSetAttribute(enc_kernel,
        cudaFuncAttributeMaxDynamicSharedMemorySize, ENCH_SMEM_BYTES);
    cudaFuncSetAttribute(aggw16_kernel,
        cudaFuncAttributeMaxDynamicSharedMemorySize, AGW16_SMEM_BYTES);
    cudaFuncSetAttribute(enc0_kernel,
        cudaFuncAttributeMaxDynamicSharedMemorySize, ENC0_SMEM_BYTES);

    // 0) independent work first: W^T fp16 conversion, zero-inits, tail
    wconv_kernel<<<HDIM, HDIM>>>(W1, W2);
    cudaMemsetAsync(aggpair, 0, (size_t)2 * P * HDIM * sizeof(float));
    cudaMemsetAsync(out, 0, (size_t)P * HDIM * sizeof(float));
    int tail = out_size - P * HDIM;
    if (tail > 0) {
        int elems = (tail == 2 * PNUM) ? PNUM : tail;
        tail_kernel<<<(elems + 255) / 256, 256>>>(out, tail);
    }

    // 1) CSR build (g_counts is zero by invariant; scan23 re-zeroes it)
    prep_kernel<<<(N + 255) / 256, 256>>>(ids, N);
    scan1_kernel<<<SCAN_NB, 256>>>();
    scan23_kernel<<<SCAN_NB, 256>>>();
    scatter_kernel<<<(N + 255) / 256, 256>>>(N);

    // 2) enc0 -> h0 (fp16) + fused seg_max -> agg
    enc0_kernel<<<(N + 127) / 128, 256, ENC0_SMEM_BYTES>>>(
        x, W0, b0, g0, be0, h0, agg, N);

    // 3) layer 1: aggW(agg) fp16; enc1 -> h1 + fused seg_max -> agg2
    aggw16_kernel<<<(P + 127) / 128, 256, AGW16_SMEM_BYTES>>>(
        agg, WB1, b1, aggw, P);
    enc_kernel<<<(N + 127) / 128, 256, ENCH_SMEM_BYTES>>>(
        h0, aggw, WT1, g1, be1, h1, agg2, N);

    // 4) layer 2: aggW(agg2) fp16; enc2 (no h store) + fused seg_max -> out
    aggw16_kernel<<<(P + 127) / 128, 256, AGW16_SMEM_BYTES>>>(
        agg2, WB2, b2, aggw, P);
    enc_kernel<<<(N + 127) / 128, 256, ENCH_SMEM_BYTES>>>(
        h1, aggw, WT2, g2, be2, nullptr, out, N);
}

// round 16
// speedup vs baseline: 1.8146x; 1.0348x over previous
#include <cuda_runtime.h>
#include <cuda_fp16.h>
#include <cstdint>

#define HDIM 128
#define NMAX 500000
#define PNUM 50000
#define LN_EPS 1e-5f
#define SCAN_NB ((PNUM + 255) / 256)   // 196

// ---------------- scratch (static __device__; no allocation) ----------------
__device__ __half g_h0[(size_t)NMAX * HDIM];
__device__ __half g_h1[(size_t)NMAX * HDIM];
__device__ __half g_WT1[HDIM * HDIM];
__device__ __half g_WT2[HDIM * HDIM];
__device__ __half g_WB1[HDIM * HDIM];
__device__ __half g_WB2[HDIM * HDIM];
__device__ float g_aggpair[(size_t)2 * PNUM * HDIM];  // [0]=agg, [1]=agg2
__device__ __half g_aggw[(size_t)PNUM * HDIM];
__device__ int   g_counts[PNUM];                       // zero-invariant
__device__ int   g_scantmp[PNUM];
__device__ int   g_blocksums[SCAN_NB];
__device__ int   g_offsets[PNUM + 1];
__device__ int   g_cursor[PNUM];
__device__ int   g_order[NMAX];
__device__ int   g_sid[NMAX];
__device__ int   g_ids[NMAX];

// ---------------- prep: dtype detect + convert + histogram + weight conv ----
__global__ void prep_kernel(const void* idsraw,
                            const float* __restrict__ W1,
                            const float* __restrict__ W2, int N) {
    __shared__ int s_ok;
    const long long* a64 = (const long long*)idsraw;
    int lane_ok = 1;
    if (threadIdx.x < 16) {
        long long v = a64[threadIdx.x];
        lane_ok = (v >= 0 && v < PNUM);
    }
    if (threadIdx.x < 32) {
        unsigned m = __ballot_sync(0xffffffffu, lane_ok);
        if (threadIdx.x == 0) s_ok = ((m & 0xffffu) == 0xffffu) ? 1 : 0;
    }
    __syncthreads();
    int ids64 = s_ok;
    int i = blockIdx.x * blockDim.x + threadIdx.x;

    // folded weight conversion (first 65536 threads)
    if (i < 4 * HDIM * HDIM) {
        int which = i >> 14;
        int j = i & 16383;
        int k = j >> 7, n = j & 127;
        if (which == 0)
            g_WT1[n * HDIM + k] = __float2half(W1[(size_t)k * HDIM + n]);
        else if (which == 1)
            g_WT2[n * HDIM + k] = __float2half(W2[(size_t)k * HDIM + n]);
        else if (which == 2)
            g_WB1[n * HDIM + k] = __float2half(W1[(size_t)(k + HDIM) * HDIM + n]);
        else
            g_WB2[n * HDIM + k] = __float2half(W2[(size_t)(k + HDIM) * HDIM + n]);
    }

    if (i >= N) return;
    int v = ids64 ? (int)a64[i] : ((const int*)idsraw)[i];
    g_ids[i] = v;
    atomicAdd(&g_counts[v], 1);
}

// ---------------- scan over g_counts ----------------
__device__ __forceinline__ int block_inclusive_scan_256(int v, int* wsum) {
    int lane = threadIdx.x & 31, w = threadIdx.x >> 5;
    int x = v;
#pragma unroll
    for (int o = 1; o < 32; o <<= 1) {
        int t = __shfl_up_sync(0xffffffffu, x, o);
        if (lane >= o) x += t;
    }
    if (lane == 31) wsum[w] = x;
    __syncthreads();
    if (w == 0) {
        int y = (lane < 8) ? wsum[lane] : 0;
#pragma unroll
        for (int o = 1; o < 8; o <<= 1) {
            int t = __shfl_up_sync(0xffffffffu, y, o);
            if (lane >= o) y += t;
        }
        if (lane < 8) wsum[lane] = y;
    }
    __syncthreads();
    return x + (w > 0 ? wsum[w - 1] : 0);
}

__global__ void scan1_kernel() {
    __shared__ int wsum[8];
    int i = blockIdx.x * 256 + threadIdx.x;
    int v = (i < PNUM) ? g_counts[i] : 0;
    int incl = block_inclusive_scan_256(v, wsum);
    if (i < PNUM) g_scantmp[i] = incl;
    if (threadIdx.x == 255) g_blocksums[blockIdx.x] = incl;
}

// merged scan2+scan3 + counts-re-zero + tail write + boundary-row zeroing
__global__ void scan23_kernel(float* __restrict__ agg,
                              float* __restrict__ agg2,
                              float* __restrict__ out, int tailkind) {
    __shared__ int wsum[8];
    __shared__ int bs[256];
    int t = threadIdx.x;
    int v = (t < SCAN_NB) ? g_blocksums[t] : 0;
    int incl = block_inclusive_scan_256(v, wsum);
    bs[t] = incl;
    __syncthreads();
    int i = blockIdx.x * 256 + t;
    if (i >= PNUM) return;
    int off = (blockIdx.x > 0) ? bs[blockIdx.x - 1] : 0;
    int inclv = off + g_scantmp[i];
    int excl = inclv - g_counts[i];
    g_counts[i] = 0;           // restore zero-invariant for next run
    g_offsets[i] = excl;
    g_cursor[i] = excl;
    if (i == PNUM - 1) g_offsets[PNUM] = inclv;

    // arange tail (thread i writes element i)
    float* base = out + (size_t)PNUM * HDIM;
    if (tailkind == 1) base[i] = (float)i;
    else if (tailkind == 2) ((long long*)base)[i] = (long long)i;

    // boundary/empty segments need zero-initialized rows for atomicMax path
    bool nz = (inclv == excl) || ((excl >> 7) != ((inclv - 1) >> 7));
    if (nz) {
        float4 z = make_float4(0.f, 0.f, 0.f, 0.f);
        float4* r0p = (float4*)(agg  + (size_t)i * HDIM);
        float4* r1p = (float4*)(agg2 + (size_t)i * HDIM);
        float4* r2p = (float4*)(out  + (size_t)i * HDIM);
#pragma unroll 4
        for (int c = 0; c < 32; c++) { r0p[c] = z; r1p[c] = z; r2p[c] = z; }
    }
}

__global__ void scatter_kernel(int N) {
    int i = blockIdx.x * blockDim.x + threadIdx.x;
    if (i >= N) return;
    int id = g_ids[i];
    int pos = atomicAdd(&g_cursor[id], 1);
    g_order[pos] = i;
    g_sid[pos] = id;
}

#define STAGE_STRIDE 132
#define ENC0_SMEM_FLOATS (128 * STAGE_STRIDE + 128)
#define ENC0_SMEM_BYTES (ENC0_SMEM_FLOATS * 4)

// ---------------- encoder 0 with fused segmented max -------------------------
__global__ __launch_bounds__(256, 2) void enc0_kernel(
    const float* __restrict__ x, const float* __restrict__ W0,
    const float* __restrict__ b0, const float* __restrict__ g0,
    const float* __restrict__ be0, __half* __restrict__ out,
    float* __restrict__ maxout, int N)
{
    extern __shared__ float sm[];
    float* stage = sm;
    int* sidp = (int*)(sm + 128 * STAGE_STRIDE);

    const int tid = threadIdx.x;
    const int lane = tid & 31;
    const int warp = tid >> 5;
    const int row0 = blockIdx.x * 128;

    if (tid < 128) {
        int r = row0 + tid;
        sidp[tid] = g_sid[(r < N) ? r : (N - 1)];
    }

    float w[9][4], bb[4], gg[4], ee[4];
#pragma unroll
    for (int k = 0; k < 9; k++)
#pragma unroll
        for (int c = 0; c < 4; c++)
            w[k][c] = W0[k * HDIM + lane + 32 * c];
#pragma unroll
    for (int c = 0; c < 4; c++) {
        bb[c] = b0[lane + 32 * c];
        gg[c] = g0[lane + 32 * c];
        ee[c] = be0[lane + 32 * c];
    }

#pragma unroll 1
    for (int rr = 0; rr < 16; rr++) {
        int rl = warp * 16 + rr;
        int spos = row0 + rl;
        int sp = (spos < N) ? spos : (N - 1);
        int srow = g_order[sp];

        float xv = (lane < 9) ? x[(size_t)srow * 9 + lane] : 0.f;
        float z[4] = {bb[0], bb[1], bb[2], bb[3]};
#pragma unroll
        for (int k = 0; k < 9; k++) {
            float xk = __shfl_sync(0xffffffffu, xv, k);
#pragma unroll
            for (int c = 0; c < 4; c++)
                z[c] = fmaf(xk, w[k][c], z[c]);
        }
        float s  = z[0] + z[1] + z[2] + z[3];
        float s2 = z[0]*z[0] + z[1]*z[1] + z[2]*z[2] + z[3]*z[3];
#pragma unroll
        for (int o = 16; o > 0; o >>= 1) {
            s  += __shfl_xor_sync(0xffffffffu, s, o);
            s2 += __shfl_xor_sync(0xffffffffu, s2, o);
        }
        float mu  = s * (1.f / HDIM);
        float var = fmaf(s2, 1.f / HDIM, -mu * mu);
        float rs  = rsqrtf(var + LN_EPS);
#pragma unroll
        for (int c = 0; c < 4; c++)
            stage[rl * STAGE_STRIDE + lane + 32 * c] =
                fmaxf(fmaf((z[c] - mu) * rs, gg[c], ee[c]), 0.f);
    }
    __syncthreads();

#pragma unroll 1
    for (int rr = 0; rr < 16; rr++) {
        int rl = warp * 16 + rr;
        int spos = row0 + rl;
        if (spos < N) {
            float4 v = *(const float4*)&stage[rl * STAGE_STRIDE + lane * 4];
            __half2 h0v = __floats2half2_rn(v.x, v.y);
            __half2 h1v = __floats2half2_rn(v.z, v.w);
            uint2 pk = make_uint2(*(unsigned*)&h0v, *(unsigned*)&h1v);
            *(uint2*)(out + (size_t)spos * HDIM + lane * 4) = pk;
        }
    }

    {
        const int p_first = sidp[0];
        const int p_last  = sidp[127];
        for (int seg = p_first + warp; seg <= p_last; seg += 8) {
            int b = g_offsets[seg], e = g_offsets[seg + 1];
            int r0 = b - row0; if (r0 < 0) r0 = 0;
            int r1 = e - row0; if (r1 > 128) r1 = 128;
            if (r1 <= r0) continue;
            float4 m = make_float4(0.f, 0.f, 0.f, 0.f);
            for (int r = r0; r < r1; r++) {
                float4 vv = *(const float4*)&stage[r * STAGE_STRIDE + lane * 4];
                m.x = fmaxf(m.x, vv.x); m.y = fmaxf(m.y, vv.y);
                m.z = fmaxf(m.z, vv.z); m.w = fmaxf(m.w, vv.w);
            }
            float* dst = maxout + (size_t)seg * HDIM + lane * 4;
            bool bnd = (b < row0) || (e > row0 + 128);
            if (bnd) {
                atomicMax((int*)dst + 0, __float_as_int(m.x));
                atomicMax((int*)dst + 1, __float_as_int(m.y));
                atomicMax((int*)dst + 2, __float_as_int(m.z));
                atomicMax((int*)dst + 3, __float_as_int(m.w));
            } else {
                *(float4*)dst = m;
            }
        }
    }
}

// ---------------- mma helpers ----------------
__device__ __forceinline__ void cp_async16(void* s, const void* g) {
    unsigned sa = (unsigned)__cvta_generic_to_shared(s);
    asm volatile("cp.async.cg.shared.global [%0], [%1], 16;\n" :: "r"(sa), "l"(g));
}
__device__ __forceinline__ void cp_commit() {
    asm volatile("cp.async.commit_group;\n" ::: "memory");
}
template<int n> __device__ __forceinline__ void cp_wait() {
    asm volatile("cp.async.wait_group %0;\n" :: "n"(n) : "memory");
}
__device__ __forceinline__ void mma_f16(float acc[4], const unsigned a[4], const unsigned b[2]) {
    asm volatile(
        "mma.sync.aligned.m16n8k16.row.col.f32.f16.f16.f32 "
        "{%0,%1,%2,%3},{%4,%5,%6,%7},{%8,%9},{%0,%1,%2,%3};\n"
        : "+f"(acc[0]), "+f"(acc[1]), "+f"(acc[2]), "+f"(acc[3])
        : "r"(a[0]), "r"(a[1]), "r"(a[2]), "r"(a[3]), "r"(b[0]), "r"(b[1]));
}
__device__ __forceinline__ void ldsm_x4(unsigned r[4], const __half* p) {
    unsigned a = (unsigned)__cvta_generic_to_shared(p);
    asm volatile("ldmatrix.sync.aligned.m8n8.x4.shared.b16 {%0,%1,%2,%3}, [%4];\n"
        : "=r"(r[0]), "=r"(r[1]), "=r"(r[2]), "=r"(r[3]) : "r"(a));
}
__device__ __forceinline__ void ldsm_x2(unsigned r[2], const __half* p) {
    unsigned a = (unsigned)__cvta_generic_to_shared(p);
    asm volatile("ldmatrix.sync.aligned.m8n8.x2.shared.b16 {%0,%1}, [%2];\n"
        : "=r"(r[0]), "=r"(r[1]) : "r"(a));
}

// ---------------- aggw16: aggW = bias + agg @ W_bot, fp16 MMA, fp16 output ---
#define AGH_STRIDE 136
#define AGH_BUF (128 * AGH_STRIDE)
#define AGW16_SMEM_BYTES (2 * AGH_BUF * 2)

__global__ __launch_bounds__(256, 2) void aggw16_kernel(
    const float* __restrict__ agg, const __half* __restrict__ WB,
    const float* __restrict__ b, __half* __restrict__ aggw, int P)
{
    extern __shared__ float sm[];
    __half* Ah = (__half*)sm;
    __half* Wh = Ah + AGH_BUF;

    const int tid = threadIdx.x;
    const int lane = tid & 31;
    const int quad_r = lane >> 2, quad_c = lane & 3;
    const int warp = tid >> 5;
    const int warp_m = warp >> 1, warp_n = warp & 1;
    const int row0 = blockIdx.x * 128;

#pragma unroll
    for (int i = 0; i < 8; i++) {
        int idx = tid + i * 256;
        int n = idx >> 4, f = idx & 15;
        cp_async16(Wh + n * AGH_STRIDE + f * 8, WB + (size_t)n * HDIM + f * 8);
    }
    cp_commit();

#pragma unroll
    for (int i = 0; i < 16; i++) {
        int idx = tid + i * 256;
        int r = idx >> 5, f = idx & 31;
        int gr = row0 + r; if (gr >= P) gr = P - 1;
        float4 v = *(const float4*)(agg + (size_t)gr * HDIM + f * 4);
        __half2 p0 = __floats2half2_rn(v.x, v.y);
        __half2 p1 = __floats2half2_rn(v.z, v.w);
        uint2 pk = make_uint2(*(unsigned*)&p0, *(unsigned*)&p1);
        *(uint2*)(Ah + r * AGH_STRIDE + f * 4) = pk;
    }

    float acc[2][8][4];
#pragma unroll
    for (int nt = 0; nt < 8; nt++) {
        float2 bv = *(const float2*)&b[warp_n * 64 + nt * 8 + quad_c * 2];
#pragma unroll
        for (int mf = 0; mf < 2; mf++) {
            acc[mf][nt][0] = bv.x; acc[mf][nt][1] = bv.y;
            acc[mf][nt][2] = bv.x; acc[mf][nt][3] = bv.y;
        }
    }

    cp_wait<0>();
    __syncthreads();

    const __half* baseA0 = Ah + (warp_m * 32 + (lane & 15)) * AGH_STRIDE
                              + ((lane >> 4) << 3);
    const __half* baseA1 = baseA0 + 16 * AGH_STRIDE;
    const __half* baseB  = Wh + (warp_n * 64 + (lane & 7)) * AGH_STRIDE
                              + (((lane >> 3) & 1) << 3);

#pragma unroll 1
    for (int ks = 0; ks < 8; ks++) {
        const int kk = ks * 16;
        unsigned afr[2][4];
        ldsm_x4(afr[0], baseA0 + kk);
        ldsm_x4(afr[1], baseA1 + kk);
        unsigned bfr[8][2];
#pragma unroll
        for (int nt = 0; nt < 8; nt++)
            ldsm_x2(bfr[nt], baseB + nt * 8 * AGH_STRIDE + kk);
#pragma unroll
        for (int mf = 0; mf < 2; mf++)
#pragma unroll
            for (int nt = 0; nt < 8; nt++)
                mma_f16(acc[mf][nt], afr[mf], bfr[nt]);
    }

#pragma unroll
    for (int nt = 0; nt < 8; nt++) {
        int col = warp_n * 64 + nt * 8 + quad_c * 2;
#pragma unroll
        for (int mf = 0; mf < 2; mf++)
#pragma unroll
            for (int h = 0; h < 2; h++) {
                int grow = row0 + warp_m * 32 + mf * 16 + h * 8 + quad_r;
                if (grow < P) {
                    __half2 hv = __floats2half2_rn(acc[mf][nt][2 * h],
                                                   acc[mf][nt][2 * h + 1]);
                    *(unsigned*)(aggw + (size_t)grow * HDIM + col) =
                        *(unsigned*)&hv;
                }
            }
    }
}

// ---------------- encoder 1/2: single-shot K=128 fp16 mma + fused segmax -----
#define EH_STRIDE 136
#define EH_BUF (128 * EH_STRIDE)
#define ENCH_SMEM_BYTES 72192

__global__ __launch_bounds__(256, 2) void enc_kernel(
    const __half* __restrict__ hprev, const __half* __restrict__ aggw,
    const __half* __restrict__ WT, const float* __restrict__ gw,
    const float* __restrict__ be, __half* __restrict__ hout,
    float* __restrict__ maxout, int N)
{
    extern __shared__ char smraw[];
    __half* Ah = (__half*)smraw;
    __half* Wh = Ah + EH_BUF;
    float* stage = (float*)smraw;
    float2* red2 = (float2*)(smraw + 69632);
    int*   sidp = (int*)(smraw + 71680);

    const int tid = threadIdx.x;
    const int lane = tid & 31;
    const int quad_r = lane >> 2, quad_c = lane & 3;
    const int warp = tid >> 5;
    const int warp_m = warp >> 1, warp_n = warp & 1;
    const int row0 = blockIdx.x * 128;

    if (tid < 128) {
        int r = row0 + tid;
        sidp[tid] = g_sid[(r < N) ? r : (N - 1)];
    }

#pragma unroll
    for (int i = 0; i < 8; i++) {
        int idx = tid + i * 256;
        int r = idx >> 4, f = idx & 15;
        int gr = row0 + r; if (gr >= N) gr = N - 1;
        cp_async16(Ah + r * EH_STRIDE + f * 8,
                   hprev + (size_t)gr * HDIM + f * 8);
    }
#pragma unroll
    for (int i = 0; i < 8; i++) {
        int idx = tid + i * 256;
        int n = idx >> 4, f = idx & 15;
        cp_async16(Wh + n * EH_STRIDE + f * 8, WT + (size_t)n * HDIM + f * 8);
    }
    cp_commit();
    __syncthreads();

    float acc[2][8][4];
#pragma unroll
    for (int mf = 0; mf < 2; mf++)
#pragma unroll
        for (int h = 0; h < 2; h++) {
            int rl = warp_m * 32 + mf * 16 + h * 8 + quad_r;
            const __half* base = aggw + (size_t)sidp[rl] * HDIM;
#pragma unroll
            for (int nt = 0; nt < 8; nt++) {
                unsigned u = *(const unsigned*)(base + warp_n * 64 + nt * 8
                                                + quad_c * 2);
                float2 v = __half22float2(*(__half2*)&u);
                acc[mf][nt][2 * h]     = v.x;
                acc[mf][nt][2 * h + 1] = v.y;
            }
        }

    cp_wait<0>();
    __syncthreads();

    const __half* baseA0 = Ah + (warp_m * 32 + (lane & 15)) * EH_STRIDE
                              + ((lane >> 4) << 3);
    const __half* baseA1 = baseA0 + 16 * EH_STRIDE;
    const __half* baseB  = Wh + (warp_n * 64 + (lane & 7)) * EH_STRIDE
                              + (((lane >> 3) & 1) << 3);

#pragma unroll 1
    for (int ks = 0; ks < 8; ks++) {
        const int kk = ks * 16;
        unsigned afr[2][4];
        ldsm_x4(afr[0], baseA0 + kk);
        ldsm_x4(afr[1], baseA1 + kk);
        unsigned bfr[8][2];
#pragma unroll
        for (int nt = 0; nt < 8; nt++)
            ldsm_x2(bfr[nt], baseB + nt * 8 * EH_STRIDE + kk);
#pragma unroll
        for (int mf = 0; mf < 2; mf++)
#pragma unroll
            for (int nt = 0; nt < 8; nt++)
                mma_f16(acc[mf][nt], afr[mf], bfr[nt]);
    }

    // ---- LayerNorm statistics ----
    float s[2][2], q[2][2];
#pragma unroll
    for (int mf = 0; mf < 2; mf++)
#pragma unroll
        for (int h = 0; h < 2; h++) {
            float ss = 0.f, qq = 0.f;
#pragma unroll
            for (int nt = 0; nt < 8; nt++) {
                float z0 = acc[mf][nt][2 * h], z1 = acc[mf][nt][2 * h + 1];
                ss += z0 + z1;
                qq += z0 * z0 + z1 * z1;
            }
            s[mf][h] = ss; q[mf][h] = qq;
        }
#pragma unroll
    for (int mk = 1; mk <= 2; mk <<= 1)
#pragma unroll
        for (int mf = 0; mf < 2; mf++)
#pragma unroll
            for (int h = 0; h < 2; h++) {
                s[mf][h] += __shfl_xor_sync(0xffffffffu, s[mf][h], mk);
                q[mf][h] += __shfl_xor_sync(0xffffffffu, q[mf][h], mk);
            }
    if (quad_c == 0) {
#pragma unroll
        for (int mf = 0; mf < 2; mf++)
#pragma unroll
            for (int h = 0; h < 2; h++) {
                int rl = warp_m * 32 + mf * 16 + h * 8 + quad_r;
                red2[rl * 2 + warp_n] = make_float2(s[mf][h], q[mf][h]);
            }
    }
    __syncthreads();
    float mu[2][2], rs[2][2];
#pragma unroll
    for (int mf = 0; mf < 2; mf++)
#pragma unroll
        for (int h = 0; h < 2; h++) {
            int rl = warp_m * 32 + mf * 16 + h * 8 + quad_r;
            float2 r0 = red2[rl * 2 + 0], r1 = red2[rl * 2 + 1];
            float ss = r0.x + r1.x, qq = r0.y + r1.y;
            float m = ss * (1.f / HDIM);
            float var = fmaf(qq, 1.f / HDIM, -m * m);
            mu[mf][h] = m;
            rs[mf][h] = rsqrtf(var + LN_EPS);
        }
    __syncthreads();

    // ---- normalize + ReLU into stage ----
#pragma unroll
    for (int nt = 0; nt < 8; nt++) {
        int col = warp_n * 64 + nt * 8 + quad_c * 2;
        float2 gv = *(const float2*)&gw[col];
        float2 ev = *(const float2*)&be[col];
#pragma unroll
        for (int mf = 0; mf < 2; mf++)
#pragma unroll
            for (int h = 0; h < 2; h++) {
                int rl = warp_m * 32 + mf * 16 + h * 8 + quad_r;
                float z0 = acc[mf][nt][2 * h], z1 = acc[mf][nt][2 * h + 1];
                float2 o;
                o.x = fmaxf(fmaf((z0 - mu[mf][h]) * rs[mf][h], gv.x, ev.x), 0.f);
                o.y = fmaxf(fmaf((z1 - mu[mf][h]) * rs[mf][h], gv.y, ev.y), 0.f);
                *(float2*)&stage[rl * STAGE_STRIDE + col] = o;
            }
    }
    __syncthreads();

    if (hout) {
#pragma unroll 1
        for (int rr = 0; rr < 16; rr++) {
            int rl = warp * 16 + rr;
            int grow = row0 + rl;
            if (grow < N) {
                float4 v = *(const float4*)&stage[rl * STAGE_STRIDE + lane * 4];
                __half2 h0v = __floats2half2_rn(v.x, v.y);
                __half2 h1v = __floats2half2_rn(v.z, v.w);
                uint2 pk = make_uint2(*(unsigned*)&h0v, *(unsigned*)&h1v);
                *(uint2*)(hout + (size_t)grow * HDIM + lane * 4) = pk;
            }
        }
    }

    {
        const int p_first = sidp[0];
        const int p_last  = sidp[127];
        for (int seg = p_first + warp; seg <= p_last; seg += 8) {
            int b = g_offsets[seg], e = g_offsets[seg + 1];
            int r0 = b - row0; if (r0 < 0) r0 = 0;
            int r1 = e - row0; if (r1 > 128) r1 = 128;
            if (r1 <= r0) continue;
            float4 m = make_float4(0.f, 0.f, 0.f, 0.f);
            for (int r = r0; r < r1; r++) {
                float4 v = *(const float4*)&stage[r * STAGE_STRIDE + lane * 4];
                m.x = fmaxf(m.x, v.x); m.y = fmaxf(m.y, v.y);
                m.z = fmaxf(m.z, v.z); m.w = fmaxf(m.w, v.w);
            }
            float* dst = maxout + (size_t)seg * HDIM + lane * 4;
            bool bnd = (b < row0) || (e > row0 + 128);
            if (bnd) {
                atomicMax((int*)dst + 0, __float_as_int(m.x));
                atomicMax((int*)dst + 1, __float_as_int(m.y));
                atomicMax((int*)dst + 2, __float_as_int(m.z));
                atomicMax((int*)dst + 3, __float_as_int(m.w));
            } else {
                *(float4*)dst = m;
            }
        }
    }
}

// ---------------- generic tail fallback (odd tail sizes only) ----------------
__global__ void tail_kernel(float* out, int tail) {
    int i = blockIdx.x * blockDim.x + threadIdx.x;
    float* base = out + (size_t)PNUM * HDIM;
    if (i < tail) base[i] = (float)i;
}

// ---------------- launch ----------------
extern "C" void kernel_launch(void* const* d_in, const int* in_sizes, int n_in,
                              void* d_out, int out_size) {
    const float* x   = (const float*)d_in[0];
    const void*  ids = d_in[1];
    const float* W0  = (const float*)d_in[2];
    const float* b0  = (const float*)d_in[3];
    const float* g0  = (const float*)d_in[4];
    const float* be0 = (const float*)d_in[5];
    const float* W1  = (const float*)d_in[6];
    const float* b1  = (const float*)d_in[7];
    const float* g1  = (const float*)d_in[8];
    const float* be1 = (const float*)d_in[9];
    const float* W2  = (const float*)d_in[10];
    const float* b2  = (const float*)d_in[11];
    const float* g2  = (const float*)d_in[12];
    const float* be2 = (const float*)d_in[13];

    const int N = in_sizes[0] / 9;
    const int P = PNUM;
    float* out = (float*)d_out;

    __half *h0, *h1, *WT1, *WT2, *WB1, *WB2, *aggw;
    float *aggpair;
    cudaGetSymbolAddress((void**)&h0,   g_h0);
    cudaGetSymbolAddress((void**)&h1,   g_h1);
    cudaGetSymbolAddress((void**)&WT1,  g_WT1);
    cudaGetSymbolAddress((void**)&WT2,  g_WT2);
    cudaGetSymbolAddress((void**)&WB1,  g_WB1);
    cudaGetSymbolAddress((void**)&WB2,  g_WB2);
    cudaGetSymbolAddress((void**)&aggw, g_aggw);
    cudaGetSymbolAddress((void**)&aggpair, g_aggpair);
    float* agg  = aggpair;
    float* agg2 = aggpair + (size_t)P * HDIM;

    cudaFuncSetAttribute(enc_kernel,
        cudaFuncAttributeMaxDynamicSharedMemorySize, ENCH_SMEM_BYTES);
    cudaFuncSetAttribute(aggw16_kernel,
        cudaFuncAttributeMaxDynamicSharedMemorySize, AGW16_SMEM_BYTES);
    cudaFuncSetAttribute(enc0_kernel,
        cudaFuncAttributeMaxDynamicSharedMemorySize, ENC0_SMEM_BYTES);

    // tail kind: 1 = float arange (tail==P), 2 = int64 arange (tail==2P)
    int tail = out_size - P * HDIM;
    int tailkind = (tail == PNUM) ? 1 : (tail == 2 * PNUM) ? 2 : 0;
    if (tail > 0 && tailkind == 0)
        tail_kernel<<<(tail + 255) / 256, 256>>>(out, tail);

    // 1) CSR build (weights converted inside prep; boundary rows zeroed and
    //    tail written inside scan23; g_counts zero-invariant maintained)
    prep_kernel<<<(N + 255) / 256, 256>>>(ids, W1, W2, N);
    scan1_kernel<<<SCAN_NB, 256>>>();
    scan23_kernel<<<SCAN_NB, 256>>>(agg, agg2, out, tailkind);
    scatter_kernel<<<(N + 255) / 256, 256>>>(N);

    // 2) enc0 -> h0 (fp16) + fused seg_max -> agg
    enc0_kernel<<<(N + 127) / 128, 256, ENC0_SMEM_BYTES>>>(
        x, W0, b0, g0, be0, h0, agg, N);

    // 3) layer 1: aggW(agg) fp16; enc1 -> h1 + fused seg_max -> agg2
    aggw16_kernel<<<(P + 127) / 128, 256, AGW16_SMEM_BYTES>>>(
        agg, WB1, b1, aggw, P);
    enc_kernel<<<(N + 127) / 128, 256, ENCH_SMEM_BYTES>>>(
        h0, aggw, WT1, g1, be1, h1, agg2, N);

    // 4) layer 2: aggW(agg2) fp16; enc2 (no h store) + fused seg_max -> out
    aggw16_kernel<<<(P + 127) / 128, 256, AGW16_SMEM_BYTES>>>(
        agg2, WB2, b2, aggw, P);
    enc_kernel<<<(N + 127) / 128, 256, ENCH_SMEM_BYTES>>>(
        h1, aggw, WT2, g2, be2, nullptr, out, N);
}

// round 17
// speedup vs baseline: 1.8252x; 1.0058x over previous
#include <cuda_runtime.h>
#include <cuda_fp16.h>
#include <cstdint>

#define HDIM 128
#define NMAX 500000
#define PNUM 50000
#define LN_EPS 1e-5f
#define SCAN_NB ((PNUM + 255) / 256)   // 196

// ---------------- scratch (static __device__; no allocation) ----------------
__device__ __half g_h0[(size_t)NMAX * HDIM];
__device__ __half g_h1[(size_t)NMAX * HDIM];
__device__ __half g_WT1[HDIM * HDIM];
__device__ __half g_WT2[HDIM * HDIM];
__device__ __half g_WB1[HDIM * HDIM];
__device__ __half g_WB2[HDIM * HDIM];
__device__ float g_aggpair[(size_t)2 * PNUM * HDIM];  // [0]=agg, [1]=agg2
__device__ __half g_aggw[(size_t)PNUM * HDIM];
__device__ int   g_counts[PNUM];                       // zero-invariant
__device__ int   g_scantmp[PNUM];
__device__ int   g_blocksums[SCAN_NB];
__device__ int   g_offsets[PNUM + 1];
__device__ int   g_cursor[PNUM];
__device__ int2  g_osid[NMAX];     // sorted position -> (orig row, id)
__device__ int   g_ids[NMAX];

// ---------------- prep: dtype detect + convert + histogram + weight conv ----
__global__ void prep_kernel(const void* idsraw,
                            const float* __restrict__ W1,
                            const float* __restrict__ W2, int N) {
    __shared__ int s_ok;
    const long long* a64 = (const long long*)idsraw;
    int lane_ok = 1;
    if (threadIdx.x < 16) {
        long long v = a64[threadIdx.x];
        lane_ok = (v >= 0 && v < PNUM);
    }
    if (threadIdx.x < 32) {
        unsigned m = __ballot_sync(0xffffffffu, lane_ok);
        if (threadIdx.x == 0) s_ok = ((m & 0xffffu) == 0xffffu) ? 1 : 0;
    }
    __syncthreads();
    int ids64 = s_ok;
    int i = blockIdx.x * blockDim.x + threadIdx.x;

    // folded weight conversion (first 65536 threads)
    if (i < 4 * HDIM * HDIM) {
        int which = i >> 14;
        int j = i & 16383;
        int k = j >> 7, n = j & 127;
        if (which == 0)
            g_WT1[n * HDIM + k] = __float2half(W1[(size_t)k * HDIM + n]);
        else if (which == 1)
            g_WT2[n * HDIM + k] = __float2half(W2[(size_t)k * HDIM + n]);
        else if (which == 2)
            g_WB1[n * HDIM + k] = __float2half(W1[(size_t)(k + HDIM) * HDIM + n]);
        else
            g_WB2[n * HDIM + k] = __float2half(W2[(size_t)(k + HDIM) * HDIM + n]);
    }

    if (i >= N) return;
    int v = ids64 ? (int)a64[i] : ((const int*)idsraw)[i];
    g_ids[i] = v;
    atomicAdd(&g_counts[v], 1);
}

// ---------------- scan over g_counts ----------------
__device__ __forceinline__ int block_inclusive_scan_256(int v, int* wsum) {
    int lane = threadIdx.x & 31, w = threadIdx.x >> 5;
    int x = v;
#pragma unroll
    for (int o = 1; o < 32; o <<= 1) {
        int t = __shfl_up_sync(0xffffffffu, x, o);
        if (lane >= o) x += t;
    }
    if (lane == 31) wsum[w] = x;
    __syncthreads();
    if (w == 0) {
        int y = (lane < 8) ? wsum[lane] : 0;
#pragma unroll
        for (int o = 1; o < 8; o <<= 1) {
            int t = __shfl_up_sync(0xffffffffu, y, o);
            if (lane >= o) y += t;
        }
        if (lane < 8) wsum[lane] = y;
    }
    __syncthreads();
    return x + (w > 0 ? wsum[w - 1] : 0);
}

__global__ void scan1_kernel() {
    __shared__ int wsum[8];
    int i = blockIdx.x * 256 + threadIdx.x;
    int v = (i < PNUM) ? g_counts[i] : 0;
    int incl = block_inclusive_scan_256(v, wsum);
    if (i < PNUM) g_scantmp[i] = incl;
    if (threadIdx.x == 255) g_blocksums[blockIdx.x] = incl;
}

// merged scan2+scan3 + counts-re-zero + tail write + boundary-row zeroing
__global__ void scan23_kernel(float* __restrict__ agg,
                              float* __restrict__ agg2,
                              float* __restrict__ out, int tailkind) {
    __shared__ int wsum[8];
    __shared__ int bs[256];
    int t = threadIdx.x;
    int v = (t < SCAN_NB) ? g_blocksums[t] : 0;
    int incl = block_inclusive_scan_256(v, wsum);
    bs[t] = incl;
    __syncthreads();
    int i = blockIdx.x * 256 + t;
    if (i >= PNUM) return;
    int off = (blockIdx.x > 0) ? bs[blockIdx.x - 1] : 0;
    int inclv = off + g_scantmp[i];
    int excl = inclv - g_counts[i];
    g_counts[i] = 0;           // restore zero-invariant for next run
    g_offsets[i] = excl;
    g_cursor[i] = excl;
    if (i == PNUM - 1) g_offsets[PNUM] = inclv;

    // arange tail (thread i writes element i)
    float* base = out + (size_t)PNUM * HDIM;
    if (tailkind == 1) base[i] = (float)i;
    else if (tailkind == 2) ((long long*)base)[i] = (long long)i;

    // boundary/empty segments need zero-initialized rows for atomicMax path
    bool nz = (inclv == excl) || ((excl >> 7) != ((inclv - 1) >> 7));
    if (nz) {
        float4 z = make_float4(0.f, 0.f, 0.f, 0.f);
        float4* r0p = (float4*)(agg  + (size_t)i * HDIM);
        float4* r1p = (float4*)(agg2 + (size_t)i * HDIM);
        float4* r2p = (float4*)(out  + (size_t)i * HDIM);
#pragma unroll 4
        for (int c = 0; c < 32; c++) { r0p[c] = z; r1p[c] = z; r2p[c] = z; }
    }
}

__global__ void scatter_kernel(int N) {
    int i = blockIdx.x * blockDim.x + threadIdx.x;
    if (i >= N) return;
    int id = g_ids[i];
    int pos = atomicAdd(&g_cursor[id], 1);
    g_osid[pos] = make_int2(i, id);    // single 8B scattered store
}

#define STAGE_STRIDE 132
#define ENC0_SMEM_FLOATS (128 * STAGE_STRIDE + 128)
#define ENC0_SMEM_BYTES (ENC0_SMEM_FLOATS * 4)

// ---------------- encoder 0 with fused segmented max -------------------------
__global__ __launch_bounds__(256, 2) void enc0_kernel(
    const float* __restrict__ x, const float* __restrict__ W0,
    const float* __restrict__ b0, const float* __restrict__ g0,
    const float* __restrict__ be0, __half* __restrict__ out,
    float* __restrict__ maxout, int N)
{
    extern __shared__ float sm[];
    float* stage = sm;
    int* sidp = (int*)(sm + 128 * STAGE_STRIDE);

    const int tid = threadIdx.x;
    const int lane = tid & 31;
    const int warp = tid >> 5;
    const int row0 = blockIdx.x * 128;

    if (tid < 128) {
        int r = row0 + tid;
        sidp[tid] = g_osid[(r < N) ? r : (N - 1)].y;
    }

    float w[9][4], bb[4], gg[4], ee[4];
#pragma unroll
    for (int k = 0; k < 9; k++)
#pragma unroll
        for (int c = 0; c < 4; c++)
            w[k][c] = W0[k * HDIM + lane + 32 * c];
#pragma unroll
    for (int c = 0; c < 4; c++) {
        bb[c] = b0[lane + 32 * c];
        gg[c] = g0[lane + 32 * c];
        ee[c] = be0[lane + 32 * c];
    }

#pragma unroll 1
    for (int rr = 0; rr < 16; rr++) {
        int rl = warp * 16 + rr;
        int spos = row0 + rl;
        int sp = (spos < N) ? spos : (N - 1);
        int srow = g_osid[sp].x;

        float xv = (lane < 9) ? x[(size_t)srow * 9 + lane] : 0.f;
        float z[4] = {bb[0], bb[1], bb[2], bb[3]};
#pragma unroll
        for (int k = 0; k < 9; k++) {
            float xk = __shfl_sync(0xffffffffu, xv, k);
#pragma unroll
            for (int c = 0; c < 4; c++)
                z[c] = fmaf(xk, w[k][c], z[c]);
        }
        float s  = z[0] + z[1] + z[2] + z[3];
        float s2 = z[0]*z[0] + z[1]*z[1] + z[2]*z[2] + z[3]*z[3];
#pragma unroll
        for (int o = 16; o > 0; o >>= 1) {
            s  += __shfl_xor_sync(0xffffffffu, s, o);
            s2 += __shfl_xor_sync(0xffffffffu, s2, o);
        }
        float mu  = s * (1.f / HDIM);
        float var = fmaf(s2, 1.f / HDIM, -mu * mu);
        float rs  = rsqrtf(var + LN_EPS);
#pragma unroll
        for (int c = 0; c < 4; c++)
            stage[rl * STAGE_STRIDE + lane + 32 * c] =
                fmaxf(fmaf((z[c] - mu) * rs, gg[c], ee[c]), 0.f);
    }
    __syncthreads();

#pragma unroll 1
    for (int rr = 0; rr < 16; rr++) {
        int rl = warp * 16 + rr;
        int spos = row0 + rl;
        if (spos < N) {
            float4 v = *(const float4*)&stage[rl * STAGE_STRIDE + lane * 4];
            __half2 h0v = __floats2half2_rn(v.x, v.y);
            __half2 h1v = __floats2half2_rn(v.z, v.w);
            uint2 pk = make_uint2(*(unsigned*)&h0v, *(unsigned*)&h1v);
            *(uint2*)(out + (size_t)spos * HDIM + lane * 4) = pk;
        }
    }

    {
        const int p_first = sidp[0];
        const int p_last  = sidp[127];
        for (int seg = p_first + warp; seg <= p_last; seg += 8) {
            int b = g_offsets[seg], e = g_offsets[seg + 1];
            int r0 = b - row0; if (r0 < 0) r0 = 0;
            int r1 = e - row0; if (r1 > 128) r1 = 128;
            if (r1 <= r0) continue;
            float4 m = make_float4(0.f, 0.f, 0.f, 0.f);
            for (int r = r0; r < r1; r++) {
                float4 vv = *(const float4*)&stage[r * STAGE_STRIDE + lane * 4];
                m.x = fmaxf(m.x, vv.x); m.y = fmaxf(m.y, vv.y);
                m.z = fmaxf(m.z, vv.z); m.w = fmaxf(m.w, vv.w);
            }
            float* dst = maxout + (size_t)seg * HDIM + lane * 4;
            bool bnd = (b < row0) || (e > row0 + 128);
            if (bnd) {
                atomicMax((int*)dst + 0, __float_as_int(m.x));
                atomicMax((int*)dst + 1, __float_as_int(m.y));
                atomicMax((int*)dst + 2, __float_as_int(m.z));
                atomicMax((int*)dst + 3, __float_as_int(m.w));
            } else {
                *(float4*)dst = m;
            }
        }
    }
}

// ---------------- mma helpers ----------------
__device__ __forceinline__ void cp_async16(void* s, const void* g) {
    unsigned sa = (unsigned)__cvta_generic_to_shared(s);
    asm volatile("cp.async.cg.shared.global [%0], [%1], 16;\n" :: "r"(sa), "l"(g));
}
__device__ __forceinline__ void cp_commit() {
    asm volatile("cp.async.commit_group;\n" ::: "memory");
}
template<int n> __device__ __forceinline__ void cp_wait() {
    asm volatile("cp.async.wait_group %0;\n" :: "n"(n) : "memory");
}
__device__ __forceinline__ void mma_f16(float acc[4], const unsigned a[4], const unsigned b[2]) {
    asm volatile(
        "mma.sync.aligned.m16n8k16.row.col.f32.f16.f16.f32 "
        "{%0,%1,%2,%3},{%4,%5,%6,%7},{%8,%9},{%0,%1,%2,%3};\n"
        : "+f"(acc[0]), "+f"(acc[1]), "+f"(acc[2]), "+f"(acc[3])
        : "r"(a[0]), "r"(a[1]), "r"(a[2]), "r"(a[3]), "r"(b[0]), "r"(b[1]));
}
__device__ __forceinline__ void ldsm_x4(unsigned r[4], const __half* p) {
    unsigned a = (unsigned)__cvta_generic_to_shared(p);
    asm volatile("ldmatrix.sync.aligned.m8n8.x4.shared.b16 {%0,%1,%2,%3}, [%4];\n"
        : "=r"(r[0]), "=r"(r[1]), "=r"(r[2]), "=r"(r[3]) : "r"(a));
}
__device__ __forceinline__ void ldsm_x2(unsigned r[2], const __half* p) {
    unsigned a = (unsigned)__cvta_generic_to_shared(p);
    asm volatile("ldmatrix.sync.aligned.m8n8.x2.shared.b16 {%0,%1}, [%2];\n"
        : "=r"(r[0]), "=r"(r[1]) : "r"(a));
}

// ---------------- aggw16: aggW = bias + agg @ W_bot, fp16 MMA, fp16 output ---
#define AGH_STRIDE 136
#define AGH_BUF (128 * AGH_STRIDE)
#define AGW16_SMEM_BYTES (2 * AGH_BUF * 2)

__global__ __launch_bounds__(256, 2) void aggw16_kernel(
    const float* __restrict__ agg, const __half* __restrict__ WB,
    const float* __restrict__ b, __half* __restrict__ aggw, int P)
{
    extern __shared__ float sm[];
    __half* Ah = (__half*)sm;
    __half* Wh = Ah + AGH_BUF;

    const int tid = threadIdx.x;
    const int lane = tid & 31;
    const int quad_r = lane >> 2, quad_c = lane & 3;
    const int warp = tid >> 5;
    const int warp_m = warp >> 1, warp_n = warp & 1;
    const int row0 = blockIdx.x * 128;

#pragma unroll
    for (int i = 0; i < 8; i++) {
        int idx = tid + i * 256;
        int n = idx >> 4, f = idx & 15;
        cp_async16(Wh + n * AGH_STRIDE + f * 8, WB + (size_t)n * HDIM + f * 8);
    }
    cp_commit();

#pragma unroll
    for (int i = 0; i < 16; i++) {
        int idx = tid + i * 256;
        int r = idx >> 5, f = idx & 31;
        int gr = row0 + r; if (gr >= P) gr = P - 1;
        float4 v = *(const float4*)(agg + (size_t)gr * HDIM + f * 4);
        __half2 p0 = __floats2half2_rn(v.x, v.y);
        __half2 p1 = __floats2half2_rn(v.z, v.w);
        uint2 pk = make_uint2(*(unsigned*)&p0, *(unsigned*)&p1);
        *(uint2*)(Ah + r * AGH_STRIDE + f * 4) = pk;
    }

    float acc[2][8][4];
#pragma unroll
    for (int nt = 0; nt < 8; nt++) {
        float2 bv = *(const float2*)&b[warp_n * 64 + nt * 8 + quad_c * 2];
#pragma unroll
        for (int mf = 0; mf < 2; mf++) {
            acc[mf][nt][0] = bv.x; acc[mf][nt][1] = bv.y;
            acc[mf][nt][2] = bv.x; acc[mf][nt][3] = bv.y;
        }
    }

    cp_wait<0>();
    __syncthreads();

    const __half* baseA0 = Ah + (warp_m * 32 + (lane & 15)) * AGH_STRIDE
                              + ((lane >> 4) << 3);
    const __half* baseA1 = baseA0 + 16 * AGH_STRIDE;
    const __half* baseB  = Wh + (warp_n * 64 + (lane & 7)) * AGH_STRIDE
                              + (((lane >> 3) & 1) << 3);

#pragma unroll 1
    for (int ks = 0; ks < 8; ks++) {
        const int kk = ks * 16;
        unsigned afr[2][4];
        ldsm_x4(afr[0], baseA0 + kk);
        ldsm_x4(afr[1], baseA1 + kk);
        unsigned bfr[8][2];
#pragma unroll
        for (int nt = 0; nt < 8; nt++)
            ldsm_x2(bfr[nt], baseB + nt * 8 * AGH_STRIDE + kk);
#pragma unroll
        for (int mf = 0; mf < 2; mf++)
#pragma unroll
            for (int nt = 0; nt < 8; nt++)
                mma_f16(acc[mf][nt], afr[mf], bfr[nt]);
    }

#pragma unroll
    for (int nt = 0; nt < 8; nt++) {
        int col = warp_n * 64 + nt * 8 + quad_c * 2;
#pragma unroll
        for (int mf = 0; mf < 2; mf++)
#pragma unroll
            for (int h = 0; h < 2; h++) {
                int grow = row0 + warp_m * 32 + mf * 16 + h * 8 + quad_r;
                if (grow < P) {
                    __half2 hv = __floats2half2_rn(acc[mf][nt][2 * h],
                                                   acc[mf][nt][2 * h + 1]);
                    *(unsigned*)(aggw + (size_t)grow * HDIM + col) =
                        *(unsigned*)&hv;
                }
            }
    }
}

// ---------------- encoder 1/2: single-shot K=128 fp16 mma + fused segmax -----
#define EH_STRIDE 136
#define EH_BUF (128 * EH_STRIDE)
#define ENCH_SMEM_BYTES 72192

__global__ __launch_bounds__(256, 2) void enc_kernel(
    const __half* __restrict__ hprev, const __half* __restrict__ aggw,
    const __half* __restrict__ WT, const float* __restrict__ gw,
    const float* __restrict__ be, __half* __restrict__ hout,
    float* __restrict__ maxout, int N)
{
    extern __shared__ char smraw[];
    __half* Ah = (__half*)smraw;
    __half* Wh = Ah + EH_BUF;
    float* stage = (float*)smraw;
    float2* red2 = (float2*)(smraw + 69632);
    int*   sidp = (int*)(smraw + 71680);

    const int tid = threadIdx.x;
    const int lane = tid & 31;
    const int quad_r = lane >> 2, quad_c = lane & 3;
    const int warp = tid >> 5;
    const int warp_m = warp >> 1, warp_n = warp & 1;
    const int row0 = blockIdx.x * 128;

    if (tid < 128) {
        int r = row0 + tid;
        sidp[tid] = g_osid[(r < N) ? r : (N - 1)].y;
    }

#pragma unroll
    for (int i = 0; i < 8; i++) {
        int idx = tid + i * 256;
        int r = idx >> 4, f = idx & 15;
        int gr = row0 + r; if (gr >= N) gr = N - 1;
        cp_async16(Ah + r * EH_STRIDE + f * 8,
                   hprev + (size_t)gr * HDIM + f * 8);
    }
#pragma unroll
    for (int i = 0; i < 8; i++) {
        int idx = tid + i * 256;
        int n = idx >> 4, f = idx & 15;
        cp_async16(Wh + n * EH_STRIDE + f * 8, WT + (size_t)n * HDIM + f * 8);
    }
    cp_commit();
    __syncthreads();

    float acc[2][8][4];
#pragma unroll
    for (int mf = 0; mf < 2; mf++)
#pragma unroll
        for (int h = 0; h < 2; h++) {
            int rl = warp_m * 32 + mf * 16 + h * 8 + quad_r;
            const __half* base = aggw + (size_t)sidp[rl] * HDIM;
#pragma unroll
            for (int nt = 0; nt < 8; nt++) {
                unsigned u = *(const unsigned*)(base + warp_n * 64 + nt * 8
                                                + quad_c * 2);
                float2 v = __half22float2(*(__half2*)&u);
                acc[mf][nt][2 * h]     = v.x;
                acc[mf][nt][2 * h + 1] = v.y;
            }
        }

    cp_wait<0>();
    __syncthreads();

    const __half* baseA0 = Ah + (warp_m * 32 + (lane & 15)) * EH_STRIDE
                              + ((lane >> 4) << 3);
    const __half* baseA1 = baseA0 + 16 * EH_STRIDE;
    const __half* baseB  = Wh + (warp_n * 64 + (lane & 7)) * EH_STRIDE
                              + (((lane >> 3) & 1) << 3);

#pragma unroll 1
    for (int ks = 0; ks < 8; ks++) {
        const int kk = ks * 16;
        unsigned afr[2][4];
        ldsm_x4(afr[0], baseA0 + kk);
        ldsm_x4(afr[1], baseA1 + kk);
        unsigned bfr[8][2];
#pragma unroll
        for (int nt = 0; nt < 8; nt++)
            ldsm_x2(bfr[nt], baseB + nt * 8 * EH_STRIDE + kk);
#pragma unroll
        for (int mf = 0; mf < 2; mf++)
#pragma unroll
            for (int nt = 0; nt < 8; nt++)
                mma_f16(acc[mf][nt], afr[mf], bfr[nt]);
    }

    // ---- LayerNorm statistics ----
    float s[2][2], q[2][2];
#pragma unroll
    for (int mf = 0; mf < 2; mf++)
#pragma unroll
        for (int h = 0; h < 2; h++) {
            float ss = 0.f, qq = 0.f;
#pragma unroll
            for (int nt = 0; nt < 8; nt++) {
                float z0 = acc[mf][nt][2 * h], z1 = acc[mf][nt][2 * h + 1];
                ss += z0 + z1;
                qq += z0 * z0 + z1 * z1;
            }
            s[mf][h] = ss; q[mf][h] = qq;
        }
#pragma unroll
    for (int mk = 1; mk <= 2; mk <<= 1)
#pragma unroll
        for (int mf = 0; mf < 2; mf++)
#pragma unroll
            for (int h = 0; h < 2; h++) {
                s[mf][h] += __shfl_xor_sync(0xffffffffu, s[mf][h], mk);
                q[mf][h] += __shfl_xor_sync(0xffffffffu, q[mf][h], mk);
            }
    if (quad_c == 0) {
#pragma unroll
        for (int mf = 0; mf < 2; mf++)
#pragma unroll
            for (int h = 0; h < 2; h++) {
                int rl = warp_m * 32 + mf * 16 + h * 8 + quad_r;
                red2[rl * 2 + warp_n] = make_float2(s[mf][h], q[mf][h]);
            }
    }
    __syncthreads();
    float mu[2][2], rs[2][2];
#pragma unroll
    for (int mf = 0; mf < 2; mf++)
#pragma unroll
        for (int h = 0; h < 2; h++) {
            int rl = warp_m * 32 + mf * 16 + h * 8 + quad_r;
            float2 r0 = red2[rl * 2 + 0], r1 = red2[rl * 2 + 1];
            float ss = r0.x + r1.x, qq = r0.y + r1.y;
            float m = ss * (1.f / HDIM);
            float var = fmaf(qq, 1.f / HDIM, -m * m);
            mu[mf][h] = m;
            rs[mf][h] = rsqrtf(var + LN_EPS);
        }
    __syncthreads();

    // ---- normalize + ReLU into stage ----
#pragma unroll
    for (int nt = 0; nt < 8; nt++) {
        int col = warp_n * 64 + nt * 8 + quad_c * 2;
        float2 gv = *(const float2*)&gw[col];
        float2 ev = *(const float2*)&be[col];
#pragma unroll
        for (int mf = 0; mf < 2; mf++)
#pragma unroll
            for (int h = 0; h < 2; h++) {
                int rl = warp_m * 32 + mf * 16 + h * 8 + quad_r;
                float z0 = acc[mf][nt][2 * h], z1 = acc[mf][nt][2 * h + 1];
                float2 o;
                o.x = fmaxf(fmaf((z0 - mu[mf][h]) * rs[mf][h], gv.x, ev.x), 0.f);
                o.y = fmaxf(fmaf((z1 - mu[mf][h]) * rs[mf][h], gv.y, ev.y), 0.f);
                *(float2*)&stage[rl * STAGE_STRIDE + col] = o;
            }
    }
    __syncthreads();

    if (hout) {
#pragma unroll 1
        for (int rr = 0; rr < 16; rr++) {
            int rl = warp * 16 + rr;
            int grow = row0 + rl;
            if (grow < N) {
                float4 v = *(const float4*)&stage[rl * STAGE_STRIDE + lane * 4];
                __half2 h0v = __floats2half2_rn(v.x, v.y);
                __half2 h1v = __floats2half2_rn(v.z, v.w);
                uint2 pk = make_uint2(*(unsigned*)&h0v, *(unsigned*)&h1v);
                *(uint2*)(hout + (size_t)grow * HDIM + lane * 4) = pk;
            }
        }
    }

    {
        const int p_first = sidp[0];
        const int p_last  = sidp[127];
        for (int seg = p_first + warp; seg <= p_last; seg += 8) {
            int b = g_offsets[seg], e = g_offsets[seg + 1];
            int r0 = b - row0; if (r0 < 0) r0 = 0;
            int r1 = e - row0; if (r1 > 128) r1 = 128;
            if (r1 <= r0) continue;
            float4 m = make_float4(0.f, 0.f, 0.f, 0.f);
            for (int r = r0; r < r1; r++) {
                float4 v = *(const float4*)&stage[r * STAGE_STRIDE + lane * 4];
                m.x = fmaxf(m.x, v.x); m.y = fmaxf(m.y, v.y);
                m.z = fmaxf(m.z, v.z); m.w = fmaxf(m.w, v.w);
            }
            float* dst = maxout + (size_t)seg * HDIM + lane * 4;
            bool bnd = (b < row0) || (e > row0 + 128);
            if (bnd) {
                atomicMax((int*)dst + 0, __float_as_int(m.x));
                atomicMax((int*)dst + 1, __float_as_int(m.y));
                atomicMax((int*)dst + 2, __float_as_int(m.z));
                atomicMax((int*)dst + 3, __float_as_int(m.w));
            } else {
                *(float4*)dst = m;
            }
        }
    }
}

// ---------------- generic tail fallback (odd tail sizes only) ----------------
__global__ void tail_kernel(float* out, int tail) {
    int i = blockIdx.x * blockDim.x + threadIdx.x;
    float* base = out + (size_t)PNUM * HDIM;
    if (i < tail) base[i] = (float)i;
}

// ---------------- launch ----------------
extern "C" void kernel_launch(void* const* d_in, const int* in_sizes, int n_in,
                              void* d_out, int out_size) {
    const float* x   = (const float*)d_in[0];
    const void*  ids = d_in[1];
    const float* W0  = (const float*)d_in[2];
    const float* b0  = (const float*)d_in[3];
    const float* g0  = (const float*)d_in[4];
    const float* be0 = (const float*)d_in[5];
    const float* W1  = (const float*)d_in[6];
    const float* b1  = (const float*)d_in[7];
    const float* g1  = (const float*)d_in[8];
    const float* be1 = (const float*)d_in[9];
    const float* W2  = (const float*)d_in[10];
    const float* b2  = (const float*)d_in[11];
    const float* g2  = (const float*)d_in[12];
    const float* be2 = (const float*)d_in[13];

    const int N = in_sizes[0] / 9;
    const int P = PNUM;
    float* out = (float*)d_out;

    __half *h0, *h1, *WT1, *WT2, *WB1, *WB2, *aggw;
    float *aggpair;
    cudaGetSymbolAddress((void**)&h0,   g_h0);
    cudaGetSymbolAddress((void**)&h1,   g_h1);
    cudaGetSymbolAddress((void**)&WT1,  g_WT1);
    cudaGetSymbolAddress((void**)&WT2,  g_WT2);
    cudaGetSymbolAddress((void**)&WB1,  g_WB1);
    cudaGetSymbolAddress((void**)&WB2,  g_WB2);
    cudaGetSymbolAddress((void**)&aggw, g_aggw);
    cudaGetSymbolAddress((void**)&aggpair, g_aggpair);
    float* agg  = aggpair;
    float* agg2 = aggpair + (size_t)P * HDIM;

    cudaFuncSetAttribute(enc_kernel,
        cudaFuncAttributeMaxDynamicSharedMemorySize, ENCH_SMEM_BYTES);
    cudaFuncSetAttribute(aggw16_kernel,
        cudaFuncAttributeMaxDynamicSharedMemorySize, AGW16_SMEM_BYTES);
    cudaFuncSetAttribute(enc0_kernel,
        cudaFuncAttributeMaxDynamicSharedMemorySize, ENC0_SMEM_BYTES);

    // tail kind: 1 = float arange (tail==P), 2 = int64 arange (tail==2P)
    int tail = out_size - P * HDIM;
    int tailkind = (tail == PNUM) ? 1 : (tail == 2 * PNUM) ? 2 : 0;
    if (tail > 0 && tailkind == 0)
        tail_kernel<<<(tail + 255) / 256, 256>>>(out, tail);

    // 1) CSR build
    prep_kernel<<<(N + 255) / 256, 256>>>(ids, W1, W2, N);
    scan1_kernel<<<SCAN_NB, 256>>>();
    scan23_kernel<<<SCAN_NB, 256>>>(agg, agg2, out, tailkind);
    scatter_kernel<<<(N + 255) / 256, 256>>>(N);

    // 2) enc0 -> h0 (fp16) + fused seg_max -> agg
    enc0_kernel<<<(N + 127) / 128, 256, ENC0_SMEM_BYTES>>>(
        x, W0, b0, g0, be0, h0, agg, N);

    // 3) layer 1: aggW(agg) fp16; enc1 -> h1 + fused seg_max -> agg2
    aggw16_kernel<<<(P + 127) / 128, 256, AGW16_SMEM_BYTES>>>(
        agg, WB1, b1, aggw, P);
    enc_kernel<<<(N + 127) / 128, 256, ENCH_SMEM_BYTES>>>(
        h0, aggw, WT1, g1, be1, h1, agg2, N);

    // 4) layer 2: aggW(agg2) fp16; enc2 (no h store) + fused seg_max -> out
    aggw16_kernel<<<(P + 127) / 128, 256, AGW16_SMEM_BYTES>>>(
        agg2, WB2, b2, aggw, P);
    enc_kernel<<<(N + 127) / 128, 256, ENCH_SMEM_BYTES>>>(
        h1, aggw, WT2, g2, be2, nullptr, out, N);
}